// round 11
// baseline (speedup 1.0000x reference)
#include <cuda_runtime.h>
#include <cuda_bf16.h>
#include <math_constants.h>
#include <cstdint>

// Problem constants
#define SDIM 1024
#define BDIM 4
#define EDIM 256
#define HDIM 8
#define DDIM 32

// d_out layout: out_rgb [S,B,E], out_dpt [S,B,E], shared_rgb [B,H,S,S], shared_dpt [B,H,S,S]
#define OFF_OUT_RGB  0
#define OFF_OUT_DPT  (SDIM*BDIM*EDIM)              // 1048576
#define OFF_SHARED   (2*SDIM*BDIM*EDIM)            // 2097152
#define BHSS         ((size_t)BDIM*HDIM*SDIM*SDIM) // 33554432

#define SCALE 0.17677669529663687f   // 1/sqrt(32)

// Scratch
__device__ float g_qkv[6 * BDIM * HDIM * SDIM * DDIM];   // 25 MB
__device__ float g_ocat[2 * BDIM * SDIM * EDIM];         // 8 MB
__device__ float g_sums[2 * 32 * SDIM];                  // exp-sums per (st,bh,q)

// ---------------------------------------------------------------------------
// tf32 helpers (mma.sync m16n8k8, fp32 accum)
// ---------------------------------------------------------------------------
__device__ __forceinline__ uint32_t f2tf(float f) {
    uint32_t u;
    asm("cvt.rna.tf32.f32 %0, %1;" : "=r"(u) : "f"(f));
    return u;
}

__device__ __forceinline__ void mma_tf32(float* d, const uint32_t* a, const uint32_t* b) {
    asm volatile(
        "mma.sync.aligned.m16n8k8.row.col.f32.tf32.tf32.f32 "
        "{%0,%1,%2,%3}, {%4,%5,%6,%7}, {%8,%9}, {%0,%1,%2,%3};"
        : "+f"(d[0]), "+f"(d[1]), "+f"(d[2]), "+f"(d[3])
        : "r"(a[0]), "r"(a[1]), "r"(a[2]), "r"(a[3]),
          "r"(b[0]), "r"(b[1]));
}

__device__ __forceinline__ void stage4(uint32_t* dst, float4 v) {
    uint4 u = make_uint4(f2tf(v.x), f2tf(v.y), f2tf(v.z), f2tf(v.w));
    *reinterpret_cast<uint4*>(dst) = u;
}

// ---------------------------------------------------------------------------
// Kernel 0: zero the sums accumulator (graph-replayed every launch)
// ---------------------------------------------------------------------------
__global__ void zero_sums_kernel() {
    g_sums[blockIdx.x * 256 + threadIdx.x] = 0.f;
}

// ---------------------------------------------------------------------------
// Kernel 1: batched QKV projection via tf32 mma. grid.z = proj id 0..5.
// ---------------------------------------------------------------------------
struct ProjArgs {
    const float* x[6];
    const float* w[2];
    const float* b[2];
};

__global__ __launch_bounds__(256) void proj_tf32_kernel(ProjArgs args)
{
    __shared__ uint32_t As[128][36];
    __shared__ uint32_t Bs[128][36];
    const int proj = blockIdx.z;
    const int st = proj / 3;
    const int wsel = proj - st * 3;
    const float* x = args.x[proj];
    const float* W = args.w[st] + (size_t)wsel * 256 * 256;
    const float* bias = args.b[st] + wsel * 256;

    const int bm = blockIdx.y * 128;
    const int bn = blockIdx.x * 128;
    const int tid = threadIdx.x;
    const int wid = tid >> 5;
    const int lane = tid & 31;
    const int gid = lane >> 2;
    const int tig = lane & 3;
    const int wm = (wid & 3) * 32;
    const int wn = (wid >> 2) * 64;

    const int sr0 = tid >> 3;            // 0..31, +32*t
    const int sc0 = (tid & 7) * 4;       // 0,4,..28

    float4 pa[4], pb[4];
#pragma unroll
    for (int t = 0; t < 4; t++) {
        pa[t] = *reinterpret_cast<const float4*>(x + (size_t)(bm + sr0 + t * 32) * 256 + sc0);
        pb[t] = *reinterpret_cast<const float4*>(W + (size_t)(bn + sr0 + t * 32) * 256 + sc0);
    }

    float acc[2][8][4] = {};

    for (int kt = 0; kt < 8; kt++) {
#pragma unroll
        for (int t = 0; t < 4; t++) {
            const int r = sr0 + t * 32;
            As[r][sc0 + 0] = f2tf(pa[t].x); As[r][sc0 + 1] = f2tf(pa[t].y);
            As[r][sc0 + 2] = f2tf(pa[t].z); As[r][sc0 + 3] = f2tf(pa[t].w);
            Bs[r][sc0 + 0] = f2tf(pb[t].x); Bs[r][sc0 + 1] = f2tf(pb[t].y);
            Bs[r][sc0 + 2] = f2tf(pb[t].z); Bs[r][sc0 + 3] = f2tf(pb[t].w);
        }
        __syncthreads();

        if (kt < 7) {
            const int k0 = (kt + 1) * 32;
#pragma unroll
            for (int t = 0; t < 4; t++) {
                pa[t] = *reinterpret_cast<const float4*>(x + (size_t)(bm + sr0 + t * 32) * 256 + k0 + sc0);
                pb[t] = *reinterpret_cast<const float4*>(W + (size_t)(bn + sr0 + t * 32) * 256 + k0 + sc0);
            }
        }

#pragma unroll
        for (int kc = 0; kc < 4; kc++) {
            const int k8 = kc * 8;
            uint32_t a[2][4], b[8][2];
#pragma unroll
            for (int i = 0; i < 2; i++) {
                const int r = wm + i * 16;
                a[i][0] = As[r + gid][k8 + tig];
                a[i][1] = As[r + gid + 8][k8 + tig];
                a[i][2] = As[r + gid][k8 + tig + 4];
                a[i][3] = As[r + gid + 8][k8 + tig + 4];
            }
#pragma unroll
            for (int j = 0; j < 8; j++) {
                const int c = wn + j * 8;
                b[j][0] = Bs[c + gid][k8 + tig];
                b[j][1] = Bs[c + gid][k8 + tig + 4];
            }
#pragma unroll
            for (int i = 0; i < 2; i++)
#pragma unroll
                for (int j = 0; j < 8; j++)
                    mma_tf32(acc[i][j], a[i], b[j]);
        }
        __syncthreads();
    }

#pragma unroll
    for (int i = 0; i < 2; i++) {
        const int m0 = bm + wm + i * 16 + gid;
        const int s0 = m0 >> 2, b0 = m0 & 3;
        const int m1 = m0 + 8;
        const int s1 = m1 >> 2, b1 = m1 & 3;
#pragma unroll
        for (int j = 0; j < 8; j++) {
            const int c0 = bn + wn + j * 8 + tig * 2;
            const int h = c0 >> 5;
            const int d = c0 & 31;
            const float bv0 = bias[c0], bv1 = bias[c0 + 1];
            float* p0 = &g_qkv[(((size_t)(proj * 4 + b0) * 8 + h) * 1024 + s0) * 32 + d];
            float* p1 = &g_qkv[(((size_t)(proj * 4 + b1) * 8 + h) * 1024 + s1) * 32 + d];
            *reinterpret_cast<float2*>(p0) = make_float2(acc[i][j][0] + bv0, acc[i][j][1] + bv1);
            *reinterpret_cast<float2*>(p1) = make_float2(acc[i][j][2] + bv0, acc[i][j][3] + bv1);
        }
    }
}

// ---------------------------------------------------------------------------
// Kernel 2: exp-sum stats only (no score writes). QK^T via tf32 mma,
// per-row sum of exp(scaled score) with mask, atomicAdd into g_sums.
// Accumulation order matches attn_fused_kernel exactly -> identical values.
// ---------------------------------------------------------------------------
__global__ __launch_bounds__(256) void sums_kernel(const unsigned char* __restrict__ mask)
{
    __shared__ uint32_t Qs[128][36];
    __shared__ uint32_t Ks[128][36];
    const int z = blockIdx.z;
    const int st = z >> 5;
    const int bh = z & 31;
    const int bq = blockIdx.y * 128;
    const int bk = blockIdx.x * 128;

    const float* Q = g_qkv + ((size_t)(st * 3 + 0) * 32 + bh) * (SDIM * DDIM);
    const float* K = g_qkv + ((size_t)(st * 3 + 1) * 32 + bh) * (SDIM * DDIM);

    const int tid = threadIdx.x;
    for (int i = tid * 4; i < 128 * 32; i += 1024) {
        const int r = i >> 5, c = i & 31;
        float4 q4 = *reinterpret_cast<const float4*>(Q + (size_t)(bq + r) * 32 + c);
        float4 k4 = *reinterpret_cast<const float4*>(K + (size_t)(bk + r) * 32 + c);
        Qs[r][c + 0] = f2tf(q4.x); Qs[r][c + 1] = f2tf(q4.y);
        Qs[r][c + 2] = f2tf(q4.z); Qs[r][c + 3] = f2tf(q4.w);
        Ks[r][c + 0] = f2tf(k4.x); Ks[r][c + 1] = f2tf(k4.y);
        Ks[r][c + 2] = f2tf(k4.z); Ks[r][c + 3] = f2tf(k4.w);
    }
    __syncthreads();

    const int wid = tid >> 5;
    const int lane = tid & 31;
    const int gid = lane >> 2;
    const int tig = lane & 3;
    const int wm = (wid & 3) * 32;
    const int wn = (wid >> 2) * 64;

    float acc[2][8][4] = {};
#pragma unroll
    for (int kc = 0; kc < 4; kc++) {
        const int k0 = kc * 8;
        uint32_t a[2][4], b[8][2];
#pragma unroll
        for (int i = 0; i < 2; i++) {
            const int r = wm + i * 16;
            a[i][0] = Qs[r + gid][k0 + tig];
            a[i][1] = Qs[r + gid + 8][k0 + tig];
            a[i][2] = Qs[r + gid][k0 + tig + 4];
            a[i][3] = Qs[r + gid + 8][k0 + tig + 4];
        }
#pragma unroll
        for (int j = 0; j < 8; j++) {
            const int c = wn + j * 8;
            b[j][0] = Ks[c + gid][k0 + tig];
            b[j][1] = Ks[c + gid][k0 + tig + 4];
        }
#pragma unroll
        for (int i = 0; i < 2; i++)
#pragma unroll
            for (int j = 0; j < 8; j++)
                mma_tf32(acc[i][j], a[i], b[j]);
    }

    const unsigned char* mrow = mask + (size_t)(bh >> 3) * SDIM;
    float* sums = g_sums + (size_t)z * SDIM;
#pragma unroll
    for (int i = 0; i < 2; i++) {
        float slo = 0.f, shi = 0.f;
#pragma unroll
        for (int j = 0; j < 8; j++) {
            const int c0 = bk + wn + j * 8 + tig * 2;
            const float m0 = mrow[c0] ? 0.f : 1.f;
            const float m1 = mrow[c0 + 1] ? 0.f : 1.f;
            slo += m0 * __expf(acc[i][j][0] * SCALE) + m1 * __expf(acc[i][j][1] * SCALE);
            shi += m0 * __expf(acc[i][j][2] * SCALE) + m1 * __expf(acc[i][j][3] * SCALE);
        }
        slo += __shfl_xor_sync(0xffffffffu, slo, 1);
        slo += __shfl_xor_sync(0xffffffffu, slo, 2);
        shi += __shfl_xor_sync(0xffffffffu, shi, 1);
        shi += __shfl_xor_sync(0xffffffffu, shi, 2);
        if (tig == 0) {
            atomicAdd(&sums[bq + wm + i * 16 + gid], slo);
            atomicAdd(&sums[bq + wm + i * 16 + gid + 8], shi);
        }
    }
}

// ---------------------------------------------------------------------------
// Kernel 3 (FULLY FUSED, shuffle-free):
// QK^T with KEY-PERMUTED B operand so the score C-fragment lands directly in
// PV A-fragment layout: sigma(n) = (n even ? n/2 : n/2+4) applied to the key
// index when loading K fragments makes thread (gid,tig) hold scores for keys
// {tig, tig+4} of rows {gid, gid+8} -- exactly mma A layout. exp/blend in
// registers, single prob write (scalar stcs), PV mma immediately. No SHFL.
// Numerics: every dot product accumulates in the same order as before ->
// bitwise-identical results.
// ---------------------------------------------------------------------------
// smem layout (u32 indices):
#define KSOFF(st,buf)  (((st) * 2 + (buf)) * 1152)         // K tiles 2x2 x 32x36
#define VSOFF(st,buf)  (4608 + ((st) * 2 + (buf)) * 1280)  // V tiles 2x2 x 32x40
#define MSKOFF         9728                                // mask 1024 f32
#define FUSED_SMEM     (10752 * 4)                         // 43008 bytes

__global__ __launch_bounds__(256, 2) void attn_fused_kernel(
    float* __restrict__ dout, const unsigned char* __restrict__ mask,
    const float* __restrict__ alpha_p, const float* __restrict__ beta_p)
{
    extern __shared__ uint32_t sm[];
    float* msk = reinterpret_cast<float*>(sm + MSKOFF);
    const int bh = blockIdx.y;
    const int b = bh >> 3, h = bh & 7;
    const int bq = blockIdx.x * 128;

    const int tid = threadIdx.x;
    const int wid = tid >> 5;
    const int lane = tid & 31;
    const int gid = lane >> 2;
    const int tig = lane & 3;
    const int sr0 = tid >> 3;          // 0..31
    const int sc0 = (tid & 7) * 4;     // 0,4,..28
    const int r = wid * 16;            // warp q-row base (local)
    // key permutation for the score B operand: sigma(gid)
    const int kp = (gid >> 1) + ((gid & 1) << 2);

    const float* Q1 = g_qkv + ((size_t)(0) * 32 + bh) * (SDIM * DDIM);
    const float* K1 = g_qkv + ((size_t)(1) * 32 + bh) * (SDIM * DDIM);
    const float* V1 = g_qkv + ((size_t)(2) * 32 + bh) * (SDIM * DDIM);
    const float* Q2 = g_qkv + ((size_t)(3) * 32 + bh) * (SDIM * DDIM);
    const float* K2 = g_qkv + ((size_t)(4) * 32 + bh) * (SDIM * DDIM);
    const float* V2 = g_qkv + ((size_t)(5) * 32 + bh) * (SDIM * DDIM);
    float* S1 = dout + OFF_SHARED + ((size_t)bh * SDIM + bq) * SDIM;
    float* S2 = S1 + BHSS;

    // mask multiplier table
    for (int i = tid; i < SDIM; i += 256)
        msk[i] = mask[(size_t)b * SDIM + i] ? 0.f : 1.f;

    // Q fragments straight from gmem (one-time prologue)
    uint32_t qf[2][4][4];
#pragma unroll
    for (int st = 0; st < 2; st++) {
        const float* Q = st ? Q2 : Q1;
#pragma unroll
        for (int ks = 0; ks < 4; ks++) {
            qf[st][ks][0] = f2tf(Q[(size_t)(bq + r + gid) * 32 + 8 * ks + tig]);
            qf[st][ks][1] = f2tf(Q[(size_t)(bq + r + gid + 8) * 32 + 8 * ks + tig]);
            qf[st][ks][2] = f2tf(Q[(size_t)(bq + r + gid) * 32 + 8 * ks + tig + 4]);
            qf[st][ks][3] = f2tf(Q[(size_t)(bq + r + gid + 8) * 32 + 8 * ks + tig + 4]);
        }
    }

    // blend coefficients folded with inverse sums (per thread's 2 rows)
    const float a = *alpha_p, bt = *beta_p;
    const int q0 = bq + r + gid;
    const float i1lo = 1.f / g_sums[(size_t)bh * SDIM + q0];
    const float i1hi = 1.f / g_sums[(size_t)bh * SDIM + q0 + 8];
    const float i2lo = 1.f / g_sums[(size_t)(32 + bh) * SDIM + q0];
    const float i2hi = 1.f / g_sums[(size_t)(32 + bh) * SDIM + q0 + 8];
    const float c1lo = (1.f - a) * i1lo, c2lo = a * i2lo;
    const float c1hi = (1.f - a) * i1hi, c2hi = a * i2hi;
    const float d2lo = (1.f - bt) * i2lo, d1lo = bt * i1lo;
    const float d2hi = (1.f - bt) * i2hi, d1hi = bt * i1hi;

    // stage K/V tile 0 into buffer 0 (vectorized)
    stage4(sm + KSOFF(0, 0) + sr0 * 36 + sc0,
           *reinterpret_cast<const float4*>(K1 + (size_t)sr0 * 32 + sc0));
    stage4(sm + KSOFF(1, 0) + sr0 * 36 + sc0,
           *reinterpret_cast<const float4*>(K2 + (size_t)sr0 * 32 + sc0));
    stage4(sm + VSOFF(0, 0) + sr0 * 40 + sc0,
           *reinterpret_cast<const float4*>(V1 + (size_t)sr0 * 32 + sc0));
    stage4(sm + VSOFF(1, 0) + sr0 * 40 + sc0,
           *reinterpret_cast<const float4*>(V2 + (size_t)sr0 * 32 + sc0));
    __syncthreads();

    float o[2][4][4] = {};

    for (int kt = 0; kt < 32; kt++) {
        const int cur = kt & 1;

        // prefetch next K/V tiles into registers
        float4 k1n, k2n, v1n, v2n;
        if (kt < 31) {
            const int k0 = (kt + 1) * 32;
            k1n = *reinterpret_cast<const float4*>(K1 + (size_t)(k0 + sr0) * 32 + sc0);
            k2n = *reinterpret_cast<const float4*>(K2 + (size_t)(k0 + sr0) * 32 + sc0);
            v1n = *reinterpret_cast<const float4*>(V1 + (size_t)(k0 + sr0) * 32 + sc0);
            v2n = *reinterpret_cast<const float4*>(V2 + (size_t)(k0 + sr0) * 32 + sc0);
        }

        const uint32_t* KA = sm + KSOFF(0, cur);
        const uint32_t* KB = sm + KSOFF(1, cur);
        const uint32_t* VA = sm + VSOFF(0, cur);
        const uint32_t* VB = sm + VSOFF(1, cur);

        // ---- per 8-key group: permuted scores -> probs -> PV mma ----
#pragma unroll
        for (int j = 0; j < 4; j++) {
            float sA[4] = {}, sB[4] = {};
#pragma unroll
            for (int ks = 0; ks < 4; ks++) {
                uint32_t bf[2];
                bf[0] = KA[(j * 8 + kp) * 36 + 8 * ks + tig];
                bf[1] = KA[(j * 8 + kp) * 36 + 8 * ks + tig + 4];
                mma_tf32(sA, qf[0][ks], bf);
                bf[0] = KB[(j * 8 + kp) * 36 + 8 * ks + tig];
                bf[1] = KB[(j * 8 + kp) * 36 + 8 * ks + tig + 4];
                mma_tf32(sB, qf[1][ks], bf);
            }
            // thread now holds scores for keys {tig, tig+4}, rows {gid, gid+8}:
            //   sX[0]=(gid,tig) sX[1]=(gid,tig+4) sX[2]=(gid+8,tig) sX[3]=(gid+8,tig+4)
            const int cb = kt * 32 + j * 8;
            const float m0 = msk[cb + tig], m1 = msk[cb + tig + 4];
            const float e1x = m0 * __expf(sA[0] * SCALE), e1y = m1 * __expf(sA[1] * SCALE);
            const float e1z = m0 * __expf(sA[2] * SCALE), e1w = m1 * __expf(sA[3] * SCALE);
            const float e2x = m0 * __expf(sB[0] * SCALE), e2y = m1 * __expf(sB[1] * SCALE);
            const float e2z = m0 * __expf(sB[2] * SCALE), e2w = m1 * __expf(sB[3] * SCALE);
            const float p1x = c1lo * e1x + c2lo * e2x, p1y = c1lo * e1y + c2lo * e2y;
            const float p1z = c1hi * e1z + c2hi * e2z, p1w = c1hi * e1w + c2hi * e2w;
            const float p2x = d2lo * e2x + d1lo * e1x, p2y = d2lo * e2y + d1lo * e1y;
            const float p2z = d2hi * e2z + d1hi * e1z, p2w = d2hi * e2w + d1hi * e1w;
            // single DRAM write of the blended probs (scalar, keys tig / tig+4)
            __stcs(S1 + (size_t)(r + gid) * SDIM + cb + tig,         p1x);
            __stcs(S1 + (size_t)(r + gid) * SDIM + cb + tig + 4,     p1y);
            __stcs(S1 + (size_t)(r + gid + 8) * SDIM + cb + tig,     p1z);
            __stcs(S1 + (size_t)(r + gid + 8) * SDIM + cb + tig + 4, p1w);
            __stcs(S2 + (size_t)(r + gid) * SDIM + cb + tig,         p2x);
            __stcs(S2 + (size_t)(r + gid) * SDIM + cb + tig + 4,     p2y);
            __stcs(S2 + (size_t)(r + gid + 8) * SDIM + cb + tig,     p2z);
            __stcs(S2 + (size_t)(r + gid + 8) * SDIM + cb + tig + 4, p2w);

            // C-fragment IS the A-fragment (reorder only), PV mma right away
            uint32_t avA[4], avB[4];
            avA[0] = f2tf(p1x); avA[1] = f2tf(p1z); avA[2] = f2tf(p1y); avA[3] = f2tf(p1w);
            avB[0] = f2tf(p2x); avB[1] = f2tf(p2z); avB[2] = f2tf(p2y); avB[3] = f2tf(p2w);
#pragma unroll
            for (int j2 = 0; j2 < 4; j2++) {
                uint32_t bf[2];
                bf[0] = VA[(j * 8 + tig) * 40 + j2 * 8 + gid];
                bf[1] = VA[(j * 8 + tig + 4) * 40 + j2 * 8 + gid];
                mma_tf32(o[0][j2], avA, bf);
                bf[0] = VB[(j * 8 + tig) * 40 + j2 * 8 + gid];
                bf[1] = VB[(j * 8 + tig + 4) * 40 + j2 * 8 + gid];
                mma_tf32(o[1][j2], avB, bf);
            }
        }

        // stash prefetched K/V into the other buffer (vectorized)
        if (kt < 31) {
            stage4(sm + KSOFF(0, cur ^ 1) + sr0 * 36 + sc0, k1n);
            stage4(sm + KSOFF(1, cur ^ 1) + sr0 * 36 + sc0, k2n);
            stage4(sm + VSOFF(0, cur ^ 1) + sr0 * 40 + sc0, v1n);
            stage4(sm + VSOFF(1, cur ^ 1) + sr0 * 40 + sc0, v2n);
        }
        __syncthreads();
    }

    // epilogue: O -> g_ocat
#pragma unroll
    for (int st = 0; st < 2; st++) {
#pragma unroll
        for (int j2 = 0; j2 < 4; j2++) {
            const int d0 = j2 * 8 + tig * 2;
            float* o0 = &g_ocat[((size_t)(st * 4 + b) * SDIM + q0) * EDIM + h * 32 + d0];
            float* o1 = &g_ocat[((size_t)(st * 4 + b) * SDIM + q0 + 8) * EDIM + h * 32 + d0];
            *reinterpret_cast<float2*>(o0) = make_float2(o[st][j2][0], o[st][j2][1]);
            *reinterpret_cast<float2*>(o1) = make_float2(o[st][j2][2], o[st][j2][3]);
        }
    }
}

// ---------------------------------------------------------------------------
// Kernel 4: batched output projection (fp32, accuracy headroom). grid.z = st.
// ---------------------------------------------------------------------------
struct OutArgs {
    const float* w[2];
    const float* b[2];
};

__global__ __launch_bounds__(256) void outproj_kernel(OutArgs args, float* __restrict__ dout)
{
    __shared__ float As[16][64];
    __shared__ float Bs[16][64];
    const int st = blockIdx.z;
    const float* W = args.w[st];
    const float* bias = args.b[st];
    float* out = dout + (size_t)st * (SDIM * BDIM * EDIM);

    const int bm = blockIdx.y * 64;
    const int bn = blockIdx.x * 64;
    const int tid = threadIdx.x;
    const int tx = tid & 15;
    const int ty = tid >> 4;
    const float* A = g_ocat + (size_t)st * (BDIM * SDIM * EDIM);

    float acc[4][4] = {};
    const int lrow = tid >> 2;
    const int lcol = (tid & 3) * 4;

    for (int k0 = 0; k0 < 256; k0 += 16) {
        float4 va = *reinterpret_cast<const float4*>(A + (size_t)(bm + lrow) * 256 + k0 + lcol);
        float4 vb = *reinterpret_cast<const float4*>(W + (size_t)(bn + lrow) * 256 + k0 + lcol);
        As[lcol + 0][lrow] = va.x; As[lcol + 1][lrow] = va.y;
        As[lcol + 2][lrow] = va.z; As[lcol + 3][lrow] = va.w;
        Bs[lcol + 0][lrow] = vb.x; Bs[lcol + 1][lrow] = vb.y;
        Bs[lcol + 2][lrow] = vb.z; Bs[lcol + 3][lrow] = vb.w;
        __syncthreads();
#pragma unroll
        for (int kk = 0; kk < 16; kk++) {
            float a[4], b[4];
#pragma unroll
            for (int i = 0; i < 4; i++) a[i] = As[kk][ty * 4 + i];
#pragma unroll
            for (int j = 0; j < 4; j++) b[j] = Bs[kk][tx * 4 + j];
#pragma unroll
            for (int i = 0; i < 4; i++)
#pragma unroll
                for (int j = 0; j < 4; j++) acc[i][j] += a[i] * b[j];
        }
        __syncthreads();
    }

#pragma unroll
    for (int i = 0; i < 4; i++) {
        const int m = bm + ty * 4 + i;     // m = b*1024 + s
        const int b = m >> 10;
        const int s = m & 1023;
#pragma unroll
        for (int j = 0; j < 4; j++) {
            const int n = bn + tx * 4 + j;
            out[(size_t)(s * 4 + b) * 256 + n] = acc[i][j] + bias[n];
        }
    }
}

// ---------------------------------------------------------------------------
extern "C" void kernel_launch(void* const* d_in, const int* in_sizes, int n_in,
                              void* d_out, int out_size)
{
    const unsigned char* mask = (const unsigned char*)d_in[6];
    const float* alpha = (const float*)d_in[15];
    const float* beta  = (const float*)d_in[16];
    float* out = (float*)d_out;

    cudaFuncSetAttribute(attn_fused_kernel,
                         cudaFuncAttributeMaxDynamicSharedMemorySize, FUSED_SMEM);

    // 0) zero exp-sum accumulators
    zero_sums_kernel<<<256, 256>>>();

    // 1) all six QKV projections in one launch (tf32 mma)
    ProjArgs pa;
    for (int i = 0; i < 6; i++) pa.x[i] = (const float*)d_in[i];
    pa.w[0] = (const float*)d_in[7];  pa.b[0] = (const float*)d_in[8];
    pa.w[1] = (const float*)d_in[11]; pa.b[1] = (const float*)d_in[12];
    proj_tf32_kernel<<<dim3(2, 32, 6), 256>>>(pa);

    // 2) exp-sum stats only (no score writes)
    sums_kernel<<<dim3(8, 8, 64), 256>>>(mask);

    // 3) fully fused: permuted scores + normalize + blend + prob write + P@V
    attn_fused_kernel<<<dim3(8, 32), 256, FUSED_SMEM>>>(out, mask, alpha, beta);

    // 4) both output projections in one launch (fp32)
    OutArgs oa;
    oa.w[0] = (const float*)d_in[9];  oa.b[0] = (const float*)d_in[10];
    oa.w[1] = (const float*)d_in[13]; oa.b[1] = (const float*)d_in[14];
    outproj_kernel<<<dim3(4, 64, 2), 256>>>(oa, out);
}

// round 12
// speedup vs baseline: 1.0739x; 1.0739x over previous
#include <cuda_runtime.h>
#include <cuda_bf16.h>
#include <math_constants.h>
#include <cstdint>

// Problem constants
#define SDIM 1024
#define BDIM 4
#define EDIM 256
#define HDIM 8
#define DDIM 32

// d_out layout: out_rgb [S,B,E], out_dpt [S,B,E], shared_rgb [B,H,S,S], shared_dpt [B,H,S,S]
#define OFF_OUT_RGB  0
#define OFF_OUT_DPT  (SDIM*BDIM*EDIM)              // 1048576
#define OFF_SHARED   (2*SDIM*BDIM*EDIM)            // 2097152
#define BHSS         ((size_t)BDIM*HDIM*SDIM*SDIM) // 33554432

#define SCALE 0.17677669529663687f   // 1/sqrt(32)

// Scratch. g_qkv holds TF32-PRE-ROUNDED values (f2tf applied at producer;
// consumers use the bits directly — f2tf is idempotent so numerics are
// identical to converting at the consumer).
__device__ float g_qkv[6 * BDIM * HDIM * SDIM * DDIM];   // 25 MB
__device__ float g_ocat[2 * BDIM * SDIM * EDIM];         // 8 MB
__device__ float g_sums[2 * 32 * SDIM];                  // exp-sums per (st,bh,q)

// ---------------------------------------------------------------------------
// tf32 helpers (mma.sync m16n8k8, fp32 accum)
// ---------------------------------------------------------------------------
__device__ __forceinline__ uint32_t f2tf(float f) {
    uint32_t u;
    asm("cvt.rna.tf32.f32 %0, %1;" : "=r"(u) : "f"(f));
    return u;
}

__device__ __forceinline__ void mma_tf32(float* d, const uint32_t* a, const uint32_t* b) {
    asm volatile(
        "mma.sync.aligned.m16n8k8.row.col.f32.tf32.tf32.f32 "
        "{%0,%1,%2,%3}, {%4,%5,%6,%7}, {%8,%9}, {%0,%1,%2,%3};"
        : "+f"(d[0]), "+f"(d[1]), "+f"(d[2]), "+f"(d[3])
        : "r"(a[0]), "r"(a[1]), "r"(a[2]), "r"(a[3]),
          "r"(b[0]), "r"(b[1]));
}

// Convert a score C-fragment (16x8 tile: thread holds cols 2*tig, 2*tig+1 of
// rows gid, gid+8) into a PV A-fragment (thread needs cols tig, tig+4) via
// warp shuffles. No smem, no barrier.
__device__ __forceinline__ void c2a(uint32_t* av, float c0, float c1,
                                    float c2, float c3, int gid, int tig)
{
    const unsigned FULL = 0xffffffffu;
    const int base = gid * 4 + (tig >> 1);
    float x0 = __shfl_sync(FULL, c0, base);
    float x1 = __shfl_sync(FULL, c1, base);
    float y0 = __shfl_sync(FULL, c2, base);
    float y1 = __shfl_sync(FULL, c3, base);
    float z0 = __shfl_sync(FULL, c0, base + 2);
    float z1 = __shfl_sync(FULL, c1, base + 2);
    float w0 = __shfl_sync(FULL, c2, base + 2);
    float w1 = __shfl_sync(FULL, c3, base + 2);
    const bool odd = tig & 1;
    av[0] = f2tf(odd ? x1 : x0);
    av[1] = f2tf(odd ? y1 : y0);
    av[2] = f2tf(odd ? z1 : z0);
    av[3] = f2tf(odd ? w1 : w0);
}

// 16-byte async copy gmem -> smem (L2-cached, bypasses L1 register path)
__device__ __forceinline__ void cpa16(uint32_t* smem_dst, const float* gsrc) {
    uint32_t sa = (uint32_t)__cvta_generic_to_shared(smem_dst);
    asm volatile("cp.async.cg.shared.global [%0], [%1], 16;" :: "r"(sa), "l"(gsrc));
}
__device__ __forceinline__ void cpa_commit() {
    asm volatile("cp.async.commit_group;");
}
__device__ __forceinline__ void cpa_wait0() {
    asm volatile("cp.async.wait_group 0;");
}

// ---------------------------------------------------------------------------
// Kernel 0: zero the sums accumulator (graph-replayed every launch)
// ---------------------------------------------------------------------------
__global__ void zero_sums_kernel() {
    g_sums[blockIdx.x * 256 + threadIdx.x] = 0.f;
}

// ---------------------------------------------------------------------------
// Kernel 1: batched QKV projection via tf32 mma. grid.z = proj id 0..5.
// Epilogue writes TF32-ROUNDED bits into g_qkv.
// ---------------------------------------------------------------------------
struct ProjArgs {
    const float* x[6];
    const float* w[2];
    const float* b[2];
};

__global__ __launch_bounds__(256) void proj_tf32_kernel(ProjArgs args)
{
    __shared__ uint32_t As[128][36];
    __shared__ uint32_t Bs[128][36];
    const int proj = blockIdx.z;
    const int st = proj / 3;
    const int wsel = proj - st * 3;
    const float* x = args.x[proj];
    const float* W = args.w[st] + (size_t)wsel * 256 * 256;
    const float* bias = args.b[st] + wsel * 256;

    const int bm = blockIdx.y * 128;
    const int bn = blockIdx.x * 128;
    const int tid = threadIdx.x;
    const int wid = tid >> 5;
    const int lane = tid & 31;
    const int gid = lane >> 2;
    const int tig = lane & 3;
    const int wm = (wid & 3) * 32;
    const int wn = (wid >> 2) * 64;

    const int sr0 = tid >> 3;            // 0..31, +32*t
    const int sc0 = (tid & 7) * 4;       // 0,4,..28

    float4 pa[4], pb[4];
#pragma unroll
    for (int t = 0; t < 4; t++) {
        pa[t] = *reinterpret_cast<const float4*>(x + (size_t)(bm + sr0 + t * 32) * 256 + sc0);
        pb[t] = *reinterpret_cast<const float4*>(W + (size_t)(bn + sr0 + t * 32) * 256 + sc0);
    }

    float acc[2][8][4] = {};

    for (int kt = 0; kt < 8; kt++) {
#pragma unroll
        for (int t = 0; t < 4; t++) {
            const int r = sr0 + t * 32;
            As[r][sc0 + 0] = f2tf(pa[t].x); As[r][sc0 + 1] = f2tf(pa[t].y);
            As[r][sc0 + 2] = f2tf(pa[t].z); As[r][sc0 + 3] = f2tf(pa[t].w);
            Bs[r][sc0 + 0] = f2tf(pb[t].x); Bs[r][sc0 + 1] = f2tf(pb[t].y);
            Bs[r][sc0 + 2] = f2tf(pb[t].z); Bs[r][sc0 + 3] = f2tf(pb[t].w);
        }
        __syncthreads();

        if (kt < 7) {
            const int k0 = (kt + 1) * 32;
#pragma unroll
            for (int t = 0; t < 4; t++) {
                pa[t] = *reinterpret_cast<const float4*>(x + (size_t)(bm + sr0 + t * 32) * 256 + k0 + sc0);
                pb[t] = *reinterpret_cast<const float4*>(W + (size_t)(bn + sr0 + t * 32) * 256 + k0 + sc0);
            }
        }

#pragma unroll
        for (int kc = 0; kc < 4; kc++) {
            const int k8 = kc * 8;
            uint32_t a[2][4], b[8][2];
#pragma unroll
            for (int i = 0; i < 2; i++) {
                const int r = wm + i * 16;
                a[i][0] = As[r + gid][k8 + tig];
                a[i][1] = As[r + gid + 8][k8 + tig];
                a[i][2] = As[r + gid][k8 + tig + 4];
                a[i][3] = As[r + gid + 8][k8 + tig + 4];
            }
#pragma unroll
            for (int j = 0; j < 8; j++) {
                const int c = wn + j * 8;
                b[j][0] = Bs[c + gid][k8 + tig];
                b[j][1] = Bs[c + gid][k8 + tig + 4];
            }
#pragma unroll
            for (int i = 0; i < 2; i++)
#pragma unroll
                for (int j = 0; j < 8; j++)
                    mma_tf32(acc[i][j], a[i], b[j]);
        }
        __syncthreads();
    }

#pragma unroll
    for (int i = 0; i < 2; i++) {
        const int m0 = bm + wm + i * 16 + gid;
        const int s0 = m0 >> 2, b0 = m0 & 3;
        const int m1 = m0 + 8;
        const int s1 = m1 >> 2, b1 = m1 & 3;
#pragma unroll
        for (int j = 0; j < 8; j++) {
            const int c0 = bn + wn + j * 8 + tig * 2;
            const int h = c0 >> 5;
            const int d = c0 & 31;
            const float bv0 = bias[c0], bv1 = bias[c0 + 1];
            float* p0 = &g_qkv[(((size_t)(proj * 4 + b0) * 8 + h) * 1024 + s0) * 32 + d];
            float* p1 = &g_qkv[(((size_t)(proj * 4 + b1) * 8 + h) * 1024 + s1) * 32 + d];
            // pre-round to tf32 at the producer (consumers use bits directly)
            *reinterpret_cast<uint2*>(p0) =
                make_uint2(f2tf(acc[i][j][0] + bv0), f2tf(acc[i][j][1] + bv1));
            *reinterpret_cast<uint2*>(p1) =
                make_uint2(f2tf(acc[i][j][2] + bv0), f2tf(acc[i][j][3] + bv1));
        }
    }
}

// ---------------------------------------------------------------------------
// Kernel 2: exp-sum stats only. g_qkv already tf32-rounded -> no conversion.
// Accumulation order matches attn_fused_kernel exactly -> identical values.
// ---------------------------------------------------------------------------
__global__ __launch_bounds__(256) void sums_kernel(const unsigned char* __restrict__ mask)
{
    __shared__ uint32_t Qs[128][36];
    __shared__ uint32_t Ks[128][36];
    const int z = blockIdx.z;
    const int st = z >> 5;
    const int bh = z & 31;
    const int bq = blockIdx.y * 128;
    const int bk = blockIdx.x * 128;

    const float* Q = g_qkv + ((size_t)(st * 3 + 0) * 32 + bh) * (SDIM * DDIM);
    const float* K = g_qkv + ((size_t)(st * 3 + 1) * 32 + bh) * (SDIM * DDIM);

    const int tid = threadIdx.x;
    for (int i = tid * 4; i < 128 * 32; i += 1024) {
        const int r = i >> 5, c = i & 31;
        uint4 q4 = *reinterpret_cast<const uint4*>(Q + (size_t)(bq + r) * 32 + c);
        uint4 k4 = *reinterpret_cast<const uint4*>(K + (size_t)(bk + r) * 32 + c);
        *reinterpret_cast<uint4*>(&Qs[r][c]) = q4;
        *reinterpret_cast<uint4*>(&Ks[r][c]) = k4;
    }
    __syncthreads();

    const int wid = tid >> 5;
    const int lane = tid & 31;
    const int gid = lane >> 2;
    const int tig = lane & 3;
    const int wm = (wid & 3) * 32;
    const int wn = (wid >> 2) * 64;

    float acc[2][8][4] = {};
#pragma unroll
    for (int kc = 0; kc < 4; kc++) {
        const int k0 = kc * 8;
        uint32_t a[2][4], b[8][2];
#pragma unroll
        for (int i = 0; i < 2; i++) {
            const int r = wm + i * 16;
            a[i][0] = Qs[r + gid][k0 + tig];
            a[i][1] = Qs[r + gid + 8][k0 + tig];
            a[i][2] = Qs[r + gid][k0 + tig + 4];
            a[i][3] = Qs[r + gid + 8][k0 + tig + 4];
        }
#pragma unroll
        for (int j = 0; j < 8; j++) {
            const int c = wn + j * 8;
            b[j][0] = Ks[c + gid][k0 + tig];
            b[j][1] = Ks[c + gid][k0 + tig + 4];
        }
#pragma unroll
        for (int i = 0; i < 2; i++)
#pragma unroll
            for (int j = 0; j < 8; j++)
                mma_tf32(acc[i][j], a[i], b[j]);
    }

    const unsigned char* mrow = mask + (size_t)(bh >> 3) * SDIM;
    float* sums = g_sums + (size_t)z * SDIM;
#pragma unroll
    for (int i = 0; i < 2; i++) {
        float slo = 0.f, shi = 0.f;
#pragma unroll
        for (int j = 0; j < 8; j++) {
            const int c0 = bk + wn + j * 8 + tig * 2;
            const float m0 = mrow[c0] ? 0.f : 1.f;
            const float m1 = mrow[c0 + 1] ? 0.f : 1.f;
            slo += m0 * __expf(acc[i][j][0] * SCALE) + m1 * __expf(acc[i][j][1] * SCALE);
            shi += m0 * __expf(acc[i][j][2] * SCALE) + m1 * __expf(acc[i][j][3] * SCALE);
        }
        slo += __shfl_xor_sync(0xffffffffu, slo, 1);
        slo += __shfl_xor_sync(0xffffffffu, slo, 2);
        shi += __shfl_xor_sync(0xffffffffu, shi, 1);
        shi += __shfl_xor_sync(0xffffffffu, shi, 2);
        if (tig == 0) {
            atomicAdd(&sums[bq + wm + i * 16 + gid], slo);
            atomicAdd(&sums[bq + wm + i * 16 + gid + 8], shi);
        }
    }
}

// ---------------------------------------------------------------------------
// Kernel 3 (FULLY FUSED, round-9 structure + cp.async staging):
// recompute QK^T (tf32 mma) + exp/normalize/blend + single prob write (stcs,
// float2) + shuffle C->A fragment + P@V (tf32 mma). K/V tiles staged with
// cp.async.cg (no register round-trip, no conversion -- g_qkv pre-rounded).
// Block = one (b,h), 128 q rows, BOTH streams. 256 threads, 8 warps in m.
// V rows padded to 40 words (conflict-free fragment LDS).
// ---------------------------------------------------------------------------
// smem layout (u32 indices):
#define KSOFF(st,buf)  (((st) * 2 + (buf)) * 1152)         // K tiles 2x2 x 32x36
#define VSOFF(st,buf)  (4608 + ((st) * 2 + (buf)) * 1280)  // V tiles 2x2 x 32x40
#define MSKOFF         9728                                // mask 1024 f32
#define FUSED_SMEM     (10752 * 4)                         // 43008 bytes

__global__ __launch_bounds__(256, 2) void attn_fused_kernel(
    float* __restrict__ dout, const unsigned char* __restrict__ mask,
    const float* __restrict__ alpha_p, const float* __restrict__ beta_p)
{
    extern __shared__ uint32_t sm[];
    float* msk = reinterpret_cast<float*>(sm + MSKOFF);
    const int bh = blockIdx.y;
    const int b = bh >> 3, h = bh & 7;
    const int bq = blockIdx.x * 128;

    const int tid = threadIdx.x;
    const int wid = tid >> 5;
    const int lane = tid & 31;
    const int gid = lane >> 2;
    const int tig = lane & 3;
    const int sr0 = tid >> 3;          // 0..31
    const int sc0 = (tid & 7) * 4;     // 0,4,..28
    const int r = wid * 16;            // warp q-row base (local)

    const float* Q1 = g_qkv + ((size_t)(0) * 32 + bh) * (SDIM * DDIM);
    const float* K1 = g_qkv + ((size_t)(1) * 32 + bh) * (SDIM * DDIM);
    const float* V1 = g_qkv + ((size_t)(2) * 32 + bh) * (SDIM * DDIM);
    const float* Q2 = g_qkv + ((size_t)(3) * 32 + bh) * (SDIM * DDIM);
    const float* K2 = g_qkv + ((size_t)(4) * 32 + bh) * (SDIM * DDIM);
    const float* V2 = g_qkv + ((size_t)(5) * 32 + bh) * (SDIM * DDIM);
    float* S1 = dout + OFF_SHARED + ((size_t)bh * SDIM + bq) * SDIM;
    float* S2 = S1 + BHSS;

    // mask multiplier table
    for (int i = tid; i < SDIM; i += 256)
        msk[i] = mask[(size_t)b * SDIM + i] ? 0.f : 1.f;

    // Q fragments: g_qkv is pre-rounded, use bits directly (no CVT)
    uint32_t qf[2][4][4];
#pragma unroll
    for (int st = 0; st < 2; st++) {
        const uint32_t* Q = reinterpret_cast<const uint32_t*>(st ? Q2 : Q1);
#pragma unroll
        for (int ks = 0; ks < 4; ks++) {
            qf[st][ks][0] = Q[(size_t)(bq + r + gid) * 32 + 8 * ks + tig];
            qf[st][ks][1] = Q[(size_t)(bq + r + gid + 8) * 32 + 8 * ks + tig];
            qf[st][ks][2] = Q[(size_t)(bq + r + gid) * 32 + 8 * ks + tig + 4];
            qf[st][ks][3] = Q[(size_t)(bq + r + gid + 8) * 32 + 8 * ks + tig + 4];
        }
    }

    // blend coefficients folded with inverse sums (per thread's 2 rows)
    const float a = *alpha_p, bt = *beta_p;
    const int q0 = bq + r + gid;
    const float i1lo = 1.f / g_sums[(size_t)bh * SDIM + q0];
    const float i1hi = 1.f / g_sums[(size_t)bh * SDIM + q0 + 8];
    const float i2lo = 1.f / g_sums[(size_t)(32 + bh) * SDIM + q0];
    const float i2hi = 1.f / g_sums[(size_t)(32 + bh) * SDIM + q0 + 8];
    const float c1lo = (1.f - a) * i1lo, c2lo = a * i2lo;
    const float c1hi = (1.f - a) * i1hi, c2hi = a * i2hi;
    const float d2lo = (1.f - bt) * i2lo, d1lo = bt * i1lo;
    const float d2hi = (1.f - bt) * i2hi, d1hi = bt * i1hi;

    // stage K/V tile 0 into buffer 0 via cp.async
    cpa16(sm + KSOFF(0, 0) + sr0 * 36 + sc0, K1 + (size_t)sr0 * 32 + sc0);
    cpa16(sm + KSOFF(1, 0) + sr0 * 36 + sc0, K2 + (size_t)sr0 * 32 + sc0);
    cpa16(sm + VSOFF(0, 0) + sr0 * 40 + sc0, V1 + (size_t)sr0 * 32 + sc0);
    cpa16(sm + VSOFF(1, 0) + sr0 * 40 + sc0, V2 + (size_t)sr0 * 32 + sc0);
    cpa_commit();
    cpa_wait0();
    __syncthreads();

    float o[2][4][4] = {};

    for (int kt = 0; kt < 32; kt++) {
        const int cur = kt & 1;

        // async-prefetch next K/V tiles into the other buffer
        if (kt < 31) {
            const int k0 = (kt + 1) * 32;
            cpa16(sm + KSOFF(0, cur ^ 1) + sr0 * 36 + sc0, K1 + (size_t)(k0 + sr0) * 32 + sc0);
            cpa16(sm + KSOFF(1, cur ^ 1) + sr0 * 36 + sc0, K2 + (size_t)(k0 + sr0) * 32 + sc0);
            cpa16(sm + VSOFF(0, cur ^ 1) + sr0 * 40 + sc0, V1 + (size_t)(k0 + sr0) * 32 + sc0);
            cpa16(sm + VSOFF(1, cur ^ 1) + sr0 * 40 + sc0, V2 + (size_t)(k0 + sr0) * 32 + sc0);
            cpa_commit();
        }

        const uint32_t* KA = sm + KSOFF(0, cur);
        const uint32_t* KB = sm + KSOFF(1, cur);
        const uint32_t* VA = sm + VSOFF(0, cur);
        const uint32_t* VB = sm + VSOFF(1, cur);

        // ---- per 8-key group: scores -> probs -> shuffle -> PV mma ----
#pragma unroll
        for (int j = 0; j < 4; j++) {
            float sA[4] = {}, sB[4] = {};
#pragma unroll
            for (int ks = 0; ks < 4; ks++) {
                uint32_t bf[2];
                bf[0] = KA[(j * 8 + gid) * 36 + 8 * ks + tig];
                bf[1] = KA[(j * 8 + gid) * 36 + 8 * ks + tig + 4];
                mma_tf32(sA, qf[0][ks], bf);
                bf[0] = KB[(j * 8 + gid) * 36 + 8 * ks + tig];
                bf[1] = KB[(j * 8 + gid) * 36 + 8 * ks + tig + 4];
                mma_tf32(sB, qf[1][ks], bf);
            }
            const int c0 = kt * 32 + j * 8 + tig * 2;
            const float2 mp = *reinterpret_cast<const float2*>(msk + c0);
            const float m0 = mp.x, m1 = mp.y;
            const float e1x = m0 * __expf(sA[0] * SCALE), e1y = m1 * __expf(sA[1] * SCALE);
            const float e1z = m0 * __expf(sA[2] * SCALE), e1w = m1 * __expf(sA[3] * SCALE);
            const float e2x = m0 * __expf(sB[0] * SCALE), e2y = m1 * __expf(sB[1] * SCALE);
            const float e2z = m0 * __expf(sB[2] * SCALE), e2w = m1 * __expf(sB[3] * SCALE);
            const float p1x = c1lo * e1x + c2lo * e2x, p1y = c1lo * e1y + c2lo * e2y;
            const float p1z = c1hi * e1z + c2hi * e2z, p1w = c1hi * e1w + c2hi * e2w;
            const float p2x = d2lo * e2x + d1lo * e1x, p2y = d2lo * e2y + d1lo * e1y;
            const float p2z = d2hi * e2z + d1hi * e1z, p2w = d2hi * e2w + d1hi * e1w;
            // single DRAM write of the blended probs (coalesced float2)
            __stcs(reinterpret_cast<float2*>(S1 + (size_t)(r + gid) * SDIM + c0), make_float2(p1x, p1y));
            __stcs(reinterpret_cast<float2*>(S1 + (size_t)(r + gid + 8) * SDIM + c0), make_float2(p1z, p1w));
            __stcs(reinterpret_cast<float2*>(S2 + (size_t)(r + gid) * SDIM + c0), make_float2(p2x, p2y));
            __stcs(reinterpret_cast<float2*>(S2 + (size_t)(r + gid + 8) * SDIM + c0), make_float2(p2z, p2w));

            // C-fragment -> A-fragment in registers, then PV mma right away
            uint32_t avA[4], avB[4];
            c2a(avA, p1x, p1y, p1z, p1w, gid, tig);
            c2a(avB, p2x, p2y, p2z, p2w, gid, tig);
#pragma unroll
            for (int j2 = 0; j2 < 4; j2++) {
                uint32_t bf[2];
                bf[0] = VA[(j * 8 + tig) * 40 + j2 * 8 + gid];
                bf[1] = VA[(j * 8 + tig + 4) * 40 + j2 * 8 + gid];
                mma_tf32(o[0][j2], avA, bf);
                bf[0] = VB[(j * 8 + tig) * 40 + j2 * 8 + gid];
                bf[1] = VB[(j * 8 + tig + 4) * 40 + j2 * 8 + gid];
                mma_tf32(o[1][j2], avB, bf);
            }
        }

        if (kt < 31) cpa_wait0();   // next tile landed (compute already done)
        __syncthreads();
    }

    // epilogue: O -> g_ocat
#pragma unroll
    for (int st = 0; st < 2; st++) {
#pragma unroll
        for (int j2 = 0; j2 < 4; j2++) {
            const int d0 = j2 * 8 + tig * 2;
            float* o0 = &g_ocat[((size_t)(st * 4 + b) * SDIM + q0) * EDIM + h * 32 + d0];
            float* o1 = &g_ocat[((size_t)(st * 4 + b) * SDIM + q0 + 8) * EDIM + h * 32 + d0];
            *reinterpret_cast<float2*>(o0) = make_float2(o[st][j2][0], o[st][j2][1]);
            *reinterpret_cast<float2*>(o1) = make_float2(o[st][j2][2], o[st][j2][3]);
        }
    }
}

// ---------------------------------------------------------------------------
// Kernel 4: batched output projection (fp32, accuracy headroom). grid.z = st.
// ---------------------------------------------------------------------------
struct OutArgs {
    const float* w[2];
    const float* b[2];
};

__global__ __launch_bounds__(256) void outproj_kernel(OutArgs args, float* __restrict__ dout)
{
    __shared__ float As[16][64];
    __shared__ float Bs[16][64];
    const int st = blockIdx.z;
    const float* W = args.w[st];
    const float* bias = args.b[st];
    float* out = dout + (size_t)st * (SDIM * BDIM * EDIM);

    const int bm = blockIdx.y * 64;
    const int bn = blockIdx.x * 64;
    const int tid = threadIdx.x;
    const int tx = tid & 15;
    const int ty = tid >> 4;
    const float* A = g_ocat + (size_t)st * (BDIM * SDIM * EDIM);

    float acc[4][4] = {};
    const int lrow = tid >> 2;
    const int lcol = (tid & 3) * 4;

    for (int k0 = 0; k0 < 256; k0 += 16) {
        float4 va = *reinterpret_cast<const float4*>(A + (size_t)(bm + lrow) * 256 + k0 + lcol);
        float4 vb = *reinterpret_cast<const float4*>(W + (size_t)(bn + lrow) * 256 + k0 + lcol);
        As[lcol + 0][lrow] = va.x; As[lcol + 1][lrow] = va.y;
        As[lcol + 2][lrow] = va.z; As[lcol + 3][lrow] = va.w;
        Bs[lcol + 0][lrow] = vb.x; Bs[lcol + 1][lrow] = vb.y;
        Bs[lcol + 2][lrow] = vb.z; Bs[lcol + 3][lrow] = vb.w;
        __syncthreads();
#pragma unroll
        for (int kk = 0; kk < 16; kk++) {
            float a[4], b[4];
#pragma unroll
            for (int i = 0; i < 4; i++) a[i] = As[kk][ty * 4 + i];
#pragma unroll
            for (int j = 0; j < 4; j++) b[j] = Bs[kk][tx * 4 + j];
#pragma unroll
            for (int i = 0; i < 4; i++)
#pragma unroll
                for (int j = 0; j < 4; j++) acc[i][j] += a[i] * b[j];
        }
        __syncthreads();
    }

#pragma unroll
    for (int i = 0; i < 4; i++) {
        const int m = bm + ty * 4 + i;     // m = b*1024 + s
        const int b = m >> 10;
        const int s = m & 1023;
#pragma unroll
        for (int j = 0; j < 4; j++) {
            const int n = bn + tx * 4 + j;
            out[(size_t)(s * 4 + b) * 256 + n] = acc[i][j] + bias[n];
        }
    }
}

// ---------------------------------------------------------------------------
extern "C" void kernel_launch(void* const* d_in, const int* in_sizes, int n_in,
                              void* d_out, int out_size)
{
    const unsigned char* mask = (const unsigned char*)d_in[6];
    const float* alpha = (const float*)d_in[15];
    const float* beta  = (const float*)d_in[16];
    float* out = (float*)d_out;

    cudaFuncSetAttribute(attn_fused_kernel,
                         cudaFuncAttributeMaxDynamicSharedMemorySize, FUSED_SMEM);

    // 0) zero exp-sum accumulators
    zero_sums_kernel<<<256, 256>>>();

    // 1) all six QKV projections in one launch (tf32 mma, pre-rounded output)
    ProjArgs pa;
    for (int i = 0; i < 6; i++) pa.x[i] = (const float*)d_in[i];
    pa.w[0] = (const float*)d_in[7];  pa.b[0] = (const float*)d_in[8];
    pa.w[1] = (const float*)d_in[11]; pa.b[1] = (const float*)d_in[12];
    proj_tf32_kernel<<<dim3(2, 32, 6), 256>>>(pa);

    // 2) exp-sum stats only (no score writes)
    sums_kernel<<<dim3(8, 8, 64), 256>>>(mask);

    // 3) fully fused: recompute scores + normalize + blend + prob write + P@V
    attn_fused_kernel<<<dim3(8, 32), 256, FUSED_SMEM>>>(out, mask, alpha, beta);

    // 4) both output projections in one launch (fp32)
    OutArgs oa;
    oa.w[0] = (const float*)d_in[9];  oa.b[0] = (const float*)d_in[10];
    oa.w[1] = (const float*)d_in[13]; oa.b[1] = (const float*)d_in[14];
    outproj_kernel<<<dim3(4, 64, 2), 256>>>(oa, out);
}

// round 13
// speedup vs baseline: 1.1752x; 1.0944x over previous
#include <cuda_runtime.h>
#include <cuda_bf16.h>
#include <math_constants.h>
#include <cstdint>

// Problem constants
#define SDIM 1024
#define BDIM 4
#define EDIM 256
#define HDIM 8
#define DDIM 32

// d_out layout: out_rgb [S,B,E], out_dpt [S,B,E], shared_rgb [B,H,S,S], shared_dpt [B,H,S,S]
#define OFF_OUT_RGB  0
#define OFF_OUT_DPT  (SDIM*BDIM*EDIM)              // 1048576
#define OFF_SHARED   (2*SDIM*BDIM*EDIM)            // 2097152
#define BHSS         ((size_t)BDIM*HDIM*SDIM*SDIM) // 33554432

#define SCALE 0.17677669529663687f   // 1/sqrt(32)

// Scratch. g_qkv holds TF32-PRE-ROUNDED values (f2tf applied at producer).
__device__ float g_qkv[6 * BDIM * HDIM * SDIM * DDIM];   // 25 MB
__device__ float g_ocat[2 * BDIM * SDIM * EDIM];         // 8 MB
__device__ float g_sums[2 * 32 * SDIM];                  // exp-sums per (st,bh,q)

// ---------------------------------------------------------------------------
// tf32 helpers (mma.sync m16n8k8, fp32 accum)
// ---------------------------------------------------------------------------
__device__ __forceinline__ uint32_t f2tf(float f) {
    uint32_t u;
    asm("cvt.rna.tf32.f32 %0, %1;" : "=r"(u) : "f"(f));
    return u;
}

__device__ __forceinline__ void mma_tf32(float* d, const uint32_t* a, const uint32_t* b) {
    asm volatile(
        "mma.sync.aligned.m16n8k8.row.col.f32.tf32.tf32.f32 "
        "{%0,%1,%2,%3}, {%4,%5,%6,%7}, {%8,%9}, {%0,%1,%2,%3};"
        : "+f"(d[0]), "+f"(d[1]), "+f"(d[2]), "+f"(d[3])
        : "r"(a[0]), "r"(a[1]), "r"(a[2]), "r"(a[3]),
          "r"(b[0]), "r"(b[1]));
}

// Convert a score C-fragment (16x8 tile) into a PV A-fragment via shuffles.
__device__ __forceinline__ void c2a(uint32_t* av, float c0, float c1,
                                    float c2, float c3, int gid, int tig)
{
    const unsigned FULL = 0xffffffffu;
    const int base = gid * 4 + (tig >> 1);
    float x0 = __shfl_sync(FULL, c0, base);
    float x1 = __shfl_sync(FULL, c1, base);
    float y0 = __shfl_sync(FULL, c2, base);
    float y1 = __shfl_sync(FULL, c3, base);
    float z0 = __shfl_sync(FULL, c0, base + 2);
    float z1 = __shfl_sync(FULL, c1, base + 2);
    float w0 = __shfl_sync(FULL, c2, base + 2);
    float w1 = __shfl_sync(FULL, c3, base + 2);
    const bool odd = tig & 1;
    av[0] = f2tf(odd ? x1 : x0);
    av[1] = f2tf(odd ? y1 : y0);
    av[2] = f2tf(odd ? z1 : z0);
    av[3] = f2tf(odd ? w1 : w0);
}

// 16-byte async copy gmem -> smem
__device__ __forceinline__ void cpa16(uint32_t* smem_dst, const float* gsrc) {
    uint32_t sa = (uint32_t)__cvta_generic_to_shared(smem_dst);
    asm volatile("cp.async.cg.shared.global [%0], [%1], 16;" :: "r"(sa), "l"(gsrc));
}
__device__ __forceinline__ void cpa_commit() {
    asm volatile("cp.async.commit_group;");
}
__device__ __forceinline__ void cpa_wait0() {
    asm volatile("cp.async.wait_group 0;");
}

// ---------------------------------------------------------------------------
// Kernel 0: zero the sums accumulator
// ---------------------------------------------------------------------------
__global__ void zero_sums_kernel() {
    g_sums[blockIdx.x * 256 + threadIdx.x] = 0.f;
}

// ---------------------------------------------------------------------------
// Kernel 1: batched QKV projection via tf32 mma. grid.z = proj id 0..5.
// Epilogue writes TF32-ROUNDED bits into g_qkv.
// ---------------------------------------------------------------------------
struct ProjArgs {
    const float* x[6];
    const float* w[2];
    const float* b[2];
};

__global__ __launch_bounds__(256) void proj_tf32_kernel(ProjArgs args)
{
    __shared__ uint32_t As[128][36];
    __shared__ uint32_t Bs[128][36];
    const int proj = blockIdx.z;
    const int st = proj / 3;
    const int wsel = proj - st * 3;
    const float* x = args.x[proj];
    const float* W = args.w[st] + (size_t)wsel * 256 * 256;
    const float* bias = args.b[st] + wsel * 256;

    const int bm = blockIdx.y * 128;
    const int bn = blockIdx.x * 128;
    const int tid = threadIdx.x;
    const int wid = tid >> 5;
    const int lane = tid & 31;
    const int gid = lane >> 2;
    const int tig = lane & 3;
    const int wm = (wid & 3) * 32;
    const int wn = (wid >> 2) * 64;

    const int sr0 = tid >> 3;            // 0..31, +32*t
    const int sc0 = (tid & 7) * 4;       // 0,4,..28

    float4 pa[4], pb[4];
#pragma unroll
    for (int t = 0; t < 4; t++) {
        pa[t] = *reinterpret_cast<const float4*>(x + (size_t)(bm + sr0 + t * 32) * 256 + sc0);
        pb[t] = *reinterpret_cast<const float4*>(W + (size_t)(bn + sr0 + t * 32) * 256 + sc0);
    }

    float acc[2][8][4] = {};

    for (int kt = 0; kt < 8; kt++) {
#pragma unroll
        for (int t = 0; t < 4; t++) {
            const int r = sr0 + t * 32;
            As[r][sc0 + 0] = f2tf(pa[t].x); As[r][sc0 + 1] = f2tf(pa[t].y);
            As[r][sc0 + 2] = f2tf(pa[t].z); As[r][sc0 + 3] = f2tf(pa[t].w);
            Bs[r][sc0 + 0] = f2tf(pb[t].x); Bs[r][sc0 + 1] = f2tf(pb[t].y);
            Bs[r][sc0 + 2] = f2tf(pb[t].z); Bs[r][sc0 + 3] = f2tf(pb[t].w);
        }
        __syncthreads();

        if (kt < 7) {
            const int k0 = (kt + 1) * 32;
#pragma unroll
            for (int t = 0; t < 4; t++) {
                pa[t] = *reinterpret_cast<const float4*>(x + (size_t)(bm + sr0 + t * 32) * 256 + k0 + sc0);
                pb[t] = *reinterpret_cast<const float4*>(W + (size_t)(bn + sr0 + t * 32) * 256 + k0 + sc0);
            }
        }

#pragma unroll
        for (int kc = 0; kc < 4; kc++) {
            const int k8 = kc * 8;
            uint32_t a[2][4], b[8][2];
#pragma unroll
            for (int i = 0; i < 2; i++) {
                const int r = wm + i * 16;
                a[i][0] = As[r + gid][k8 + tig];
                a[i][1] = As[r + gid + 8][k8 + tig];
                a[i][2] = As[r + gid][k8 + tig + 4];
                a[i][3] = As[r + gid + 8][k8 + tig + 4];
            }
#pragma unroll
            for (int j = 0; j < 8; j++) {
                const int c = wn + j * 8;
                b[j][0] = Bs[c + gid][k8 + tig];
                b[j][1] = Bs[c + gid][k8 + tig + 4];
            }
#pragma unroll
            for (int i = 0; i < 2; i++)
#pragma unroll
                for (int j = 0; j < 8; j++)
                    mma_tf32(acc[i][j], a[i], b[j]);
        }
        __syncthreads();
    }

#pragma unroll
    for (int i = 0; i < 2; i++) {
        const int m0 = bm + wm + i * 16 + gid;
        const int s0 = m0 >> 2, b0 = m0 & 3;
        const int m1 = m0 + 8;
        const int s1 = m1 >> 2, b1 = m1 & 3;
#pragma unroll
        for (int j = 0; j < 8; j++) {
            const int c0 = bn + wn + j * 8 + tig * 2;
            const int h = c0 >> 5;
            const int d = c0 & 31;
            const float bv0 = bias[c0], bv1 = bias[c0 + 1];
            float* p0 = &g_qkv[(((size_t)(proj * 4 + b0) * 8 + h) * 1024 + s0) * 32 + d];
            float* p1 = &g_qkv[(((size_t)(proj * 4 + b1) * 8 + h) * 1024 + s1) * 32 + d];
            *reinterpret_cast<uint2*>(p0) =
                make_uint2(f2tf(acc[i][j][0] + bv0), f2tf(acc[i][j][1] + bv1));
            *reinterpret_cast<uint2*>(p1) =
                make_uint2(f2tf(acc[i][j][2] + bv0), f2tf(acc[i][j][3] + bv1));
        }
    }
}

// ---------------------------------------------------------------------------
// Kernel 2: exp-sum stats only. g_qkv already tf32-rounded -> no conversion.
// ---------------------------------------------------------------------------
__global__ __launch_bounds__(256) void sums_kernel(const unsigned char* __restrict__ mask)
{
    __shared__ uint32_t Qs[128][36];
    __shared__ uint32_t Ks[128][36];
    const int z = blockIdx.z;
    const int st = z >> 5;
    const int bh = z & 31;
    const int bq = blockIdx.y * 128;
    const int bk = blockIdx.x * 128;

    const float* Q = g_qkv + ((size_t)(st * 3 + 0) * 32 + bh) * (SDIM * DDIM);
    const float* K = g_qkv + ((size_t)(st * 3 + 1) * 32 + bh) * (SDIM * DDIM);

    const int tid = threadIdx.x;
    for (int i = tid * 4; i < 128 * 32; i += 1024) {
        const int r = i >> 5, c = i & 31;
        uint4 q4 = *reinterpret_cast<const uint4*>(Q + (size_t)(bq + r) * 32 + c);
        uint4 k4 = *reinterpret_cast<const uint4*>(K + (size_t)(bk + r) * 32 + c);
        *reinterpret_cast<uint4*>(&Qs[r][c]) = q4;
        *reinterpret_cast<uint4*>(&Ks[r][c]) = k4;
    }
    __syncthreads();

    const int wid = tid >> 5;
    const int lane = tid & 31;
    const int gid = lane >> 2;
    const int tig = lane & 3;
    const int wm = (wid & 3) * 32;
    const int wn = (wid >> 2) * 64;

    float acc[2][8][4] = {};
#pragma unroll
    for (int kc = 0; kc < 4; kc++) {
        const int k0 = kc * 8;
        uint32_t a[2][4], b[8][2];
#pragma unroll
        for (int i = 0; i < 2; i++) {
            const int r = wm + i * 16;
            a[i][0] = Qs[r + gid][k0 + tig];
            a[i][1] = Qs[r + gid + 8][k0 + tig];
            a[i][2] = Qs[r + gid][k0 + tig + 4];
            a[i][3] = Qs[r + gid + 8][k0 + tig + 4];
        }
#pragma unroll
        for (int j = 0; j < 8; j++) {
            const int c = wn + j * 8;
            b[j][0] = Ks[c + gid][k0 + tig];
            b[j][1] = Ks[c + gid][k0 + tig + 4];
        }
#pragma unroll
        for (int i = 0; i < 2; i++)
#pragma unroll
            for (int j = 0; j < 8; j++)
                mma_tf32(acc[i][j], a[i], b[j]);
    }

    const unsigned char* mrow = mask + (size_t)(bh >> 3) * SDIM;
    float* sums = g_sums + (size_t)z * SDIM;
#pragma unroll
    for (int i = 0; i < 2; i++) {
        float slo = 0.f, shi = 0.f;
#pragma unroll
        for (int j = 0; j < 8; j++) {
            const int c0 = bk + wn + j * 8 + tig * 2;
            const float m0 = mrow[c0] ? 0.f : 1.f;
            const float m1 = mrow[c0 + 1] ? 0.f : 1.f;
            slo += m0 * __expf(acc[i][j][0] * SCALE) + m1 * __expf(acc[i][j][1] * SCALE);
            shi += m0 * __expf(acc[i][j][2] * SCALE) + m1 * __expf(acc[i][j][3] * SCALE);
        }
        slo += __shfl_xor_sync(0xffffffffu, slo, 1);
        slo += __shfl_xor_sync(0xffffffffu, slo, 2);
        shi += __shfl_xor_sync(0xffffffffu, shi, 1);
        shi += __shfl_xor_sync(0xffffffffu, shi, 2);
        if (tig == 0) {
            atomicAdd(&sums[bq + wm + i * 16 + gid], slo);
            atomicAdd(&sums[bq + wm + i * 16 + gid + 8], shi);
        }
    }
}

// ---------------------------------------------------------------------------
// Kernel 3 (FULLY FUSED): 64 q-rows / 128 threads / 4 warps per CTA.
// Grid 512 CTAs -> 4 CTAs/SM (reg-limited), much better SM load balance than
// the previous 256x256-thread config (2-vs-1 CTA skew). Per-warp code is
// identical to round 11 -> bitwise-identical numerics.
// ---------------------------------------------------------------------------
// smem layout (u32 indices):
#define KSOFF(st,buf)  (((st) * 2 + (buf)) * 1152)         // K tiles 2x2 x 32x36
#define VSOFF(st,buf)  (4608 + ((st) * 2 + (buf)) * 1280)  // V tiles 2x2 x 32x40
#define MSKOFF         9728                                // mask 1024 f32
#define FUSED_SMEM     (10752 * 4)                         // 43008 bytes

__global__ __launch_bounds__(128, 4) void attn_fused_kernel(
    float* __restrict__ dout, const unsigned char* __restrict__ mask,
    const float* __restrict__ alpha_p, const float* __restrict__ beta_p)
{
    extern __shared__ uint32_t sm[];
    float* msk = reinterpret_cast<float*>(sm + MSKOFF);
    const int bh = blockIdx.y;
    const int b = bh >> 3, h = bh & 7;
    const int bq = blockIdx.x * 64;

    const int tid = threadIdx.x;
    const int wid = tid >> 5;          // 0..3
    const int lane = tid & 31;
    const int gid = lane >> 2;
    const int tig = lane & 3;
    const int sr0 = tid >> 3;          // 0..15 (stage rows sr0, sr0+16)
    const int sc0 = (tid & 7) * 4;     // 0,4,..28
    const int r = wid * 16;            // warp q-row base (local, 0..48)

    const float* Q1 = g_qkv + ((size_t)(0) * 32 + bh) * (SDIM * DDIM);
    const float* K1 = g_qkv + ((size_t)(1) * 32 + bh) * (SDIM * DDIM);
    const float* V1 = g_qkv + ((size_t)(2) * 32 + bh) * (SDIM * DDIM);
    const float* Q2 = g_qkv + ((size_t)(3) * 32 + bh) * (SDIM * DDIM);
    const float* K2 = g_qkv + ((size_t)(4) * 32 + bh) * (SDIM * DDIM);
    const float* V2 = g_qkv + ((size_t)(5) * 32 + bh) * (SDIM * DDIM);
    float* S1 = dout + OFF_SHARED + ((size_t)bh * SDIM + bq) * SDIM;
    float* S2 = S1 + BHSS;

    // mask multiplier table
    for (int i = tid; i < SDIM; i += 128)
        msk[i] = mask[(size_t)b * SDIM + i] ? 0.f : 1.f;

    // Q fragments: g_qkv is pre-rounded, use bits directly (no CVT)
    uint32_t qf[2][4][4];
#pragma unroll
    for (int st = 0; st < 2; st++) {
        const uint32_t* Q = reinterpret_cast<const uint32_t*>(st ? Q2 : Q1);
#pragma unroll
        for (int ks = 0; ks < 4; ks++) {
            qf[st][ks][0] = Q[(size_t)(bq + r + gid) * 32 + 8 * ks + tig];
            qf[st][ks][1] = Q[(size_t)(bq + r + gid + 8) * 32 + 8 * ks + tig];
            qf[st][ks][2] = Q[(size_t)(bq + r + gid) * 32 + 8 * ks + tig + 4];
            qf[st][ks][3] = Q[(size_t)(bq + r + gid + 8) * 32 + 8 * ks + tig + 4];
        }
    }

    // blend coefficients folded with inverse sums (per thread's 2 rows)
    const float a = *alpha_p, bt = *beta_p;
    const int q0 = bq + r + gid;
    const float i1lo = 1.f / g_sums[(size_t)bh * SDIM + q0];
    const float i1hi = 1.f / g_sums[(size_t)bh * SDIM + q0 + 8];
    const float i2lo = 1.f / g_sums[(size_t)(32 + bh) * SDIM + q0];
    const float i2hi = 1.f / g_sums[(size_t)(32 + bh) * SDIM + q0 + 8];
    const float c1lo = (1.f - a) * i1lo, c2lo = a * i2lo;
    const float c1hi = (1.f - a) * i1hi, c2hi = a * i2hi;
    const float d2lo = (1.f - bt) * i2lo, d1lo = bt * i1lo;
    const float d2hi = (1.f - bt) * i2hi, d1hi = bt * i1hi;

    // stage K/V tile 0 into buffer 0 via cp.async (2 rows per thread)
#pragma unroll
    for (int t = 0; t < 2; t++) {
        const int rr = sr0 + t * 16;
        cpa16(sm + KSOFF(0, 0) + rr * 36 + sc0, K1 + (size_t)rr * 32 + sc0);
        cpa16(sm + KSOFF(1, 0) + rr * 36 + sc0, K2 + (size_t)rr * 32 + sc0);
        cpa16(sm + VSOFF(0, 0) + rr * 40 + sc0, V1 + (size_t)rr * 32 + sc0);
        cpa16(sm + VSOFF(1, 0) + rr * 40 + sc0, V2 + (size_t)rr * 32 + sc0);
    }
    cpa_commit();
    cpa_wait0();
    __syncthreads();

    float o[2][4][4] = {};

    for (int kt = 0; kt < 32; kt++) {
        const int cur = kt & 1;

        // async-prefetch next K/V tiles into the other buffer
        if (kt < 31) {
            const int k0 = (kt + 1) * 32;
#pragma unroll
            for (int t = 0; t < 2; t++) {
                const int rr = sr0 + t * 16;
                cpa16(sm + KSOFF(0, cur ^ 1) + rr * 36 + sc0, K1 + (size_t)(k0 + rr) * 32 + sc0);
                cpa16(sm + KSOFF(1, cur ^ 1) + rr * 36 + sc0, K2 + (size_t)(k0 + rr) * 32 + sc0);
                cpa16(sm + VSOFF(0, cur ^ 1) + rr * 40 + sc0, V1 + (size_t)(k0 + rr) * 32 + sc0);
                cpa16(sm + VSOFF(1, cur ^ 1) + rr * 40 + sc0, V2 + (size_t)(k0 + rr) * 32 + sc0);
            }
            cpa_commit();
        }

        const uint32_t* KA = sm + KSOFF(0, cur);
        const uint32_t* KB = sm + KSOFF(1, cur);
        const uint32_t* VA = sm + VSOFF(0, cur);
        const uint32_t* VB = sm + VSOFF(1, cur);

        // ---- per 8-key group: scores -> probs -> shuffle -> PV mma ----
#pragma unroll
        for (int j = 0; j < 4; j++) {
            float sA[4] = {}, sB[4] = {};
#pragma unroll
            for (int ks = 0; ks < 4; ks++) {
                uint32_t bf[2];
                bf[0] = KA[(j * 8 + gid) * 36 + 8 * ks + tig];
                bf[1] = KA[(j * 8 + gid) * 36 + 8 * ks + tig + 4];
                mma_tf32(sA, qf[0][ks], bf);
                bf[0] = KB[(j * 8 + gid) * 36 + 8 * ks + tig];
                bf[1] = KB[(j * 8 + gid) * 36 + 8 * ks + tig + 4];
                mma_tf32(sB, qf[1][ks], bf);
            }
            const int c0 = kt * 32 + j * 8 + tig * 2;
            const float2 mp = *reinterpret_cast<const float2*>(msk + c0);
            const float m0 = mp.x, m1 = mp.y;
            const float e1x = m0 * __expf(sA[0] * SCALE), e1y = m1 * __expf(sA[1] * SCALE);
            const float e1z = m0 * __expf(sA[2] * SCALE), e1w = m1 * __expf(sA[3] * SCALE);
            const float e2x = m0 * __expf(sB[0] * SCALE), e2y = m1 * __expf(sB[1] * SCALE);
            const float e2z = m0 * __expf(sB[2] * SCALE), e2w = m1 * __expf(sB[3] * SCALE);
            const float p1x = c1lo * e1x + c2lo * e2x, p1y = c1lo * e1y + c2lo * e2y;
            const float p1z = c1hi * e1z + c2hi * e2z, p1w = c1hi * e1w + c2hi * e2w;
            const float p2x = d2lo * e2x + d1lo * e1x, p2y = d2lo * e2y + d1lo * e1y;
            const float p2z = d2hi * e2z + d1hi * e1z, p2w = d2hi * e2w + d1hi * e1w;
            // single DRAM write of the blended probs (coalesced float2)
            __stcs(reinterpret_cast<float2*>(S1 + (size_t)(r + gid) * SDIM + c0), make_float2(p1x, p1y));
            __stcs(reinterpret_cast<float2*>(S1 + (size_t)(r + gid + 8) * SDIM + c0), make_float2(p1z, p1w));
            __stcs(reinterpret_cast<float2*>(S2 + (size_t)(r + gid) * SDIM + c0), make_float2(p2x, p2y));
            __stcs(reinterpret_cast<float2*>(S2 + (size_t)(r + gid + 8) * SDIM + c0), make_float2(p2z, p2w));

            // C-fragment -> A-fragment in registers, then PV mma right away
            uint32_t avA[4], avB[4];
            c2a(avA, p1x, p1y, p1z, p1w, gid, tig);
            c2a(avB, p2x, p2y, p2z, p2w, gid, tig);
#pragma unroll
            for (int j2 = 0; j2 < 4; j2++) {
                uint32_t bf[2];
                bf[0] = VA[(j * 8 + tig) * 40 + j2 * 8 + gid];
                bf[1] = VA[(j * 8 + tig + 4) * 40 + j2 * 8 + gid];
                mma_tf32(o[0][j2], avA, bf);
                bf[0] = VB[(j * 8 + tig) * 40 + j2 * 8 + gid];
                bf[1] = VB[(j * 8 + tig + 4) * 40 + j2 * 8 + gid];
                mma_tf32(o[1][j2], avB, bf);
            }
        }

        if (kt < 31) cpa_wait0();
        __syncthreads();
    }

    // epilogue: O -> g_ocat
#pragma unroll
    for (int st = 0; st < 2; st++) {
#pragma unroll
        for (int j2 = 0; j2 < 4; j2++) {
            const int d0 = j2 * 8 + tig * 2;
            float* o0 = &g_ocat[((size_t)(st * 4 + b) * SDIM + q0) * EDIM + h * 32 + d0];
            float* o1 = &g_ocat[((size_t)(st * 4 + b) * SDIM + q0 + 8) * EDIM + h * 32 + d0];
            *reinterpret_cast<float2*>(o0) = make_float2(o[st][j2][0], o[st][j2][1]);
            *reinterpret_cast<float2*>(o1) = make_float2(o[st][j2][2], o[st][j2][3]);
        }
    }
}

// ---------------------------------------------------------------------------
// Kernel 4: batched output projection via tf32 mma. grid.z = stream 0..1.
// Same structure as proj_tf32_kernel; A = g_ocat (fp32, converted in staging),
// output scattered to d_out [S,B,E].
// ---------------------------------------------------------------------------
struct OutArgs {
    const float* w[2];
    const float* b[2];
};

__global__ __launch_bounds__(256) void outproj_tf32_kernel(OutArgs args, float* __restrict__ dout)
{
    __shared__ uint32_t As[128][36];
    __shared__ uint32_t Bs[128][36];
    const int st = blockIdx.z;
    const float* A = g_ocat + (size_t)st * (BDIM * SDIM * EDIM);
    const float* W = args.w[st];
    const float* bias = args.b[st];
    float* out = dout + (size_t)st * (SDIM * BDIM * EDIM);

    const int bm = blockIdx.y * 128;
    const int bn = blockIdx.x * 128;
    const int tid = threadIdx.x;
    const int wid = tid >> 5;
    const int lane = tid & 31;
    const int gid = lane >> 2;
    const int tig = lane & 3;
    const int wm = (wid & 3) * 32;
    const int wn = (wid >> 2) * 64;

    const int sr0 = tid >> 3;
    const int sc0 = (tid & 7) * 4;

    float4 pa[4], pb[4];
#pragma unroll
    for (int t = 0; t < 4; t++) {
        pa[t] = *reinterpret_cast<const float4*>(A + (size_t)(bm + sr0 + t * 32) * 256 + sc0);
        pb[t] = *reinterpret_cast<const float4*>(W + (size_t)(bn + sr0 + t * 32) * 256 + sc0);
    }

    float acc[2][8][4] = {};

    for (int kt = 0; kt < 8; kt++) {
#pragma unroll
        for (int t = 0; t < 4; t++) {
            const int r = sr0 + t * 32;
            As[r][sc0 + 0] = f2tf(pa[t].x); As[r][sc0 + 1] = f2tf(pa[t].y);
            As[r][sc0 + 2] = f2tf(pa[t].z); As[r][sc0 + 3] = f2tf(pa[t].w);
            Bs[r][sc0 + 0] = f2tf(pb[t].x); Bs[r][sc0 + 1] = f2tf(pb[t].y);
            Bs[r][sc0 + 2] = f2tf(pb[t].z); Bs[r][sc0 + 3] = f2tf(pb[t].w);
        }
        __syncthreads();

        if (kt < 7) {
            const int k0 = (kt + 1) * 32;
#pragma unroll
            for (int t = 0; t < 4; t++) {
                pa[t] = *reinterpret_cast<const float4*>(A + (size_t)(bm + sr0 + t * 32) * 256 + k0 + sc0);
                pb[t] = *reinterpret_cast<const float4*>(W + (size_t)(bn + sr0 + t * 32) * 256 + k0 + sc0);
            }
        }

#pragma unroll
        for (int kc = 0; kc < 4; kc++) {
            const int k8 = kc * 8;
            uint32_t a[2][4], b[8][2];
#pragma unroll
            for (int i = 0; i < 2; i++) {
                const int r = wm + i * 16;
                a[i][0] = As[r + gid][k8 + tig];
                a[i][1] = As[r + gid + 8][k8 + tig];
                a[i][2] = As[r + gid][k8 + tig + 4];
                a[i][3] = As[r + gid + 8][k8 + tig + 4];
            }
#pragma unroll
            for (int j = 0; j < 8; j++) {
                const int c = wn + j * 8;
                b[j][0] = Bs[c + gid][k8 + tig];
                b[j][1] = Bs[c + gid][k8 + tig + 4];
            }
#pragma unroll
            for (int i = 0; i < 2; i++)
#pragma unroll
                for (int j = 0; j < 8; j++)
                    mma_tf32(acc[i][j], a[i], b[j]);
        }
        __syncthreads();
    }

    // epilogue: rows m = b*1024 + s  ->  out[(s*4+b)*256 + n]
#pragma unroll
    for (int i = 0; i < 2; i++) {
        const int m0 = bm + wm + i * 16 + gid;
        const int b0 = m0 >> 10, s0 = m0 & 1023;
        const int m1 = m0 + 8;
        const int b1 = m1 >> 10, s1 = m1 & 1023;
#pragma unroll
        for (int j = 0; j < 8; j++) {
            const int c0 = bn + wn + j * 8 + tig * 2;
            const float bv0 = bias[c0], bv1 = bias[c0 + 1];
            *reinterpret_cast<float2*>(out + (size_t)(s0 * 4 + b0) * 256 + c0) =
                make_float2(acc[i][j][0] + bv0, acc[i][j][1] + bv1);
            *reinterpret_cast<float2*>(out + (size_t)(s1 * 4 + b1) * 256 + c0) =
                make_float2(acc[i][j][2] + bv0, acc[i][j][3] + bv1);
        }
    }
}

// ---------------------------------------------------------------------------
extern "C" void kernel_launch(void* const* d_in, const int* in_sizes, int n_in,
                              void* d_out, int out_size)
{
    const unsigned char* mask = (const unsigned char*)d_in[6];
    const float* alpha = (const float*)d_in[15];
    const float* beta  = (const float*)d_in[16];
    float* out = (float*)d_out;

    cudaFuncSetAttribute(attn_fused_kernel,
                         cudaFuncAttributeMaxDynamicSharedMemorySize, FUSED_SMEM);

    // 0) zero exp-sum accumulators
    zero_sums_kernel<<<256, 256>>>();

    // 1) all six QKV projections in one launch (tf32 mma, pre-rounded output)
    ProjArgs pa;
    for (int i = 0; i < 6; i++) pa.x[i] = (const float*)d_in[i];
    pa.w[0] = (const float*)d_in[7];  pa.b[0] = (const float*)d_in[8];
    pa.w[1] = (const float*)d_in[11]; pa.b[1] = (const float*)d_in[12];
    proj_tf32_kernel<<<dim3(2, 32, 6), 256>>>(pa);

    // 2) exp-sum stats only (no score writes)
    sums_kernel<<<dim3(8, 8, 64), 256>>>(mask);

    // 3) fully fused attention: 512 CTAs x 128 threads (4 CTAs/SM)
    attn_fused_kernel<<<dim3(16, 32), 128, FUSED_SMEM>>>(out, mask, alpha, beta);

    // 4) both output projections in one launch (tf32 mma)
    OutArgs oa;
    oa.w[0] = (const float*)d_in[9];  oa.b[0] = (const float*)d_in[10];
    oa.w[1] = (const float*)d_in[13]; oa.b[1] = (const float*)d_in[14];
    outproj_tf32_kernel<<<dim3(2, 32, 2), 256>>>(oa, out);
}

// round 14
// speedup vs baseline: 1.2335x; 1.0496x over previous
#include <cuda_runtime.h>
#include <cuda_bf16.h>
#include <math_constants.h>
#include <cstdint>

// Problem constants
#define SDIM 1024
#define BDIM 4
#define EDIM 256
#define HDIM 8
#define DDIM 32

// d_out layout: out_rgb [S,B,E], out_dpt [S,B,E], shared_rgb [B,H,S,S], shared_dpt [B,H,S,S]
#define OFF_OUT_RGB  0
#define OFF_OUT_DPT  (SDIM*BDIM*EDIM)              // 1048576
#define OFF_SHARED   (2*SDIM*BDIM*EDIM)            // 2097152
#define BHSS         ((size_t)BDIM*HDIM*SDIM*SDIM) // 33554432

#define SCALE 0.17677669529663687f   // 1/sqrt(32)

// Scratch. g_qkv holds TF32-PRE-ROUNDED bits with FRAGMENT-FRIENDLY layout:
//   Q,K slots: [s][d'] with d permuted within 8-groups so mma pairs (tig,tig+4)
//              are adjacent (d' = (d&~7)|((d&3)<<1)|((d>>2)&1)).
//   V slots:   TRANSPOSED [d][s'] with the same permutation applied to the
//              key dim s. Operand registers receive identical values; only
//              memory placement changes.
__device__ float g_qkv[6 * BDIM * HDIM * SDIM * DDIM];   // 25 MB
__device__ float g_ocat[2 * BDIM * SDIM * EDIM];         // 8 MB
__device__ float g_sums[2 * 32 * SDIM];                  // exp-sums per (st,bh,q)

// ---------------------------------------------------------------------------
// tf32 helpers (mma.sync m16n8k8, fp32 accum)
// ---------------------------------------------------------------------------
__device__ __forceinline__ uint32_t f2tf(float f) {
    uint32_t u;
    asm("cvt.rna.tf32.f32 %0, %1;" : "=r"(u) : "f"(f));
    return u;
}

__device__ __forceinline__ void mma_tf32(float* d, const uint32_t* a, const uint32_t* b) {
    asm volatile(
        "mma.sync.aligned.m16n8k8.row.col.f32.tf32.tf32.f32 "
        "{%0,%1,%2,%3}, {%4,%5,%6,%7}, {%8,%9}, {%0,%1,%2,%3};"
        : "+f"(d[0]), "+f"(d[1]), "+f"(d[2]), "+f"(d[3])
        : "r"(a[0]), "r"(a[1]), "r"(a[2]), "r"(a[3]),
          "r"(b[0]), "r"(b[1]));
}

// Convert a score C-fragment (16x8 tile) into a PV A-fragment via shuffles.
__device__ __forceinline__ void c2a(uint32_t* av, float c0, float c1,
                                    float c2, float c3, int gid, int tig)
{
    const unsigned FULL = 0xffffffffu;
    const int base = gid * 4 + (tig >> 1);
    float x0 = __shfl_sync(FULL, c0, base);
    float x1 = __shfl_sync(FULL, c1, base);
    float y0 = __shfl_sync(FULL, c2, base);
    float y1 = __shfl_sync(FULL, c3, base);
    float z0 = __shfl_sync(FULL, c0, base + 2);
    float z1 = __shfl_sync(FULL, c1, base + 2);
    float w0 = __shfl_sync(FULL, c2, base + 2);
    float w1 = __shfl_sync(FULL, c3, base + 2);
    const bool odd = tig & 1;
    av[0] = f2tf(odd ? x1 : x0);
    av[1] = f2tf(odd ? y1 : y0);
    av[2] = f2tf(odd ? z1 : z0);
    av[3] = f2tf(odd ? w1 : w0);
}

// 16-byte async copy gmem -> smem
__device__ __forceinline__ void cpa16(uint32_t* smem_dst, const float* gsrc) {
    uint32_t sa = (uint32_t)__cvta_generic_to_shared(smem_dst);
    asm volatile("cp.async.cg.shared.global [%0], [%1], 16;" :: "r"(sa), "l"(gsrc));
}
__device__ __forceinline__ void cpa_commit() {
    asm volatile("cp.async.commit_group;");
}
__device__ __forceinline__ void cpa_wait0() {
    asm volatile("cp.async.wait_group 0;");
}

// ---------------------------------------------------------------------------
// Kernel 0: zero the sums accumulator
// ---------------------------------------------------------------------------
__global__ void zero_sums_kernel() {
    g_sums[blockIdx.x * 256 + threadIdx.x] = 0.f;
}

// ---------------------------------------------------------------------------
// Kernel 1: batched QKV projection via tf32 mma. grid.z = proj id 0..5.
// Epilogue writes TF32-ROUNDED bits into g_qkv in fragment-friendly layout.
// ---------------------------------------------------------------------------
struct ProjArgs {
    const float* x[6];
    const float* w[2];
    const float* b[2];
};

__global__ __launch_bounds__(256) void proj_tf32_kernel(ProjArgs args)
{
    __shared__ uint32_t As[128][36];
    __shared__ uint32_t Bs[128][36];
    const int proj = blockIdx.z;
    const int st = proj / 3;
    const int wsel = proj - st * 3;
    const float* x = args.x[proj];
    const float* W = args.w[st] + (size_t)wsel * 256 * 256;
    const float* bias = args.b[st] + wsel * 256;

    const int bm = blockIdx.y * 128;
    const int bn = blockIdx.x * 128;
    const int tid = threadIdx.x;
    const int wid = tid >> 5;
    const int lane = tid & 31;
    const int gid = lane >> 2;
    const int tig = lane & 3;
    const int wm = (wid & 3) * 32;
    const int wn = (wid >> 2) * 64;

    const int sr0 = tid >> 3;            // 0..31, +32*t
    const int sc0 = (tid & 7) * 4;       // 0,4,..28

    float4 pa[4], pb[4];
#pragma unroll
    for (int t = 0; t < 4; t++) {
        pa[t] = *reinterpret_cast<const float4*>(x + (size_t)(bm + sr0 + t * 32) * 256 + sc0);
        pb[t] = *reinterpret_cast<const float4*>(W + (size_t)(bn + sr0 + t * 32) * 256 + sc0);
    }

    float acc[2][8][4] = {};

    for (int kt = 0; kt < 8; kt++) {
#pragma unroll
        for (int t = 0; t < 4; t++) {
            const int r = sr0 + t * 32;
            As[r][sc0 + 0] = f2tf(pa[t].x); As[r][sc0 + 1] = f2tf(pa[t].y);
            As[r][sc0 + 2] = f2tf(pa[t].z); As[r][sc0 + 3] = f2tf(pa[t].w);
            Bs[r][sc0 + 0] = f2tf(pb[t].x); Bs[r][sc0 + 1] = f2tf(pb[t].y);
            Bs[r][sc0 + 2] = f2tf(pb[t].z); Bs[r][sc0 + 3] = f2tf(pb[t].w);
        }
        __syncthreads();

        if (kt < 7) {
            const int k0 = (kt + 1) * 32;
#pragma unroll
            for (int t = 0; t < 4; t++) {
                pa[t] = *reinterpret_cast<const float4*>(x + (size_t)(bm + sr0 + t * 32) * 256 + k0 + sc0);
                pb[t] = *reinterpret_cast<const float4*>(W + (size_t)(bn + sr0 + t * 32) * 256 + k0 + sc0);
            }
        }

#pragma unroll
        for (int kc = 0; kc < 4; kc++) {
            const int k8 = kc * 8;
            uint32_t a[2][4], b[8][2];
#pragma unroll
            for (int i = 0; i < 2; i++) {
                const int r = wm + i * 16;
                a[i][0] = As[r + gid][k8 + tig];
                a[i][1] = As[r + gid + 8][k8 + tig];
                a[i][2] = As[r + gid][k8 + tig + 4];
                a[i][3] = As[r + gid + 8][k8 + tig + 4];
            }
#pragma unroll
            for (int j = 0; j < 8; j++) {
                const int c = wn + j * 8;
                b[j][0] = Bs[c + gid][k8 + tig];
                b[j][1] = Bs[c + gid][k8 + tig + 4];
            }
#pragma unroll
            for (int i = 0; i < 2; i++)
#pragma unroll
                for (int j = 0; j < 8; j++)
                    mma_tf32(acc[i][j], a[i], b[j]);
        }
        __syncthreads();
    }

    // epilogue: scatter with fragment-friendly permutations
#pragma unroll
    for (int i = 0; i < 2; i++) {
        const int m0 = bm + wm + i * 16 + gid;
        const int s0 = m0 >> 2, b0 = m0 & 3;
        const int m1 = m0 + 8;
        const int s1 = m1 >> 2, b1 = m1 & 3;
#pragma unroll
        for (int j = 0; j < 8; j++) {
            const int c0 = bn + wn + j * 8 + tig * 2;
            const int h = c0 >> 5;
            const int d0 = c0 & 31, d1 = d0 + 1;
            const float bv0 = bias[c0], bv1 = bias[c0 + 1];
            const uint32_t r00 = f2tf(acc[i][j][0] + bv0), r01 = f2tf(acc[i][j][1] + bv1);
            const uint32_t r10 = f2tf(acc[i][j][2] + bv0), r11 = f2tf(acc[i][j][3] + bv1);
            if (wsel < 2) {
                // Q/K: [s][d'] with d permuted within 8-groups
                const int dp0 = (d0 & ~7) | ((d0 & 3) << 1) | ((d0 >> 2) & 1);
                const int dp1 = (d1 & ~7) | ((d1 & 3) << 1) | ((d1 >> 2) & 1);
                uint32_t* p0 = reinterpret_cast<uint32_t*>(
                    &g_qkv[(((size_t)(proj * 4 + b0) * 8 + h) * 1024 + s0) * 32]);
                uint32_t* p1 = reinterpret_cast<uint32_t*>(
                    &g_qkv[(((size_t)(proj * 4 + b1) * 8 + h) * 1024 + s1) * 32]);
                p0[dp0] = r00; p0[dp1] = r01;
                p1[dp0] = r10; p1[dp1] = r11;
            } else {
                // V: transposed [d][s'] with key (s) permuted within 8-groups
                const int sp0 = (s0 & ~7) | ((s0 & 3) << 1) | ((s0 >> 2) & 1);
                const int sp1 = (s1 & ~7) | ((s1 & 3) << 1) | ((s1 >> 2) & 1);
                uint32_t* base0 = reinterpret_cast<uint32_t*>(
                    &g_qkv[(((size_t)(proj * 4 + b0) * 8 + h)) * (size_t)(32 * 1024)]);
                uint32_t* base1 = reinterpret_cast<uint32_t*>(
                    &g_qkv[(((size_t)(proj * 4 + b1) * 8 + h)) * (size_t)(32 * 1024)]);
                base0[(size_t)d0 * 1024 + sp0] = r00;
                base0[(size_t)d1 * 1024 + sp0] = r01;
                base1[(size_t)d0 * 1024 + sp1] = r10;
                base1[(size_t)d1 * 1024 + sp1] = r11;
            }
        }
    }
}

// ---------------------------------------------------------------------------
// Kernel 2: exp-sum stats only. Fragment pairs now 8B-contiguous -> LDS.64.
// Smem stride 40 -> conflict-free (banks 8*gid + 2*tig).
// ---------------------------------------------------------------------------
__global__ __launch_bounds__(256) void sums_kernel(const unsigned char* __restrict__ mask)
{
    __shared__ uint32_t Qs[128][40];
    __shared__ uint32_t Ks[128][40];
    const int z = blockIdx.z;
    const int st = z >> 5;
    const int bh = z & 31;
    const int bq = blockIdx.y * 128;
    const int bk = blockIdx.x * 128;

    const float* Q = g_qkv + ((size_t)(st * 3 + 0) * 32 + bh) * (SDIM * DDIM);
    const float* K = g_qkv + ((size_t)(st * 3 + 1) * 32 + bh) * (SDIM * DDIM);

    const int tid = threadIdx.x;
    for (int i = tid * 4; i < 128 * 32; i += 1024) {
        const int r = i >> 5, c = i & 31;
        uint4 q4 = *reinterpret_cast<const uint4*>(Q + (size_t)(bq + r) * 32 + c);
        uint4 k4 = *reinterpret_cast<const uint4*>(K + (size_t)(bk + r) * 32 + c);
        *reinterpret_cast<uint4*>(&Qs[r][c]) = q4;
        *reinterpret_cast<uint4*>(&Ks[r][c]) = k4;
    }
    __syncthreads();

    const int wid = tid >> 5;
    const int lane = tid & 31;
    const int gid = lane >> 2;
    const int tig = lane & 3;
    const int wm = (wid & 3) * 32;
    const int wn = (wid >> 2) * 64;

    float acc[2][8][4] = {};
#pragma unroll
    for (int kc = 0; kc < 4; kc++) {
        const int k8 = kc * 8;
        uint32_t a[2][4], b[8][2];
#pragma unroll
        for (int i = 0; i < 2; i++) {
            const int r = wm + i * 16;
            uint2 t0 = *reinterpret_cast<const uint2*>(&Qs[r + gid][k8 + 2 * tig]);
            uint2 t1 = *reinterpret_cast<const uint2*>(&Qs[r + gid + 8][k8 + 2 * tig]);
            a[i][0] = t0.x; a[i][2] = t0.y;
            a[i][1] = t1.x; a[i][3] = t1.y;
        }
#pragma unroll
        for (int j = 0; j < 8; j++) {
            const int c = wn + j * 8;
            uint2 tb = *reinterpret_cast<const uint2*>(&Ks[c + gid][k8 + 2 * tig]);
            b[j][0] = tb.x; b[j][1] = tb.y;
        }
#pragma unroll
        for (int i = 0; i < 2; i++)
#pragma unroll
            for (int j = 0; j < 8; j++)
                mma_tf32(acc[i][j], a[i], b[j]);
    }

    const unsigned char* mrow = mask + (size_t)(bh >> 3) * SDIM;
    float* sums = g_sums + (size_t)z * SDIM;
#pragma unroll
    for (int i = 0; i < 2; i++) {
        float slo = 0.f, shi = 0.f;
#pragma unroll
        for (int j = 0; j < 8; j++) {
            const int c0 = bk + wn + j * 8 + tig * 2;
            const float m0 = mrow[c0] ? 0.f : 1.f;
            const float m1 = mrow[c0 + 1] ? 0.f : 1.f;
            slo += m0 * __expf(acc[i][j][0] * SCALE) + m1 * __expf(acc[i][j][1] * SCALE);
            shi += m0 * __expf(acc[i][j][2] * SCALE) + m1 * __expf(acc[i][j][3] * SCALE);
        }
        slo += __shfl_xor_sync(0xffffffffu, slo, 1);
        slo += __shfl_xor_sync(0xffffffffu, slo, 2);
        shi += __shfl_xor_sync(0xffffffffu, shi, 1);
        shi += __shfl_xor_sync(0xffffffffu, shi, 2);
        if (tig == 0) {
            atomicAdd(&sums[bq + wm + i * 16 + gid], slo);
            atomicAdd(&sums[bq + wm + i * 16 + gid + 8], shi);
        }
    }
}

// ---------------------------------------------------------------------------
// Kernel 3 (FULLY FUSED, 256 threads / 128 q-rows — round-12 shape):
// fragment pairs load as LDS.64/LDG.64 thanks to the producer-side layout.
// K tiles [key][d'] stride 40; V tiles [d][key'] stride 40 (both conflict-
// free: banks 8*gid + 2*tig). One sync per tile, cp.async double buffer.
// Operand registers get identical values to round 12 -> identical numerics.
// ---------------------------------------------------------------------------
// smem layout (u32 indices):
#define KSOFF(st,buf)  (((st) * 2 + (buf)) * 1280)          // K tiles 2x2 x 32x40
#define VSOFF(st,buf)  (5120 + ((st) * 2 + (buf)) * 1280)   // V tiles 2x2 x 32x40
#define MSKOFF         10240                                // mask 1024 f32
#define FUSED_SMEM     (11264 * 4)                          // 45056 bytes

__global__ __launch_bounds__(256, 2) void attn_fused_kernel(
    float* __restrict__ dout, const unsigned char* __restrict__ mask,
    const float* __restrict__ alpha_p, const float* __restrict__ beta_p)
{
    extern __shared__ uint32_t sm[];
    float* msk = reinterpret_cast<float*>(sm + MSKOFF);
    const int bh = blockIdx.y;
    const int b = bh >> 3, h = bh & 7;
    const int bq = blockIdx.x * 128;

    const int tid = threadIdx.x;
    const int wid = tid >> 5;
    const int lane = tid & 31;
    const int gid = lane >> 2;
    const int tig = lane & 3;
    const int sr0 = tid >> 3;          // 0..31
    const int sc0 = (tid & 7) * 4;     // 0,4,..28
    const int r = wid * 16;            // warp q-row base (local)

    const float* Q1 = g_qkv + ((size_t)(0) * 32 + bh) * (SDIM * DDIM);
    const float* K1 = g_qkv + ((size_t)(1) * 32 + bh) * (SDIM * DDIM);
    const float* V1 = g_qkv + ((size_t)(2) * 32 + bh) * (SDIM * DDIM);  // [d][s']
    const float* Q2 = g_qkv + ((size_t)(3) * 32 + bh) * (SDIM * DDIM);
    const float* K2 = g_qkv + ((size_t)(4) * 32 + bh) * (SDIM * DDIM);
    const float* V2 = g_qkv + ((size_t)(5) * 32 + bh) * (SDIM * DDIM);  // [d][s']
    float* S1 = dout + OFF_SHARED + ((size_t)bh * SDIM + bq) * SDIM;
    float* S2 = S1 + BHSS;

    // mask multiplier table
    for (int i = tid; i < SDIM; i += 256)
        msk[i] = mask[(size_t)b * SDIM + i] ? 0.f : 1.f;

    // Q fragments: pre-rounded + d-permuted -> uint2 loads, no CVT
    uint32_t qf[2][4][4];
#pragma unroll
    for (int st = 0; st < 2; st++) {
        const uint32_t* Q = reinterpret_cast<const uint32_t*>(st ? Q2 : Q1);
#pragma unroll
        for (int ks = 0; ks < 4; ks++) {
            uint2 q0v = *reinterpret_cast<const uint2*>(&Q[(size_t)(bq + r + gid) * 32 + 8 * ks + 2 * tig]);
            uint2 q1v = *reinterpret_cast<const uint2*>(&Q[(size_t)(bq + r + gid + 8) * 32 + 8 * ks + 2 * tig]);
            qf[st][ks][0] = q0v.x; qf[st][ks][2] = q0v.y;
            qf[st][ks][1] = q1v.x; qf[st][ks][3] = q1v.y;
        }
    }

    // blend coefficients folded with inverse sums (per thread's 2 rows)
    const float a = *alpha_p, bt = *beta_p;
    const int q0 = bq + r + gid;
    const float i1lo = 1.f / g_sums[(size_t)bh * SDIM + q0];
    const float i1hi = 1.f / g_sums[(size_t)bh * SDIM + q0 + 8];
    const float i2lo = 1.f / g_sums[(size_t)(32 + bh) * SDIM + q0];
    const float i2hi = 1.f / g_sums[(size_t)(32 + bh) * SDIM + q0 + 8];
    const float c1lo = (1.f - a) * i1lo, c2lo = a * i2lo;
    const float c1hi = (1.f - a) * i1hi, c2hi = a * i2hi;
    const float d2lo = (1.f - bt) * i2lo, d1lo = bt * i1lo;
    const float d2hi = (1.f - bt) * i2hi, d1hi = bt * i1hi;

    // stage K/V tile 0 into buffer 0 via cp.async
    // K: rows = keys (gmem [s][d']); V: rows = d (gmem [d][s'])
    cpa16(sm + KSOFF(0, 0) + sr0 * 40 + sc0, K1 + (size_t)sr0 * 32 + sc0);
    cpa16(sm + KSOFF(1, 0) + sr0 * 40 + sc0, K2 + (size_t)sr0 * 32 + sc0);
    cpa16(sm + VSOFF(0, 0) + sr0 * 40 + sc0, V1 + (size_t)sr0 * 1024 + sc0);
    cpa16(sm + VSOFF(1, 0) + sr0 * 40 + sc0, V2 + (size_t)sr0 * 1024 + sc0);
    cpa_commit();
    cpa_wait0();
    __syncthreads();

    float o[2][4][4] = {};

    for (int kt = 0; kt < 32; kt++) {
        const int cur = kt & 1;

        // async-prefetch next K/V tiles into the other buffer
        if (kt < 31) {
            const int k0 = (kt + 1) * 32;
            cpa16(sm + KSOFF(0, cur ^ 1) + sr0 * 40 + sc0, K1 + (size_t)(k0 + sr0) * 32 + sc0);
            cpa16(sm + KSOFF(1, cur ^ 1) + sr0 * 40 + sc0, K2 + (size_t)(k0 + sr0) * 32 + sc0);
            cpa16(sm + VSOFF(0, cur ^ 1) + sr0 * 40 + sc0, V1 + (size_t)sr0 * 1024 + k0 + sc0);
            cpa16(sm + VSOFF(1, cur ^ 1) + sr0 * 40 + sc0, V2 + (size_t)sr0 * 1024 + k0 + sc0);
            cpa_commit();
        }

        const uint32_t* KA = sm + KSOFF(0, cur);
        const uint32_t* KB = sm + KSOFF(1, cur);
        const uint32_t* VA = sm + VSOFF(0, cur);
        const uint32_t* VB = sm + VSOFF(1, cur);

        // ---- per 8-key group: scores -> probs -> shuffle -> PV mma ----
#pragma unroll
        for (int j = 0; j < 4; j++) {
            float sA[4] = {}, sB[4] = {};
#pragma unroll
            for (int ks = 0; ks < 4; ks++) {
                uint32_t bf[2];
                uint2 kk = *reinterpret_cast<const uint2*>(&KA[(j * 8 + gid) * 40 + 8 * ks + 2 * tig]);
                bf[0] = kk.x; bf[1] = kk.y;
                mma_tf32(sA, qf[0][ks], bf);
                kk = *reinterpret_cast<const uint2*>(&KB[(j * 8 + gid) * 40 + 8 * ks + 2 * tig]);
                bf[0] = kk.x; bf[1] = kk.y;
                mma_tf32(sB, qf[1][ks], bf);
            }
            const int c0 = kt * 32 + j * 8 + tig * 2;
            const float2 mp = *reinterpret_cast<const float2*>(msk + c0);
            const float m0 = mp.x, m1 = mp.y;
            const float e1x = m0 * __expf(sA[0] * SCALE), e1y = m1 * __expf(sA[1] * SCALE);
            const float e1z = m0 * __expf(sA[2] * SCALE), e1w = m1 * __expf(sA[3] * SCALE);
            const float e2x = m0 * __expf(sB[0] * SCALE), e2y = m1 * __expf(sB[1] * SCALE);
            const float e2z = m0 * __expf(sB[2] * SCALE), e2w = m1 * __expf(sB[3] * SCALE);
            const float p1x = c1lo * e1x + c2lo * e2x, p1y = c1lo * e1y + c2lo * e2y;
            const float p1z = c1hi * e1z + c2hi * e2z, p1w = c1hi * e1w + c2hi * e2w;
            const float p2x = d2lo * e2x + d1lo * e1x, p2y = d2lo * e2y + d1lo * e1y;
            const float p2z = d2hi * e2z + d1hi * e1z, p2w = d2hi * e2w + d1hi * e1w;
            // single DRAM write of the blended probs (coalesced float2)
            __stcs(reinterpret_cast<float2*>(S1 + (size_t)(r + gid) * SDIM + c0), make_float2(p1x, p1y));
            __stcs(reinterpret_cast<float2*>(S1 + (size_t)(r + gid + 8) * SDIM + c0), make_float2(p1z, p1w));
            __stcs(reinterpret_cast<float2*>(S2 + (size_t)(r + gid) * SDIM + c0), make_float2(p2x, p2y));
            __stcs(reinterpret_cast<float2*>(S2 + (size_t)(r + gid + 8) * SDIM + c0), make_float2(p2z, p2w));

            // C-fragment -> A-fragment in registers, then PV mma right away
            uint32_t avA[4], avB[4];
            c2a(avA, p1x, p1y, p1z, p1w, gid, tig);
            c2a(avB, p2x, p2y, p2z, p2w, gid, tig);
#pragma unroll
            for (int j2 = 0; j2 < 4; j2++) {
                uint32_t bf[2];
                uint2 vv = *reinterpret_cast<const uint2*>(&VA[(j2 * 8 + gid) * 40 + j * 8 + 2 * tig]);
                bf[0] = vv.x; bf[1] = vv.y;
                mma_tf32(o[0][j2], avA, bf);
                vv = *reinterpret_cast<const uint2*>(&VB[(j2 * 8 + gid) * 40 + j * 8 + 2 * tig]);
                bf[0] = vv.x; bf[1] = vv.y;
                mma_tf32(o[1][j2], avB, bf);
            }
        }

        if (kt < 31) cpa_wait0();
        __syncthreads();
    }

    // epilogue: O -> g_ocat
#pragma unroll
    for (int st = 0; st < 2; st++) {
#pragma unroll
        for (int j2 = 0; j2 < 4; j2++) {
            const int d0 = j2 * 8 + tig * 2;
            float* o0 = &g_ocat[((size_t)(st * 4 + b) * SDIM + q0) * EDIM + h * 32 + d0];
            float* o1 = &g_ocat[((size_t)(st * 4 + b) * SDIM + q0 + 8) * EDIM + h * 32 + d0];
            *reinterpret_cast<float2*>(o0) = make_float2(o[st][j2][0], o[st][j2][1]);
            *reinterpret_cast<float2*>(o1) = make_float2(o[st][j2][2], o[st][j2][3]);
        }
    }
}

// ---------------------------------------------------------------------------
// Kernel 4: batched output projection via tf32 mma. grid.z = stream 0..1.
// ---------------------------------------------------------------------------
struct OutArgs {
    const float* w[2];
    const float* b[2];
};

__global__ __launch_bounds__(256) void outproj_tf32_kernel(OutArgs args, float* __restrict__ dout)
{
    __shared__ uint32_t As[128][36];
    __shared__ uint32_t Bs[128][36];
    const int st = blockIdx.z;
    const float* A = g_ocat + (size_t)st * (BDIM * SDIM * EDIM);
    const float* W = args.w[st];
    const float* bias = args.b[st];
    float* out = dout + (size_t)st * (SDIM * BDIM * EDIM);

    const int bm = blockIdx.y * 128;
    const int bn = blockIdx.x * 128;
    const int tid = threadIdx.x;
    const int wid = tid >> 5;
    const int lane = tid & 31;
    const int gid = lane >> 2;
    const int tig = lane & 3;
    const int wm = (wid & 3) * 32;
    const int wn = (wid >> 2) * 64;

    const int sr0 = tid >> 3;
    const int sc0 = (tid & 7) * 4;

    float4 pa[4], pb[4];
#pragma unroll
    for (int t = 0; t < 4; t++) {
        pa[t] = *reinterpret_cast<const float4*>(A + (size_t)(bm + sr0 + t * 32) * 256 + sc0);
        pb[t] = *reinterpret_cast<const float4*>(W + (size_t)(bn + sr0 + t * 32) * 256 + sc0);
    }

    float acc[2][8][4] = {};

    for (int kt = 0; kt < 8; kt++) {
#pragma unroll
        for (int t = 0; t < 4; t++) {
            const int r = sr0 + t * 32;
            As[r][sc0 + 0] = f2tf(pa[t].x); As[r][sc0 + 1] = f2tf(pa[t].y);
            As[r][sc0 + 2] = f2tf(pa[t].z); As[r][sc0 + 3] = f2tf(pa[t].w);
            Bs[r][sc0 + 0] = f2tf(pb[t].x); Bs[r][sc0 + 1] = f2tf(pb[t].y);
            Bs[r][sc0 + 2] = f2tf(pb[t].z); Bs[r][sc0 + 3] = f2tf(pb[t].w);
        }
        __syncthreads();

        if (kt < 7) {
            const int k0 = (kt + 1) * 32;
#pragma unroll
            for (int t = 0; t < 4; t++) {
                pa[t] = *reinterpret_cast<const float4*>(A + (size_t)(bm + sr0 + t * 32) * 256 + k0 + sc0);
                pb[t] = *reinterpret_cast<const float4*>(W + (size_t)(bn + sr0 + t * 32) * 256 + k0 + sc0);
            }
        }

#pragma unroll
        for (int kc = 0; kc < 4; kc++) {
            const int k8 = kc * 8;
            uint32_t a[2][4], b[8][2];
#pragma unroll
            for (int i = 0; i < 2; i++) {
                const int r = wm + i * 16;
                a[i][0] = As[r + gid][k8 + tig];
                a[i][1] = As[r + gid + 8][k8 + tig];
                a[i][2] = As[r + gid][k8 + tig + 4];
                a[i][3] = As[r + gid + 8][k8 + tig + 4];
            }
#pragma unroll
            for (int j = 0; j < 8; j++) {
                const int c = wn + j * 8;
                b[j][0] = Bs[c + gid][k8 + tig];
                b[j][1] = Bs[c + gid][k8 + tig + 4];
            }
#pragma unroll
            for (int i = 0; i < 2; i++)
#pragma unroll
                for (int j = 0; j < 8; j++)
                    mma_tf32(acc[i][j], a[i], b[j]);
        }
        __syncthreads();
    }

    // epilogue: rows m = b*1024 + s  ->  out[(s*4+b)*256 + n]
#pragma unroll
    for (int i = 0; i < 2; i++) {
        const int m0 = bm + wm + i * 16 + gid;
        const int b0 = m0 >> 10, s0 = m0 & 1023;
        const int m1 = m0 + 8;
        const int b1 = m1 >> 10, s1 = m1 & 1023;
#pragma unroll
        for (int j = 0; j < 8; j++) {
            const int c0 = bn + wn + j * 8 + tig * 2;
            const float bv0 = bias[c0], bv1 = bias[c0 + 1];
            *reinterpret_cast<float2*>(out + (size_t)(s0 * 4 + b0) * 256 + c0) =
                make_float2(acc[i][j][0] + bv0, acc[i][j][1] + bv1);
            *reinterpret_cast<float2*>(out + (size_t)(s1 * 4 + b1) * 256 + c0) =
                make_float2(acc[i][j][2] + bv0, acc[i][j][3] + bv1);
        }
    }
}

// ---------------------------------------------------------------------------
extern "C" void kernel_launch(void* const* d_in, const int* in_sizes, int n_in,
                              void* d_out, int out_size)
{
    const unsigned char* mask = (const unsigned char*)d_in[6];
    const float* alpha = (const float*)d_in[15];
    const float* beta  = (const float*)d_in[16];
    float* out = (float*)d_out;

    cudaFuncSetAttribute(attn_fused_kernel,
                         cudaFuncAttributeMaxDynamicSharedMemorySize, FUSED_SMEM);

    // 0) zero exp-sum accumulators
    zero_sums_kernel<<<256, 256>>>();

    // 1) all six QKV projections (tf32 mma, pre-rounded fragment-friendly output)
    ProjArgs pa;
    for (int i = 0; i < 6; i++) pa.x[i] = (const float*)d_in[i];
    pa.w[0] = (const float*)d_in[7];  pa.b[0] = (const float*)d_in[8];
    pa.w[1] = (const float*)d_in[11]; pa.b[1] = (const float*)d_in[12];
    proj_tf32_kernel<<<dim3(2, 32, 6), 256>>>(pa);

    // 2) exp-sum stats only (no score writes)
    sums_kernel<<<dim3(8, 8, 64), 256>>>(mask);

    // 3) fully fused attention: 256 CTAs x 256 threads (2 CTAs/SM)
    attn_fused_kernel<<<dim3(8, 32), 256, FUSED_SMEM>>>(out, mask, alpha, beta);

    // 4) both output projections in one launch (tf32 mma)
    OutArgs oa;
    oa.w[0] = (const float*)d_in[9];  oa.b[0] = (const float*)d_in[10];
    oa.w[1] = (const float*)d_in[13]; oa.b[1] = (const float*)d_in[14];
    outproj_tf32_kernel<<<dim3(2, 32, 2), 256>>>(oa, out);
}

// round 15
// speedup vs baseline: 1.2391x; 1.0045x over previous
#include <cuda_runtime.h>
#include <cuda_bf16.h>
#include <math_constants.h>
#include <cstdint>

// Problem constants
#define SDIM 1024
#define BDIM 4
#define EDIM 256
#define HDIM 8
#define DDIM 32

// d_out layout: out_rgb [S,B,E], out_dpt [S,B,E], shared_rgb [B,H,S,S], shared_dpt [B,H,S,S]
#define OFF_OUT_RGB  0
#define OFF_OUT_DPT  (SDIM*BDIM*EDIM)              // 1048576
#define OFF_SHARED   (2*SDIM*BDIM*EDIM)            // 2097152
#define BHSS         ((size_t)BDIM*HDIM*SDIM*SDIM) // 33554432

#define SCALE 0.17677669529663687f   // 1/sqrt(32)

// Scratch. g_qkv holds TF32-PRE-ROUNDED bits with FRAGMENT-FRIENDLY layout:
//   Q,K slots: [s][d'] with d permuted within 8-groups (pairs (tig,tig+4) adjacent)
//   V slots:   TRANSPOSED [d][s'] with the same permutation on the key dim.
__device__ float g_qkv[6 * BDIM * HDIM * SDIM * DDIM];   // 25 MB
__device__ float g_ocat[2 * BDIM * SDIM * EDIM];         // 8 MB
__device__ float g_sums[2 * 32 * SDIM];                  // exp-sums per (st,bh,q)

// ---------------------------------------------------------------------------
// tf32 helpers (mma.sync m16n8k8, fp32 accum)
// ---------------------------------------------------------------------------
__device__ __forceinline__ uint32_t f2tf(float f) {
    uint32_t u;
    asm("cvt.rna.tf32.f32 %0, %1;" : "=r"(u) : "f"(f));
    return u;
}

__device__ __forceinline__ void mma_tf32(float* d, const uint32_t* a, const uint32_t* b) {
    asm volatile(
        "mma.sync.aligned.m16n8k8.row.col.f32.tf32.tf32.f32 "
        "{%0,%1,%2,%3}, {%4,%5,%6,%7}, {%8,%9}, {%0,%1,%2,%3};"
        : "+f"(d[0]), "+f"(d[1]), "+f"(d[2]), "+f"(d[3])
        : "r"(a[0]), "r"(a[1]), "r"(a[2]), "r"(a[3]),
          "r"(b[0]), "r"(b[1]));
}

// Inverse permutation gather for coalesced prob stores: thread holds values
// for keys (tig, tig+4); returns {p(col 2tig), p(col 2tig+1)} of its row.
// Pure store-path op — not on the mma dependency chain.
__device__ __forceinline__ float2 unperm(float plo, float phi, int l0, int l1, bool hi)
{
    const unsigned FULL = 0xffffffffu;
    float a0 = __shfl_sync(FULL, plo, l0);
    float b0 = __shfl_sync(FULL, phi, l0);
    float a1 = __shfl_sync(FULL, plo, l1);
    float b1 = __shfl_sync(FULL, phi, l1);
    return make_float2(hi ? b0 : a0, hi ? b1 : a1);
}

// 16-byte async copy gmem -> smem
__device__ __forceinline__ void cpa16(uint32_t* smem_dst, const float* gsrc) {
    uint32_t sa = (uint32_t)__cvta_generic_to_shared(smem_dst);
    asm volatile("cp.async.cg.shared.global [%0], [%1], 16;" :: "r"(sa), "l"(gsrc));
}
__device__ __forceinline__ void cpa_commit() {
    asm volatile("cp.async.commit_group;");
}
__device__ __forceinline__ void cpa_wait0() {
    asm volatile("cp.async.wait_group 0;");
}

// ---------------------------------------------------------------------------
// Kernel 1: batched QKV projection via tf32 mma. grid.z = proj id 0..5.
// Prologue zeroes g_sums (replaces the standalone zero kernel).
// Epilogue writes TF32-ROUNDED bits into g_qkv in fragment-friendly layout.
// ---------------------------------------------------------------------------
struct ProjArgs {
    const float* x[6];
    const float* w[2];
    const float* b[2];
};

__global__ __launch_bounds__(256) void proj_tf32_kernel(ProjArgs args)
{
    __shared__ uint32_t As[128][36];
    __shared__ uint32_t Bs[128][36];
    const int proj = blockIdx.z;
    const int st = proj / 3;
    const int wsel = proj - st * 3;
    const float* x = args.x[proj];
    const float* W = args.w[st] + (size_t)wsel * 256 * 256;
    const float* bias = args.b[st] + wsel * 256;

    const int bm = blockIdx.y * 128;
    const int bn = blockIdx.x * 128;
    const int tid = threadIdx.x;

    // zero g_sums (grid covers 98304 threads >= 65536 entries)
    {
        const int zi = ((blockIdx.z * 32 + blockIdx.y) * 2 + blockIdx.x) * 256 + tid;
        if (zi < 2 * 32 * SDIM) g_sums[zi] = 0.f;
    }

    const int wid = tid >> 5;
    const int lane = tid & 31;
    const int gid = lane >> 2;
    const int tig = lane & 3;
    const int wm = (wid & 3) * 32;
    const int wn = (wid >> 2) * 64;

    const int sr0 = tid >> 3;            // 0..31, +32*t
    const int sc0 = (tid & 7) * 4;       // 0,4,..28

    float4 pa[4], pb[4];
#pragma unroll
    for (int t = 0; t < 4; t++) {
        pa[t] = *reinterpret_cast<const float4*>(x + (size_t)(bm + sr0 + t * 32) * 256 + sc0);
        pb[t] = *reinterpret_cast<const float4*>(W + (size_t)(bn + sr0 + t * 32) * 256 + sc0);
    }

    float acc[2][8][4] = {};

    for (int kt = 0; kt < 8; kt++) {
#pragma unroll
        for (int t = 0; t < 4; t++) {
            const int r = sr0 + t * 32;
            As[r][sc0 + 0] = f2tf(pa[t].x); As[r][sc0 + 1] = f2tf(pa[t].y);
            As[r][sc0 + 2] = f2tf(pa[t].z); As[r][sc0 + 3] = f2tf(pa[t].w);
            Bs[r][sc0 + 0] = f2tf(pb[t].x); Bs[r][sc0 + 1] = f2tf(pb[t].y);
            Bs[r][sc0 + 2] = f2tf(pb[t].z); Bs[r][sc0 + 3] = f2tf(pb[t].w);
        }
        __syncthreads();

        if (kt < 7) {
            const int k0 = (kt + 1) * 32;
#pragma unroll
            for (int t = 0; t < 4; t++) {
                pa[t] = *reinterpret_cast<const float4*>(x + (size_t)(bm + sr0 + t * 32) * 256 + k0 + sc0);
                pb[t] = *reinterpret_cast<const float4*>(W + (size_t)(bn + sr0 + t * 32) * 256 + k0 + sc0);
            }
        }

#pragma unroll
        for (int kc = 0; kc < 4; kc++) {
            const int k8 = kc * 8;
            uint32_t a[2][4], b[8][2];
#pragma unroll
            for (int i = 0; i < 2; i++) {
                const int r = wm + i * 16;
                a[i][0] = As[r + gid][k8 + tig];
                a[i][1] = As[r + gid + 8][k8 + tig];
                a[i][2] = As[r + gid][k8 + tig + 4];
                a[i][3] = As[r + gid + 8][k8 + tig + 4];
            }
#pragma unroll
            for (int j = 0; j < 8; j++) {
                const int c = wn + j * 8;
                b[j][0] = Bs[c + gid][k8 + tig];
                b[j][1] = Bs[c + gid][k8 + tig + 4];
            }
#pragma unroll
            for (int i = 0; i < 2; i++)
#pragma unroll
                for (int j = 0; j < 8; j++)
                    mma_tf32(acc[i][j], a[i], b[j]);
        }
        __syncthreads();
    }

    // epilogue: scatter with fragment-friendly permutations
#pragma unroll
    for (int i = 0; i < 2; i++) {
        const int m0 = bm + wm + i * 16 + gid;
        const int s0 = m0 >> 2, b0 = m0 & 3;
        const int m1 = m0 + 8;
        const int s1 = m1 >> 2, b1 = m1 & 3;
#pragma unroll
        for (int j = 0; j < 8; j++) {
            const int c0 = bn + wn + j * 8 + tig * 2;
            const int h = c0 >> 5;
            const int d0 = c0 & 31, d1 = d0 + 1;
            const float bv0 = bias[c0], bv1 = bias[c0 + 1];
            const uint32_t r00 = f2tf(acc[i][j][0] + bv0), r01 = f2tf(acc[i][j][1] + bv1);
            const uint32_t r10 = f2tf(acc[i][j][2] + bv0), r11 = f2tf(acc[i][j][3] + bv1);
            if (wsel < 2) {
                const int dp0 = (d0 & ~7) | ((d0 & 3) << 1) | ((d0 >> 2) & 1);
                const int dp1 = (d1 & ~7) | ((d1 & 3) << 1) | ((d1 >> 2) & 1);
                uint32_t* p0 = reinterpret_cast<uint32_t*>(
                    &g_qkv[(((size_t)(proj * 4 + b0) * 8 + h) * 1024 + s0) * 32]);
                uint32_t* p1 = reinterpret_cast<uint32_t*>(
                    &g_qkv[(((size_t)(proj * 4 + b1) * 8 + h) * 1024 + s1) * 32]);
                p0[dp0] = r00; p0[dp1] = r01;
                p1[dp0] = r10; p1[dp1] = r11;
            } else {
                const int sp0 = (s0 & ~7) | ((s0 & 3) << 1) | ((s0 >> 2) & 1);
                const int sp1 = (s1 & ~7) | ((s1 & 3) << 1) | ((s1 >> 2) & 1);
                uint32_t* base0 = reinterpret_cast<uint32_t*>(
                    &g_qkv[(((size_t)(proj * 4 + b0) * 8 + h)) * (size_t)(32 * 1024)]);
                uint32_t* base1 = reinterpret_cast<uint32_t*>(
                    &g_qkv[(((size_t)(proj * 4 + b1) * 8 + h)) * (size_t)(32 * 1024)]);
                base0[(size_t)d0 * 1024 + sp0] = r00;
                base0[(size_t)d1 * 1024 + sp0] = r01;
                base1[(size_t)d0 * 1024 + sp1] = r10;
                base1[(size_t)d1 * 1024 + sp1] = r11;
            }
        }
    }
}

// ---------------------------------------------------------------------------
// Kernel 2: exp-sum stats only (unchanged from round 13).
// ---------------------------------------------------------------------------
__global__ __launch_bounds__(256) void sums_kernel(const unsigned char* __restrict__ mask)
{
    __shared__ uint32_t Qs[128][40];
    __shared__ uint32_t Ks[128][40];
    const int z = blockIdx.z;
    const int st = z >> 5;
    const int bh = z & 31;
    const int bq = blockIdx.y * 128;
    const int bk = blockIdx.x * 128;

    const float* Q = g_qkv + ((size_t)(st * 3 + 0) * 32 + bh) * (SDIM * DDIM);
    const float* K = g_qkv + ((size_t)(st * 3 + 1) * 32 + bh) * (SDIM * DDIM);

    const int tid = threadIdx.x;
    for (int i = tid * 4; i < 128 * 32; i += 1024) {
        const int r = i >> 5, c = i & 31;
        uint4 q4 = *reinterpret_cast<const uint4*>(Q + (size_t)(bq + r) * 32 + c);
        uint4 k4 = *reinterpret_cast<const uint4*>(K + (size_t)(bk + r) * 32 + c);
        *reinterpret_cast<uint4*>(&Qs[r][c]) = q4;
        *reinterpret_cast<uint4*>(&Ks[r][c]) = k4;
    }
    __syncthreads();

    const int wid = tid >> 5;
    const int lane = tid & 31;
    const int gid = lane >> 2;
    const int tig = lane & 3;
    const int wm = (wid & 3) * 32;
    const int wn = (wid >> 2) * 64;

    float acc[2][8][4] = {};
#pragma unroll
    for (int kc = 0; kc < 4; kc++) {
        const int k8 = kc * 8;
        uint32_t a[2][4], b[8][2];
#pragma unroll
        for (int i = 0; i < 2; i++) {
            const int r = wm + i * 16;
            uint2 t0 = *reinterpret_cast<const uint2*>(&Qs[r + gid][k8 + 2 * tig]);
            uint2 t1 = *reinterpret_cast<const uint2*>(&Qs[r + gid + 8][k8 + 2 * tig]);
            a[i][0] = t0.x; a[i][2] = t0.y;
            a[i][1] = t1.x; a[i][3] = t1.y;
        }
#pragma unroll
        for (int j = 0; j < 8; j++) {
            const int c = wn + j * 8;
            uint2 tb = *reinterpret_cast<const uint2*>(&Ks[c + gid][k8 + 2 * tig]);
            b[j][0] = tb.x; b[j][1] = tb.y;
        }
#pragma unroll
        for (int i = 0; i < 2; i++)
#pragma unroll
            for (int j = 0; j < 8; j++)
                mma_tf32(acc[i][j], a[i], b[j]);
    }

    const unsigned char* mrow = mask + (size_t)(bh >> 3) * SDIM;
    float* sums = g_sums + (size_t)z * SDIM;
#pragma unroll
    for (int i = 0; i < 2; i++) {
        float slo = 0.f, shi = 0.f;
#pragma unroll
        for (int j = 0; j < 8; j++) {
            const int c0 = bk + wn + j * 8 + tig * 2;
            const float m0 = mrow[c0] ? 0.f : 1.f;
            const float m1 = mrow[c0 + 1] ? 0.f : 1.f;
            slo += m0 * __expf(acc[i][j][0] * SCALE) + m1 * __expf(acc[i][j][1] * SCALE);
            shi += m0 * __expf(acc[i][j][2] * SCALE) + m1 * __expf(acc[i][j][3] * SCALE);
        }
        slo += __shfl_xor_sync(0xffffffffu, slo, 1);
        slo += __shfl_xor_sync(0xffffffffu, slo, 2);
        shi += __shfl_xor_sync(0xffffffffu, shi, 1);
        shi += __shfl_xor_sync(0xffffffffu, shi, 2);
        if (tig == 0) {
            atomicAdd(&sums[bq + wm + i * 16 + gid], slo);
            atomicAdd(&sums[bq + wm + i * 16 + gid + 8], shi);
        }
    }
}

// ---------------------------------------------------------------------------
// Kernel 3 (FULLY FUSED, shuffle-free mma chain):
// K tiles are staged with rows PERMUTED (inv_sigma within each 8-group) so the
// score C-fragment gives thread (gid,tig) scores for keys {tig, tig+4} --
// exactly the PV B-fragment layout. PV computes O^T = V^T * P^T with V^T as
// the A operand (already stored [d][key']). No shuffles between the mmas.
// Prob gmem stores stay coalesced via an inverse-shuffle on the store path
// only. Every key keeps the same k-slot in both mmas -> bitwise-identical
// results to round 13.
// ---------------------------------------------------------------------------
// smem layout (u32 indices):
#define KSOFF(st,buf)  (((st) * 2 + (buf)) * 1280)          // K tiles 2x2 x 32x40
#define VSOFF(st,buf)  (5120 + ((st) * 2 + (buf)) * 1280)   // V tiles 2x2 x 32x40
#define MSKOFF         10240                                // mask 1024 f32
#define FUSED_SMEM     (11264 * 4)                          // 45056 bytes

__global__ __launch_bounds__(256, 2) void attn_fused_kernel(
    float* __restrict__ dout, const unsigned char* __restrict__ mask,
    const float* __restrict__ alpha_p, const float* __restrict__ beta_p)
{
    extern __shared__ uint32_t sm[];
    float* msk = reinterpret_cast<float*>(sm + MSKOFF);
    const int bh = blockIdx.y;
    const int b = bh >> 3, h = bh & 7;
    const int bq = blockIdx.x * 128;

    const int tid = threadIdx.x;
    const int wid = tid >> 5;
    const int lane = tid & 31;
    const int gid = lane >> 2;
    const int tig = lane & 3;
    const int sr0 = tid >> 3;          // 0..31
    const int sc0 = (tid & 7) * 4;     // 0,4,..28
    const int r = wid * 16;            // warp q-row base (local)
    // K staging row permutation: gmem key s -> smem row inv_sigma(s)
    const int spr = (sr0 & ~7) | ((sr0 & 3) << 1) | ((sr0 >> 2) & 1);

    const float* Q1 = g_qkv + ((size_t)(0) * 32 + bh) * (SDIM * DDIM);
    const float* K1 = g_qkv + ((size_t)(1) * 32 + bh) * (SDIM * DDIM);
    const float* V1 = g_qkv + ((size_t)(2) * 32 + bh) * (SDIM * DDIM);  // [d][s']
    const float* Q2 = g_qkv + ((size_t)(3) * 32 + bh) * (SDIM * DDIM);
    const float* K2 = g_qkv + ((size_t)(4) * 32 + bh) * (SDIM * DDIM);
    const float* V2 = g_qkv + ((size_t)(5) * 32 + bh) * (SDIM * DDIM);  // [d][s']
    float* S1 = dout + OFF_SHARED + ((size_t)bh * SDIM + bq) * SDIM;
    float* S2 = S1 + BHSS;

    // mask multiplier table
    for (int i = tid; i < SDIM; i += 256)
        msk[i] = mask[(size_t)b * SDIM + i] ? 0.f : 1.f;

    // Q fragments: pre-rounded + d-permuted -> uint2 loads, no CVT
    uint32_t qf[2][4][4];
#pragma unroll
    for (int st = 0; st < 2; st++) {
        const uint32_t* Q = reinterpret_cast<const uint32_t*>(st ? Q2 : Q1);
#pragma unroll
        for (int ks = 0; ks < 4; ks++) {
            uint2 q0v = *reinterpret_cast<const uint2*>(&Q[(size_t)(bq + r + gid) * 32 + 8 * ks + 2 * tig]);
            uint2 q1v = *reinterpret_cast<const uint2*>(&Q[(size_t)(bq + r + gid + 8) * 32 + 8 * ks + 2 * tig]);
            qf[st][ks][0] = q0v.x; qf[st][ks][2] = q0v.y;
            qf[st][ks][1] = q1v.x; qf[st][ks][3] = q1v.y;
        }
    }

    // blend coefficients folded with inverse sums (per thread's 2 rows)
    const float a = *alpha_p, bt = *beta_p;
    const int q0 = bq + r + gid;
    const float i1lo = 1.f / g_sums[(size_t)bh * SDIM + q0];
    const float i1hi = 1.f / g_sums[(size_t)bh * SDIM + q0 + 8];
    const float i2lo = 1.f / g_sums[(size_t)(32 + bh) * SDIM + q0];
    const float i2hi = 1.f / g_sums[(size_t)(32 + bh) * SDIM + q0 + 8];
    const float c1lo = (1.f - a) * i1lo, c2lo = a * i2lo;
    const float c1hi = (1.f - a) * i1hi, c2hi = a * i2hi;
    const float d2lo = (1.f - bt) * i2lo, d1lo = bt * i1lo;
    const float d2hi = (1.f - bt) * i2hi, d1hi = bt * i1hi;

    // stage tile 0: K rows permuted (spr), V rows = d (identity)
    cpa16(sm + KSOFF(0, 0) + spr * 40 + sc0, K1 + (size_t)sr0 * 32 + sc0);
    cpa16(sm + KSOFF(1, 0) + spr * 40 + sc0, K2 + (size_t)sr0 * 32 + sc0);
    cpa16(sm + VSOFF(0, 0) + sr0 * 40 + sc0, V1 + (size_t)sr0 * 1024 + sc0);
    cpa16(sm + VSOFF(1, 0) + sr0 * 40 + sc0, V2 + (size_t)sr0 * 1024 + sc0);
    cpa_commit();
    cpa_wait0();
    __syncthreads();

    float oo[2][2][2][4] = {};   // [stream][d-tile][q-tile][frag]

    for (int kt = 0; kt < 32; kt++) {
        const int cur = kt & 1;

        if (kt < 31) {
            const int k0 = (kt + 1) * 32;
            cpa16(sm + KSOFF(0, cur ^ 1) + spr * 40 + sc0, K1 + (size_t)(k0 + sr0) * 32 + sc0);
            cpa16(sm + KSOFF(1, cur ^ 1) + spr * 40 + sc0, K2 + (size_t)(k0 + sr0) * 32 + sc0);
            cpa16(sm + VSOFF(0, cur ^ 1) + sr0 * 40 + sc0, V1 + (size_t)sr0 * 1024 + k0 + sc0);
            cpa16(sm + VSOFF(1, cur ^ 1) + sr0 * 40 + sc0, V2 + (size_t)sr0 * 1024 + k0 + sc0);
            cpa_commit();
        }

        const uint32_t* KA = sm + KSOFF(0, cur);
        const uint32_t* KB = sm + KSOFF(1, cur);
        const uint32_t* VA = sm + VSOFF(0, cur);
        const uint32_t* VB = sm + VSOFF(1, cur);

#pragma unroll
        for (int j = 0; j < 4; j++) {
            // scores: permuted layout -> thread holds keys {tig, tig+4}
            float sA[4] = {}, sB[4] = {};
#pragma unroll
            for (int ks = 0; ks < 4; ks++) {
                uint32_t bf[2];
                uint2 kk = *reinterpret_cast<const uint2*>(&KA[(j * 8 + gid) * 40 + 8 * ks + 2 * tig]);
                bf[0] = kk.x; bf[1] = kk.y;
                mma_tf32(sA, qf[0][ks], bf);
                kk = *reinterpret_cast<const uint2*>(&KB[(j * 8 + gid) * 40 + 8 * ks + 2 * tig]);
                bf[0] = kk.x; bf[1] = kk.y;
                mma_tf32(sB, qf[1][ks], bf);
            }
            // slots: x=(q gid, key tig) y=(q gid, key tig+4)
            //        z=(q gid+8, key tig) w=(q gid+8, key tig+4)
            const int cb = kt * 32 + j * 8;
            const float m0 = msk[cb + tig], m1 = msk[cb + tig + 4];
            const float e1x = m0 * __expf(sA[0] * SCALE), e1y = m1 * __expf(sA[1] * SCALE);
            const float e1z = m0 * __expf(sA[2] * SCALE), e1w = m1 * __expf(sA[3] * SCALE);
            const float e2x = m0 * __expf(sB[0] * SCALE), e2y = m1 * __expf(sB[1] * SCALE);
            const float e2z = m0 * __expf(sB[2] * SCALE), e2w = m1 * __expf(sB[3] * SCALE);
            const float p1x = c1lo * e1x + c2lo * e2x, p1y = c1lo * e1y + c2lo * e2y;
            const float p1z = c1hi * e1z + c2hi * e2z, p1w = c1hi * e1w + c2hi * e2w;
            const float p2x = d2lo * e2x + d1lo * e1x, p2y = d2lo * e2y + d1lo * e1y;
            const float p2z = d2hi * e2z + d1hi * e1z, p2w = d2hi * e2w + d1hi * e1w;

            // PV: probs ARE B-fragments (no shuffle). O^T = V^T * P^T.
            uint32_t bA0[2] = { f2tf(p1x), f2tf(p1y) };   // q-block [r, r+8)
            uint32_t bA1[2] = { f2tf(p1z), f2tf(p1w) };   // q-block [r+8, r+16)
            uint32_t bB0[2] = { f2tf(p2x), f2tf(p2y) };
            uint32_t bB1[2] = { f2tf(p2z), f2tf(p2w) };
#pragma unroll
            for (int i2 = 0; i2 < 2; i2++) {
                uint32_t av[4];
                uint2 v0 = *reinterpret_cast<const uint2*>(&VA[(16 * i2 + gid) * 40 + j * 8 + 2 * tig]);
                uint2 v1 = *reinterpret_cast<const uint2*>(&VA[(16 * i2 + gid + 8) * 40 + j * 8 + 2 * tig]);
                av[0] = v0.x; av[1] = v1.x; av[2] = v0.y; av[3] = v1.y;
                mma_tf32(oo[0][i2][0], av, bA0);
                mma_tf32(oo[0][i2][1], av, bA1);
                v0 = *reinterpret_cast<const uint2*>(&VB[(16 * i2 + gid) * 40 + j * 8 + 2 * tig]);
                v1 = *reinterpret_cast<const uint2*>(&VB[(16 * i2 + gid + 8) * 40 + j * 8 + 2 * tig]);
                av[0] = v0.x; av[1] = v1.x; av[2] = v0.y; av[3] = v1.y;
                mma_tf32(oo[1][i2][0], av, bB0);
                mma_tf32(oo[1][i2][1], av, bB1);
            }

            // coalesced prob stores via inverse shuffle (store path only)
            const int l0 = (lane & ~3) | ((2 * tig) & 3);
            const int l1 = (lane & ~3) | ((2 * tig + 1) & 3);
            const bool hiSel = tig >= 2;
            float2 sv;
            sv = unperm(p1x, p1y, l0, l1, hiSel);
            __stcs(reinterpret_cast<float2*>(S1 + (size_t)(r + gid) * SDIM + cb + 2 * tig), sv);
            sv = unperm(p1z, p1w, l0, l1, hiSel);
            __stcs(reinterpret_cast<float2*>(S1 + (size_t)(r + gid + 8) * SDIM + cb + 2 * tig), sv);
            sv = unperm(p2x, p2y, l0, l1, hiSel);
            __stcs(reinterpret_cast<float2*>(S2 + (size_t)(r + gid) * SDIM + cb + 2 * tig), sv);
            sv = unperm(p2z, p2w, l0, l1, hiSel);
            __stcs(reinterpret_cast<float2*>(S2 + (size_t)(r + gid + 8) * SDIM + cb + 2 * tig), sv);
        }

        if (kt < 31) cpa_wait0();
        __syncthreads();
    }

    // epilogue: O^T fragments -> g_ocat[q][h*32+d]
#pragma unroll
    for (int st2 = 0; st2 < 2; st2++)
#pragma unroll
        for (int i2 = 0; i2 < 2; i2++)
#pragma unroll
            for (int np = 0; np < 2; np++) {
                const int qg = bq + r + np * 8 + 2 * tig;
                const int dd = 16 * i2 + gid;
                float* base = &g_ocat[((size_t)(st2 * 4 + b) * SDIM + qg) * EDIM + h * 32];
                base[dd]            = oo[st2][i2][np][0];
                base[EDIM + dd]     = oo[st2][i2][np][1];
                base[dd + 8]        = oo[st2][i2][np][2];
                base[EDIM + dd + 8] = oo[st2][i2][np][3];
            }
}

// ---------------------------------------------------------------------------
// Kernel 4: batched output projection via tf32 mma. grid.z = stream 0..1.
// ---------------------------------------------------------------------------
struct OutArgs {
    const float* w[2];
    const float* b[2];
};

__global__ __launch_bounds__(256) void outproj_tf32_kernel(OutArgs args, float* __restrict__ dout)
{
    __shared__ uint32_t As[128][36];
    __shared__ uint32_t Bs[128][36];
    const int st = blockIdx.z;
    const float* A = g_ocat + (size_t)st * (BDIM * SDIM * EDIM);
    const float* W = args.w[st];
    const float* bias = args.b[st];
    float* out = dout + (size_t)st * (SDIM * BDIM * EDIM);

    const int bm = blockIdx.y * 128;
    const int bn = blockIdx.x * 128;
    const int tid = threadIdx.x;
    const int wid = tid >> 5;
    const int lane = tid & 31;
    const int gid = lane >> 2;
    const int tig = lane & 3;
    const int wm = (wid & 3) * 32;
    const int wn = (wid >> 2) * 64;

    const int sr0 = tid >> 3;
    const int sc0 = (tid & 7) * 4;

    float4 pa[4], pb[4];
#pragma unroll
    for (int t = 0; t < 4; t++) {
        pa[t] = *reinterpret_cast<const float4*>(A + (size_t)(bm + sr0 + t * 32) * 256 + sc0);
        pb[t] = *reinterpret_cast<const float4*>(W + (size_t)(bn + sr0 + t * 32) * 256 + sc0);
    }

    float acc[2][8][4] = {};

    for (int kt = 0; kt < 8; kt++) {
#pragma unroll
        for (int t = 0; t < 4; t++) {
            const int r = sr0 + t * 32;
            As[r][sc0 + 0] = f2tf(pa[t].x); As[r][sc0 + 1] = f2tf(pa[t].y);
            As[r][sc0 + 2] = f2tf(pa[t].z); As[r][sc0 + 3] = f2tf(pa[t].w);
            Bs[r][sc0 + 0] = f2tf(pb[t].x); Bs[r][sc0 + 1] = f2tf(pb[t].y);
            Bs[r][sc0 + 2] = f2tf(pb[t].z); Bs[r][sc0 + 3] = f2tf(pb[t].w);
        }
        __syncthreads();

        if (kt < 7) {
            const int k0 = (kt + 1) * 32;
#pragma unroll
            for (int t = 0; t < 4; t++) {
                pa[t] = *reinterpret_cast<const float4*>(A + (size_t)(bm + sr0 + t * 32) * 256 + k0 + sc0);
                pb[t] = *reinterpret_cast<const float4*>(W + (size_t)(bn + sr0 + t * 32) * 256 + k0 + sc0);
            }
        }

#pragma unroll
        for (int kc = 0; kc < 4; kc++) {
            const int k8 = kc * 8;
            uint32_t a[2][4], b[8][2];
#pragma unroll
            for (int i = 0; i < 2; i++) {
                const int r = wm + i * 16;
                a[i][0] = As[r + gid][k8 + tig];
                a[i][1] = As[r + gid + 8][k8 + tig];
                a[i][2] = As[r + gid][k8 + tig + 4];
                a[i][3] = As[r + gid + 8][k8 + tig + 4];
            }
#pragma unroll
            for (int j = 0; j < 8; j++) {
                const int c = wn + j * 8;
                b[j][0] = Bs[c + gid][k8 + tig];
                b[j][1] = Bs[c + gid][k8 + tig + 4];
            }
#pragma unroll
            for (int i = 0; i < 2; i++)
#pragma unroll
                for (int j = 0; j < 8; j++)
                    mma_tf32(acc[i][j], a[i], b[j]);
        }
        __syncthreads();
    }

#pragma unroll
    for (int i = 0; i < 2; i++) {
        const int m0 = bm + wm + i * 16 + gid;
        const int b0 = m0 >> 10, s0 = m0 & 1023;
        const int m1 = m0 + 8;
        const int b1 = m1 >> 10, s1 = m1 & 1023;
#pragma unroll
        for (int j = 0; j < 8; j++) {
            const int c0 = bn + wn + j * 8 + tig * 2;
            const float bv0 = bias[c0], bv1 = bias[c0 + 1];
            *reinterpret_cast<float2*>(out + (size_t)(s0 * 4 + b0) * 256 + c0) =
                make_float2(acc[i][j][0] + bv0, acc[i][j][1] + bv1);
            *reinterpret_cast<float2*>(out + (size_t)(s1 * 4 + b1) * 256 + c0) =
                make_float2(acc[i][j][2] + bv0, acc[i][j][3] + bv1);
        }
    }
}

// ---------------------------------------------------------------------------
extern "C" void kernel_launch(void* const* d_in, const int* in_sizes, int n_in,
                              void* d_out, int out_size)
{
    const unsigned char* mask = (const unsigned char*)d_in[6];
    const float* alpha = (const float*)d_in[15];
    const float* beta  = (const float*)d_in[16];
    float* out = (float*)d_out;

    cudaFuncSetAttribute(attn_fused_kernel,
                         cudaFuncAttributeMaxDynamicSharedMemorySize, FUSED_SMEM);

    // 1) QKV projections (also zero g_sums in prologue)
    ProjArgs pa;
    for (int i = 0; i < 6; i++) pa.x[i] = (const float*)d_in[i];
    pa.w[0] = (const float*)d_in[7];  pa.b[0] = (const float*)d_in[8];
    pa.w[1] = (const float*)d_in[11]; pa.b[1] = (const float*)d_in[12];
    proj_tf32_kernel<<<dim3(2, 32, 6), 256>>>(pa);

    // 2) exp-sum stats
    sums_kernel<<<dim3(8, 8, 64), 256>>>(mask);

    // 3) fully fused attention (shuffle-free mma chain)
    attn_fused_kernel<<<dim3(8, 32), 256, FUSED_SMEM>>>(out, mask, alpha, beta);

    // 4) output projections (tf32 mma)
    OutArgs oa;
    oa.w[0] = (const float*)d_in[9];  oa.b[0] = (const float*)d_in[10];
    oa.w[1] = (const float*)d_in[13]; oa.b[1] = (const float*)d_in[14];
    outproj_tf32_kernel<<<dim3(2, 32, 2), 256>>>(oa, out);
}

// round 16
// speedup vs baseline: 1.2736x; 1.0279x over previous
#include <cuda_runtime.h>
#include <cuda_bf16.h>
#include <math_constants.h>
#include <cstdint>

// Problem constants
#define SDIM 1024
#define BDIM 4
#define EDIM 256
#define HDIM 8
#define DDIM 32

// d_out layout: out_rgb [S,B,E], out_dpt [S,B,E], shared_rgb [B,H,S,S], shared_dpt [B,H,S,S]
#define OFF_OUT_RGB  0
#define OFF_OUT_DPT  (SDIM*BDIM*EDIM)              // 1048576
#define OFF_SHARED   (2*SDIM*BDIM*EDIM)            // 2097152
#define BHSS         ((size_t)BDIM*HDIM*SDIM*SDIM) // 33554432

#define SCALE 0.17677669529663687f   // 1/sqrt(32)
// exp(s*SCALE) == exp2(s * EXC), EXC = SCALE * log2(e) (compile-time fold)
#define EXC ((float)(0.17677669529663687 * 1.4426950408889634))

// Scratch. g_qkv holds TF32-PRE-ROUNDED bits with FRAGMENT-FRIENDLY layout:
//   Q,K slots: [s][d'] with d permuted within 8-groups (pairs (tig,tig+4) adjacent)
//   V slots:   TRANSPOSED [d][s'] with the same permutation on the key dim.
__device__ float g_qkv[6 * BDIM * HDIM * SDIM * DDIM];   // 25 MB
__device__ float g_ocat[2 * BDIM * SDIM * EDIM];         // 8 MB
__device__ float g_sums[2 * 32 * SDIM];                  // exp-sums per (st,bh,q)

// ---------------------------------------------------------------------------
// tf32 helpers (mma.sync m16n8k8, fp32 accum)
// ---------------------------------------------------------------------------
__device__ __forceinline__ uint32_t f2tf(float f) {
    uint32_t u;
    asm("cvt.rna.tf32.f32 %0, %1;" : "=r"(u) : "f"(f));
    return u;
}

__device__ __forceinline__ void mma_tf32(float* d, const uint32_t* a, const uint32_t* b) {
    asm volatile(
        "mma.sync.aligned.m16n8k8.row.col.f32.tf32.tf32.f32 "
        "{%0,%1,%2,%3}, {%4,%5,%6,%7}, {%8,%9}, {%0,%1,%2,%3};"
        : "+f"(d[0]), "+f"(d[1]), "+f"(d[2]), "+f"(d[3])
        : "r"(a[0]), "r"(a[1]), "r"(a[2]), "r"(a[3]),
          "r"(b[0]), "r"(b[1]));
}

// Inverse permutation gather for coalesced prob stores (store path only).
__device__ __forceinline__ float2 unperm(float plo, float phi, int l0, int l1, bool hi)
{
    const unsigned FULL = 0xffffffffu;
    float a0 = __shfl_sync(FULL, plo, l0);
    float b0 = __shfl_sync(FULL, phi, l0);
    float a1 = __shfl_sync(FULL, plo, l1);
    float b1 = __shfl_sync(FULL, phi, l1);
    return make_float2(hi ? b0 : a0, hi ? b1 : a1);
}

// 16-byte async copy gmem -> smem
__device__ __forceinline__ void cpa16(uint32_t* smem_dst, const float* gsrc) {
    uint32_t sa = (uint32_t)__cvta_generic_to_shared(smem_dst);
    asm volatile("cp.async.cg.shared.global [%0], [%1], 16;" :: "r"(sa), "l"(gsrc));
}
__device__ __forceinline__ void cpa_commit() {
    asm volatile("cp.async.commit_group;");
}
__device__ __forceinline__ void cpa_wait0() {
    asm volatile("cp.async.wait_group 0;");
}

// ---------------------------------------------------------------------------
// Kernel 1: batched QKV projection via tf32 mma. grid.z = proj id 0..5.
// Prologue zeroes g_sums. Epilogue writes TF32-ROUNDED bits, fragment layout.
// ---------------------------------------------------------------------------
struct ProjArgs {
    const float* x[6];
    const float* w[2];
    const float* b[2];
};

__global__ __launch_bounds__(256) void proj_tf32_kernel(ProjArgs args)
{
    __shared__ uint32_t As[128][36];
    __shared__ uint32_t Bs[128][36];
    const int proj = blockIdx.z;
    const int st = proj / 3;
    const int wsel = proj - st * 3;
    const float* x = args.x[proj];
    const float* W = args.w[st] + (size_t)wsel * 256 * 256;
    const float* bias = args.b[st] + wsel * 256;

    const int bm = blockIdx.y * 128;
    const int bn = blockIdx.x * 128;
    const int tid = threadIdx.x;

    // zero g_sums (grid covers 98304 threads >= 65536 entries)
    {
        const int zi = ((blockIdx.z * 32 + blockIdx.y) * 2 + blockIdx.x) * 256 + tid;
        if (zi < 2 * 32 * SDIM) g_sums[zi] = 0.f;
    }

    const int wid = tid >> 5;
    const int lane = tid & 31;
    const int gid = lane >> 2;
    const int tig = lane & 3;
    const int wm = (wid & 3) * 32;
    const int wn = (wid >> 2) * 64;

    const int sr0 = tid >> 3;            // 0..31, +32*t
    const int sc0 = (tid & 7) * 4;       // 0,4,..28

    float4 pa[4], pb[4];
#pragma unroll
    for (int t = 0; t < 4; t++) {
        pa[t] = *reinterpret_cast<const float4*>(x + (size_t)(bm + sr0 + t * 32) * 256 + sc0);
        pb[t] = *reinterpret_cast<const float4*>(W + (size_t)(bn + sr0 + t * 32) * 256 + sc0);
    }

    float acc[2][8][4] = {};

    for (int kt = 0; kt < 8; kt++) {
#pragma unroll
        for (int t = 0; t < 4; t++) {
            const int r = sr0 + t * 32;
            As[r][sc0 + 0] = f2tf(pa[t].x); As[r][sc0 + 1] = f2tf(pa[t].y);
            As[r][sc0 + 2] = f2tf(pa[t].z); As[r][sc0 + 3] = f2tf(pa[t].w);
            Bs[r][sc0 + 0] = f2tf(pb[t].x); Bs[r][sc0 + 1] = f2tf(pb[t].y);
            Bs[r][sc0 + 2] = f2tf(pb[t].z); Bs[r][sc0 + 3] = f2tf(pb[t].w);
        }
        __syncthreads();

        if (kt < 7) {
            const int k0 = (kt + 1) * 32;
#pragma unroll
            for (int t = 0; t < 4; t++) {
                pa[t] = *reinterpret_cast<const float4*>(x + (size_t)(bm + sr0 + t * 32) * 256 + k0 + sc0);
                pb[t] = *reinterpret_cast<const float4*>(W + (size_t)(bn + sr0 + t * 32) * 256 + k0 + sc0);
            }
        }

#pragma unroll
        for (int kc = 0; kc < 4; kc++) {
            const int k8 = kc * 8;
            uint32_t a[2][4], b[8][2];
#pragma unroll
            for (int i = 0; i < 2; i++) {
                const int r = wm + i * 16;
                a[i][0] = As[r + gid][k8 + tig];
                a[i][1] = As[r + gid + 8][k8 + tig];
                a[i][2] = As[r + gid][k8 + tig + 4];
                a[i][3] = As[r + gid + 8][k8 + tig + 4];
            }
#pragma unroll
            for (int j = 0; j < 8; j++) {
                const int c = wn + j * 8;
                b[j][0] = Bs[c + gid][k8 + tig];
                b[j][1] = Bs[c + gid][k8 + tig + 4];
            }
#pragma unroll
            for (int i = 0; i < 2; i++)
#pragma unroll
                for (int j = 0; j < 8; j++)
                    mma_tf32(acc[i][j], a[i], b[j]);
        }
        __syncthreads();
    }

    // epilogue: scatter with fragment-friendly permutations
#pragma unroll
    for (int i = 0; i < 2; i++) {
        const int m0 = bm + wm + i * 16 + gid;
        const int s0 = m0 >> 2, b0 = m0 & 3;
        const int m1 = m0 + 8;
        const int s1 = m1 >> 2, b1 = m1 & 3;
#pragma unroll
        for (int j = 0; j < 8; j++) {
            const int c0 = bn + wn + j * 8 + tig * 2;
            const int h = c0 >> 5;
            const int d0 = c0 & 31, d1 = d0 + 1;
            const float bv0 = bias[c0], bv1 = bias[c0 + 1];
            const uint32_t r00 = f2tf(acc[i][j][0] + bv0), r01 = f2tf(acc[i][j][1] + bv1);
            const uint32_t r10 = f2tf(acc[i][j][2] + bv0), r11 = f2tf(acc[i][j][3] + bv1);
            if (wsel < 2) {
                const int dp0 = (d0 & ~7) | ((d0 & 3) << 1) | ((d0 >> 2) & 1);
                const int dp1 = (d1 & ~7) | ((d1 & 3) << 1) | ((d1 >> 2) & 1);
                uint32_t* p0 = reinterpret_cast<uint32_t*>(
                    &g_qkv[(((size_t)(proj * 4 + b0) * 8 + h) * 1024 + s0) * 32]);
                uint32_t* p1 = reinterpret_cast<uint32_t*>(
                    &g_qkv[(((size_t)(proj * 4 + b1) * 8 + h) * 1024 + s1) * 32]);
                p0[dp0] = r00; p0[dp1] = r01;
                p1[dp0] = r10; p1[dp1] = r11;
            } else {
                const int sp0 = (s0 & ~7) | ((s0 & 3) << 1) | ((s0 >> 2) & 1);
                const int sp1 = (s1 & ~7) | ((s1 & 3) << 1) | ((s1 >> 2) & 1);
                uint32_t* base0 = reinterpret_cast<uint32_t*>(
                    &g_qkv[(((size_t)(proj * 4 + b0) * 8 + h)) * (size_t)(32 * 1024)]);
                uint32_t* base1 = reinterpret_cast<uint32_t*>(
                    &g_qkv[(((size_t)(proj * 4 + b1) * 8 + h)) * (size_t)(32 * 1024)]);
                base0[(size_t)d0 * 1024 + sp0] = r00;
                base0[(size_t)d1 * 1024 + sp0] = r01;
                base1[(size_t)d0 * 1024 + sp1] = r10;
                base1[(size_t)d1 * 1024 + sp1] = r11;
            }
        }
    }
}

// ---------------------------------------------------------------------------
// Kernel 2: exp-sum stats only. cp.async staging (pre-rounded bits).
// ---------------------------------------------------------------------------
__global__ __launch_bounds__(256) void sums_kernel(const unsigned char* __restrict__ mask)
{
    __shared__ uint32_t Qs[128][40];
    __shared__ uint32_t Ks[128][40];
    const int z = blockIdx.z;
    const int st = z >> 5;
    const int bh = z & 31;
    const int bq = blockIdx.y * 128;
    const int bk = blockIdx.x * 128;

    const float* Q = g_qkv + ((size_t)(st * 3 + 0) * 32 + bh) * (SDIM * DDIM);
    const float* K = g_qkv + ((size_t)(st * 3 + 1) * 32 + bh) * (SDIM * DDIM);

    const int tid = threadIdx.x;
    for (int i = tid * 4; i < 128 * 32; i += 1024) {
        const int r = i >> 5, c = i & 31;
        cpa16(&Qs[r][c], Q + (size_t)(bq + r) * 32 + c);
        cpa16(&Ks[r][c], K + (size_t)(bk + r) * 32 + c);
    }
    cpa_commit();
    cpa_wait0();
    __syncthreads();

    const int wid = tid >> 5;
    const int lane = tid & 31;
    const int gid = lane >> 2;
    const int tig = lane & 3;
    const int wm = (wid & 3) * 32;
    const int wn = (wid >> 2) * 64;

    float acc[2][8][4] = {};
#pragma unroll
    for (int kc = 0; kc < 4; kc++) {
        const int k8 = kc * 8;
        uint32_t a[2][4], b[8][2];
#pragma unroll
        for (int i = 0; i < 2; i++) {
            const int r = wm + i * 16;
            uint2 t0 = *reinterpret_cast<const uint2*>(&Qs[r + gid][k8 + 2 * tig]);
            uint2 t1 = *reinterpret_cast<const uint2*>(&Qs[r + gid + 8][k8 + 2 * tig]);
            a[i][0] = t0.x; a[i][2] = t0.y;
            a[i][1] = t1.x; a[i][3] = t1.y;
        }
#pragma unroll
        for (int j = 0; j < 8; j++) {
            const int c = wn + j * 8;
            uint2 tb = *reinterpret_cast<const uint2*>(&Ks[c + gid][k8 + 2 * tig]);
            b[j][0] = tb.x; b[j][1] = tb.y;
        }
#pragma unroll
        for (int i = 0; i < 2; i++)
#pragma unroll
            for (int j = 0; j < 8; j++)
                mma_tf32(acc[i][j], a[i], b[j]);
    }

    const unsigned char* mrow = mask + (size_t)(bh >> 3) * SDIM;
    float* sums = g_sums + (size_t)z * SDIM;
#pragma unroll
    for (int i = 0; i < 2; i++) {
        float slo = 0.f, shi = 0.f;
#pragma unroll
        for (int j = 0; j < 8; j++) {
            const int c0 = bk + wn + j * 8 + tig * 2;
            const float m0 = mrow[c0] ? 0.f : 1.f;
            const float m1 = mrow[c0 + 1] ? 0.f : 1.f;
            slo += m0 * exp2f(acc[i][j][0] * EXC) + m1 * exp2f(acc[i][j][1] * EXC);
            shi += m0 * exp2f(acc[i][j][2] * EXC) + m1 * exp2f(acc[i][j][3] * EXC);
        }
        slo += __shfl_xor_sync(0xffffffffu, slo, 1);
        slo += __shfl_xor_sync(0xffffffffu, slo, 2);
        shi += __shfl_xor_sync(0xffffffffu, shi, 1);
        shi += __shfl_xor_sync(0xffffffffu, shi, 2);
        if (tig == 0) {
            atomicAdd(&sums[bq + wm + i * 16 + gid], slo);
            atomicAdd(&sums[bq + wm + i * 16 + gid + 8], shi);
        }
    }
}

// ---------------------------------------------------------------------------
// Kernel 3 (FULLY FUSED, shuffle-free mma chain) — round-14 structure,
// exp via exp2f with compile-time folded constant.
// ---------------------------------------------------------------------------
// smem layout (u32 indices):
#define KSOFF(st,buf)  (((st) * 2 + (buf)) * 1280)          // K tiles 2x2 x 32x40
#define VSOFF(st,buf)  (5120 + ((st) * 2 + (buf)) * 1280)   // V tiles 2x2 x 32x40
#define MSKOFF         10240                                // mask 1024 f32
#define FUSED_SMEM     (11264 * 4)                          // 45056 bytes

__global__ __launch_bounds__(256, 2) void attn_fused_kernel(
    float* __restrict__ dout, const unsigned char* __restrict__ mask,
    const float* __restrict__ alpha_p, const float* __restrict__ beta_p)
{
    extern __shared__ uint32_t sm[];
    float* msk = reinterpret_cast<float*>(sm + MSKOFF);
    const int bh = blockIdx.y;
    const int b = bh >> 3, h = bh & 7;
    const int bq = blockIdx.x * 128;

    const int tid = threadIdx.x;
    const int wid = tid >> 5;
    const int lane = tid & 31;
    const int gid = lane >> 2;
    const int tig = lane & 3;
    const int sr0 = tid >> 3;          // 0..31
    const int sc0 = (tid & 7) * 4;     // 0,4,..28
    const int r = wid * 16;            // warp q-row base (local)
    const int spr = (sr0 & ~7) | ((sr0 & 3) << 1) | ((sr0 >> 2) & 1);

    const float* Q1 = g_qkv + ((size_t)(0) * 32 + bh) * (SDIM * DDIM);
    const float* K1 = g_qkv + ((size_t)(1) * 32 + bh) * (SDIM * DDIM);
    const float* V1 = g_qkv + ((size_t)(2) * 32 + bh) * (SDIM * DDIM);  // [d][s']
    const float* Q2 = g_qkv + ((size_t)(3) * 32 + bh) * (SDIM * DDIM);
    const float* K2 = g_qkv + ((size_t)(4) * 32 + bh) * (SDIM * DDIM);
    const float* V2 = g_qkv + ((size_t)(5) * 32 + bh) * (SDIM * DDIM);  // [d][s']
    float* S1 = dout + OFF_SHARED + ((size_t)bh * SDIM + bq) * SDIM;
    float* S2 = S1 + BHSS;

    // mask multiplier table
    for (int i = tid; i < SDIM; i += 256)
        msk[i] = mask[(size_t)b * SDIM + i] ? 0.f : 1.f;

    // Q fragments: pre-rounded + d-permuted -> uint2 loads, no CVT
    uint32_t qf[2][4][4];
#pragma unroll
    for (int st = 0; st < 2; st++) {
        const uint32_t* Q = reinterpret_cast<const uint32_t*>(st ? Q2 : Q1);
#pragma unroll
        for (int ks = 0; ks < 4; ks++) {
            uint2 q0v = *reinterpret_cast<const uint2*>(&Q[(size_t)(bq + r + gid) * 32 + 8 * ks + 2 * tig]);
            uint2 q1v = *reinterpret_cast<const uint2*>(&Q[(size_t)(bq + r + gid + 8) * 32 + 8 * ks + 2 * tig]);
            qf[st][ks][0] = q0v.x; qf[st][ks][2] = q0v.y;
            qf[st][ks][1] = q1v.x; qf[st][ks][3] = q1v.y;
        }
    }

    // blend coefficients folded with inverse sums (per thread's 2 rows)
    const float a = *alpha_p, bt = *beta_p;
    const int q0 = bq + r + gid;
    const float i1lo = 1.f / g_sums[(size_t)bh * SDIM + q0];
    const float i1hi = 1.f / g_sums[(size_t)bh * SDIM + q0 + 8];
    const float i2lo = 1.f / g_sums[(size_t)(32 + bh) * SDIM + q0];
    const float i2hi = 1.f / g_sums[(size_t)(32 + bh) * SDIM + q0 + 8];
    const float c1lo = (1.f - a) * i1lo, c2lo = a * i2lo;
    const float c1hi = (1.f - a) * i1hi, c2hi = a * i2hi;
    const float d2lo = (1.f - bt) * i2lo, d1lo = bt * i1lo;
    const float d2hi = (1.f - bt) * i2hi, d1hi = bt * i1hi;

    // stage tile 0: K rows permuted (spr), V rows = d (identity)
    cpa16(sm + KSOFF(0, 0) + spr * 40 + sc0, K1 + (size_t)sr0 * 32 + sc0);
    cpa16(sm + KSOFF(1, 0) + spr * 40 + sc0, K2 + (size_t)sr0 * 32 + sc0);
    cpa16(sm + VSOFF(0, 0) + sr0 * 40 + sc0, V1 + (size_t)sr0 * 1024 + sc0);
    cpa16(sm + VSOFF(1, 0) + sr0 * 40 + sc0, V2 + (size_t)sr0 * 1024 + sc0);
    cpa_commit();
    cpa_wait0();
    __syncthreads();

    float oo[2][2][2][4] = {};   // [stream][d-tile][q-tile][frag]

    for (int kt = 0; kt < 32; kt++) {
        const int cur = kt & 1;

        if (kt < 31) {
            const int k0 = (kt + 1) * 32;
            cpa16(sm + KSOFF(0, cur ^ 1) + spr * 40 + sc0, K1 + (size_t)(k0 + sr0) * 32 + sc0);
            cpa16(sm + KSOFF(1, cur ^ 1) + spr * 40 + sc0, K2 + (size_t)(k0 + sr0) * 32 + sc0);
            cpa16(sm + VSOFF(0, cur ^ 1) + sr0 * 40 + sc0, V1 + (size_t)sr0 * 1024 + k0 + sc0);
            cpa16(sm + VSOFF(1, cur ^ 1) + sr0 * 40 + sc0, V2 + (size_t)sr0 * 1024 + k0 + sc0);
            cpa_commit();
        }

        const uint32_t* KA = sm + KSOFF(0, cur);
        const uint32_t* KB = sm + KSOFF(1, cur);
        const uint32_t* VA = sm + VSOFF(0, cur);
        const uint32_t* VB = sm + VSOFF(1, cur);

#pragma unroll
        for (int j = 0; j < 4; j++) {
            // scores: permuted layout -> thread holds keys {tig, tig+4}
            float sA[4] = {}, sB[4] = {};
#pragma unroll
            for (int ks = 0; ks < 4; ks++) {
                uint32_t bf[2];
                uint2 kk = *reinterpret_cast<const uint2*>(&KA[(j * 8 + gid) * 40 + 8 * ks + 2 * tig]);
                bf[0] = kk.x; bf[1] = kk.y;
                mma_tf32(sA, qf[0][ks], bf);
                kk = *reinterpret_cast<const uint2*>(&KB[(j * 8 + gid) * 40 + 8 * ks + 2 * tig]);
                bf[0] = kk.x; bf[1] = kk.y;
                mma_tf32(sB, qf[1][ks], bf);
            }
            const int cb = kt * 32 + j * 8;
            const float m0 = msk[cb + tig], m1 = msk[cb + tig + 4];
            const float e1x = m0 * exp2f(sA[0] * EXC), e1y = m1 * exp2f(sA[1] * EXC);
            const float e1z = m0 * exp2f(sA[2] * EXC), e1w = m1 * exp2f(sA[3] * EXC);
            const float e2x = m0 * exp2f(sB[0] * EXC), e2y = m1 * exp2f(sB[1] * EXC);
            const float e2z = m0 * exp2f(sB[2] * EXC), e2w = m1 * exp2f(sB[3] * EXC);
            const float p1x = c1lo * e1x + c2lo * e2x, p1y = c1lo * e1y + c2lo * e2y;
            const float p1z = c1hi * e1z + c2hi * e2z, p1w = c1hi * e1w + c2hi * e2w;
            const float p2x = d2lo * e2x + d1lo * e1x, p2y = d2lo * e2y + d1lo * e1y;
            const float p2z = d2hi * e2z + d1hi * e1z, p2w = d2hi * e2w + d1hi * e1w;

            // PV: probs ARE B-fragments (no shuffle). O^T = V^T * P^T.
            uint32_t bA0[2] = { f2tf(p1x), f2tf(p1y) };
            uint32_t bA1[2] = { f2tf(p1z), f2tf(p1w) };
            uint32_t bB0[2] = { f2tf(p2x), f2tf(p2y) };
            uint32_t bB1[2] = { f2tf(p2z), f2tf(p2w) };
#pragma unroll
            for (int i2 = 0; i2 < 2; i2++) {
                uint32_t av[4];
                uint2 v0 = *reinterpret_cast<const uint2*>(&VA[(16 * i2 + gid) * 40 + j * 8 + 2 * tig]);
                uint2 v1 = *reinterpret_cast<const uint2*>(&VA[(16 * i2 + gid + 8) * 40 + j * 8 + 2 * tig]);
                av[0] = v0.x; av[1] = v1.x; av[2] = v0.y; av[3] = v1.y;
                mma_tf32(oo[0][i2][0], av, bA0);
                mma_tf32(oo[0][i2][1], av, bA1);
                v0 = *reinterpret_cast<const uint2*>(&VB[(16 * i2 + gid) * 40 + j * 8 + 2 * tig]);
                v1 = *reinterpret_cast<const uint2*>(&VB[(16 * i2 + gid + 8) * 40 + j * 8 + 2 * tig]);
                av[0] = v0.x; av[1] = v1.x; av[2] = v0.y; av[3] = v1.y;
                mma_tf32(oo[1][i2][0], av, bB0);
                mma_tf32(oo[1][i2][1], av, bB1);
            }

            // coalesced prob stores via inverse shuffle (store path only)
            const int l0 = (lane & ~3) | ((2 * tig) & 3);
            const int l1 = (lane & ~3) | ((2 * tig + 1) & 3);
            const bool hiSel = tig >= 2;
            float2 sv;
            sv = unperm(p1x, p1y, l0, l1, hiSel);
            __stcs(reinterpret_cast<float2*>(S1 + (size_t)(r + gid) * SDIM + cb + 2 * tig), sv);
            sv = unperm(p1z, p1w, l0, l1, hiSel);
            __stcs(reinterpret_cast<float2*>(S1 + (size_t)(r + gid + 8) * SDIM + cb + 2 * tig), sv);
            sv = unperm(p2x, p2y, l0, l1, hiSel);
            __stcs(reinterpret_cast<float2*>(S2 + (size_t)(r + gid) * SDIM + cb + 2 * tig), sv);
            sv = unperm(p2z, p2w, l0, l1, hiSel);
            __stcs(reinterpret_cast<float2*>(S2 + (size_t)(r + gid + 8) * SDIM + cb + 2 * tig), sv);
        }

        if (kt < 31) cpa_wait0();
        __syncthreads();
    }

    // epilogue: O^T fragments -> g_ocat[q][h*32+d]
#pragma unroll
    for (int st2 = 0; st2 < 2; st2++)
#pragma unroll
        for (int i2 = 0; i2 < 2; i2++)
#pragma unroll
            for (int np = 0; np < 2; np++) {
                const int qg = bq + r + np * 8 + 2 * tig;
                const int dd = 16 * i2 + gid;
                float* base = &g_ocat[((size_t)(st2 * 4 + b) * SDIM + qg) * EDIM + h * 32];
                base[dd]            = oo[st2][i2][np][0];
                base[EDIM + dd]     = oo[st2][i2][np][1];
                base[dd + 8]        = oo[st2][i2][np][2];
                base[EDIM + dd + 8] = oo[st2][i2][np][3];
            }
}

// ---------------------------------------------------------------------------
// Kernel 4: batched output projection via tf32 mma. 64m x 128n tiles,
// grid (2, 64, 2) = 256 CTAs (was 128 — a third of the chip sat idle).
// 8 warps: 2 in m x 4 in n; warp tile 32m x 32n.
// ---------------------------------------------------------------------------
struct OutArgs {
    const float* w[2];
    const float* b[2];
};

__global__ __launch_bounds__(256) void outproj_tf32_kernel(OutArgs args, float* __restrict__ dout)
{
    __shared__ uint32_t As[64][36];
    __shared__ uint32_t Bs[128][36];
    const int st = blockIdx.z;
    const float* A = g_ocat + (size_t)st * (BDIM * SDIM * EDIM);
    const float* W = args.w[st];
    const float* bias = args.b[st];
    float* out = dout + (size_t)st * (SDIM * BDIM * EDIM);

    const int bm = blockIdx.y * 64;
    const int bn = blockIdx.x * 128;
    const int tid = threadIdx.x;
    const int wid = tid >> 5;
    const int lane = tid & 31;
    const int gid = lane >> 2;
    const int tig = lane & 3;
    const int wm = (wid & 1) * 32;      // 2 warps in m
    const int wn = (wid >> 1) * 32;     // 4 warps in n

    const int sr0 = tid >> 3;           // 0..31
    const int sc0 = (tid & 7) * 4;

    float4 pa[2], pb[4];
#pragma unroll
    for (int t = 0; t < 2; t++)
        pa[t] = *reinterpret_cast<const float4*>(A + (size_t)(bm + sr0 + t * 32) * 256 + sc0);
#pragma unroll
    for (int t = 0; t < 4; t++)
        pb[t] = *reinterpret_cast<const float4*>(W + (size_t)(bn + sr0 + t * 32) * 256 + sc0);

    float acc[2][4][4] = {};

    for (int kt = 0; kt < 8; kt++) {
#pragma unroll
        for (int t = 0; t < 2; t++) {
            const int r = sr0 + t * 32;
            As[r][sc0 + 0] = f2tf(pa[t].x); As[r][sc0 + 1] = f2tf(pa[t].y);
            As[r][sc0 + 2] = f2tf(pa[t].z); As[r][sc0 + 3] = f2tf(pa[t].w);
        }
#pragma unroll
        for (int t = 0; t < 4; t++) {
            const int r = sr0 + t * 32;
            Bs[r][sc0 + 0] = f2tf(pb[t].x); Bs[r][sc0 + 1] = f2tf(pb[t].y);
            Bs[r][sc0 + 2] = f2tf(pb[t].z); Bs[r][sc0 + 3] = f2tf(pb[t].w);
        }
        __syncthreads();

        if (kt < 7) {
            const int k0 = (kt + 1) * 32;
#pragma unroll
            for (int t = 0; t < 2; t++)
                pa[t] = *reinterpret_cast<const float4*>(A + (size_t)(bm + sr0 + t * 32) * 256 + k0 + sc0);
#pragma unroll
            for (int t = 0; t < 4; t++)
                pb[t] = *reinterpret_cast<const float4*>(W + (size_t)(bn + sr0 + t * 32) * 256 + k0 + sc0);
        }

#pragma unroll
        for (int kc = 0; kc < 4; kc++) {
            const int k8 = kc * 8;
            uint32_t a[2][4], b[4][2];
#pragma unroll
            for (int i = 0; i < 2; i++) {
                const int r = wm + i * 16;
                a[i][0] = As[r + gid][k8 + tig];
                a[i][1] = As[r + gid + 8][k8 + tig];
                a[i][2] = As[r + gid][k8 + tig + 4];
                a[i][3] = As[r + gid + 8][k8 + tig + 4];
            }
#pragma unroll
            for (int j = 0; j < 4; j++) {
                const int c = wn + j * 8;
                b[j][0] = Bs[c + gid][k8 + tig];
                b[j][1] = Bs[c + gid][k8 + tig + 4];
            }
#pragma unroll
            for (int i = 0; i < 2; i++)
#pragma unroll
                for (int j = 0; j < 4; j++)
                    mma_tf32(acc[i][j], a[i], b[j]);
        }
        __syncthreads();
    }

    // epilogue: rows m = b*1024 + s  ->  out[(s*4+b)*256 + n]
#pragma unroll
    for (int i = 0; i < 2; i++) {
        const int m0 = bm + wm + i * 16 + gid;
        const int b0 = m0 >> 10, s0 = m0 & 1023;
        const int m1 = m0 + 8;
        const int b1 = m1 >> 10, s1 = m1 & 1023;
#pragma unroll
        for (int j = 0; j < 4; j++) {
            const int c0 = bn + wn + j * 8 + tig * 2;
            const float bv0 = bias[c0], bv1 = bias[c0 + 1];
            *reinterpret_cast<float2*>(out + (size_t)(s0 * 4 + b0) * 256 + c0) =
                make_float2(acc[i][j][0] + bv0, acc[i][j][1] + bv1);
            *reinterpret_cast<float2*>(out + (size_t)(s1 * 4 + b1) * 256 + c0) =
                make_float2(acc[i][j][2] + bv0, acc[i][j][3] + bv1);
        }
    }
}

// ---------------------------------------------------------------------------
extern "C" void kernel_launch(void* const* d_in, const int* in_sizes, int n_in,
                              void* d_out, int out_size)
{
    const unsigned char* mask = (const unsigned char*)d_in[6];
    const float* alpha = (const float*)d_in[15];
    const float* beta  = (const float*)d_in[16];
    float* out = (float*)d_out;

    cudaFuncSetAttribute(attn_fused_kernel,
                         cudaFuncAttributeMaxDynamicSharedMemorySize, FUSED_SMEM);

    // 1) QKV projections (also zero g_sums in prologue)
    ProjArgs pa;
    for (int i = 0; i < 6; i++) pa.x[i] = (const float*)d_in[i];
    pa.w[0] = (const float*)d_in[7];  pa.b[0] = (const float*)d_in[8];
    pa.w[1] = (const float*)d_in[11]; pa.b[1] = (const float*)d_in[12];
    proj_tf32_kernel<<<dim3(2, 32, 6), 256>>>(pa);

    // 2) exp-sum stats
    sums_kernel<<<dim3(8, 8, 64), 256>>>(mask);

    // 3) fully fused attention (shuffle-free mma chain)
    attn_fused_kernel<<<dim3(8, 32), 256, FUSED_SMEM>>>(out, mask, alpha, beta);

    // 4) output projections (tf32 mma, 256 CTAs)
    OutArgs oa;
    oa.w[0] = (const float*)d_in[9];  oa.b[0] = (const float*)d_in[10];
    oa.w[1] = (const float*)d_in[13]; oa.b[1] = (const float*)d_in[14];
    outproj_tf32_kernel<<<dim3(2, 64, 2), 256>>>(oa, out);
}

// round 17
// speedup vs baseline: 1.3674x; 1.0736x over previous
#include <cuda_runtime.h>
#include <cuda_bf16.h>
#include <math_constants.h>
#include <cstdint>

// Problem constants
#define SDIM 1024
#define BDIM 4
#define EDIM 256
#define HDIM 8
#define DDIM 32

// d_out layout: out_rgb [S,B,E], out_dpt [S,B,E], shared_rgb [B,H,S,S], shared_dpt [B,H,S,S]
#define OFF_OUT_RGB  0
#define OFF_OUT_DPT  (SDIM*BDIM*EDIM)              // 1048576
#define OFF_SHARED   (2*SDIM*BDIM*EDIM)            // 2097152
#define BHSS         ((size_t)BDIM*HDIM*SDIM*SDIM) // 33554432

#define SCALE 0.17677669529663687f   // 1/sqrt(32)
// exp(s*SCALE) == exp2(s * EXC), EXC = SCALE * log2(e) (compile-time fold)
#define EXC ((float)(0.17677669529663687 * 1.4426950408889634))

// Scratch. g_qkv holds TF32-PRE-ROUNDED bits with FRAGMENT-FRIENDLY layout:
//   Q,K slots: [s][d'] with d permuted within 8-groups (pairs (tig,tig+4) adjacent)
//   V slots:   TRANSPOSED [d][s'] with the same permutation on the key dim.
__device__ float g_qkv[6 * BDIM * HDIM * SDIM * DDIM];   // 25 MB
__device__ float g_ocat[2 * BDIM * SDIM * EDIM];         // 8 MB

// ---------------------------------------------------------------------------
// tf32 helpers (mma.sync m16n8k8, fp32 accum)
// ---------------------------------------------------------------------------
__device__ __forceinline__ uint32_t f2tf(float f) {
    uint32_t u;
    asm("cvt.rna.tf32.f32 %0, %1;" : "=r"(u) : "f"(f));
    return u;
}

__device__ __forceinline__ void mma_tf32(float* d, const uint32_t* a, const uint32_t* b) {
    asm volatile(
        "mma.sync.aligned.m16n8k8.row.col.f32.tf32.tf32.f32 "
        "{%0,%1,%2,%3}, {%4,%5,%6,%7}, {%8,%9}, {%0,%1,%2,%3};"
        : "+f"(d[0]), "+f"(d[1]), "+f"(d[2]), "+f"(d[3])
        : "r"(a[0]), "r"(a[1]), "r"(a[2]), "r"(a[3]),
          "r"(b[0]), "r"(b[1]));
}

// Inverse permutation gather for coalesced prob stores (store path only).
__device__ __forceinline__ float2 unperm(float plo, float phi, int l0, int l1, bool hi)
{
    const unsigned FULL = 0xffffffffu;
    float a0 = __shfl_sync(FULL, plo, l0);
    float b0 = __shfl_sync(FULL, phi, l0);
    float a1 = __shfl_sync(FULL, plo, l1);
    float b1 = __shfl_sync(FULL, phi, l1);
    return make_float2(hi ? b0 : a0, hi ? b1 : a1);
}

// 16-byte async copy gmem -> smem
__device__ __forceinline__ void cpa16(uint32_t* smem_dst, const float* gsrc) {
    uint32_t sa = (uint32_t)__cvta_generic_to_shared(smem_dst);
    asm volatile("cp.async.cg.shared.global [%0], [%1], 16;" :: "r"(sa), "l"(gsrc));
}
__device__ __forceinline__ void cpa_commit() {
    asm volatile("cp.async.commit_group;");
}
__device__ __forceinline__ void cpa_wait0() {
    asm volatile("cp.async.wait_group 0;");
}

// ---------------------------------------------------------------------------
// Kernel 1: batched QKV projection via tf32 mma. grid.z = proj id 0..5.
// Epilogue writes TF32-ROUNDED bits, fragment-friendly layout.
// ---------------------------------------------------------------------------
struct ProjArgs {
    const float* x[6];
    const float* w[2];
    const float* b[2];
};

__global__ __launch_bounds__(256) void proj_tf32_kernel(ProjArgs args)
{
    __shared__ uint32_t As[128][36];
    __shared__ uint32_t Bs[128][36];
    const int proj = blockIdx.z;
    const int st = proj / 3;
    const int wsel = proj - st * 3;
    const float* x = args.x[proj];
    const float* W = args.w[st] + (size_t)wsel * 256 * 256;
    const float* bias = args.b[st] + wsel * 256;

    const int bm = blockIdx.y * 128;
    const int bn = blockIdx.x * 128;
    const int tid = threadIdx.x;
    const int wid = tid >> 5;
    const int lane = tid & 31;
    const int gid = lane >> 2;
    const int tig = lane & 3;
    const int wm = (wid & 3) * 32;
    const int wn = (wid >> 2) * 64;

    const int sr0 = tid >> 3;            // 0..31, +32*t
    const int sc0 = (tid & 7) * 4;       // 0,4,..28

    float4 pa[4], pb[4];
#pragma unroll
    for (int t = 0; t < 4; t++) {
        pa[t] = *reinterpret_cast<const float4*>(x + (size_t)(bm + sr0 + t * 32) * 256 + sc0);
        pb[t] = *reinterpret_cast<const float4*>(W + (size_t)(bn + sr0 + t * 32) * 256 + sc0);
    }

    float acc[2][8][4] = {};

    for (int kt = 0; kt < 8; kt++) {
#pragma unroll
        for (int t = 0; t < 4; t++) {
            const int r = sr0 + t * 32;
            As[r][sc0 + 0] = f2tf(pa[t].x); As[r][sc0 + 1] = f2tf(pa[t].y);
            As[r][sc0 + 2] = f2tf(pa[t].z); As[r][sc0 + 3] = f2tf(pa[t].w);
            Bs[r][sc0 + 0] = f2tf(pb[t].x); Bs[r][sc0 + 1] = f2tf(pb[t].y);
            Bs[r][sc0 + 2] = f2tf(pb[t].z); Bs[r][sc0 + 3] = f2tf(pb[t].w);
        }
        __syncthreads();

        if (kt < 7) {
            const int k0 = (kt + 1) * 32;
#pragma unroll
            for (int t = 0; t < 4; t++) {
                pa[t] = *reinterpret_cast<const float4*>(x + (size_t)(bm + sr0 + t * 32) * 256 + k0 + sc0);
                pb[t] = *reinterpret_cast<const float4*>(W + (size_t)(bn + sr0 + t * 32) * 256 + k0 + sc0);
            }
        }

#pragma unroll
        for (int kc = 0; kc < 4; kc++) {
            const int k8 = kc * 8;
            uint32_t a[2][4], b[8][2];
#pragma unroll
            for (int i = 0; i < 2; i++) {
                const int r = wm + i * 16;
                a[i][0] = As[r + gid][k8 + tig];
                a[i][1] = As[r + gid + 8][k8 + tig];
                a[i][2] = As[r + gid][k8 + tig + 4];
                a[i][3] = As[r + gid + 8][k8 + tig + 4];
            }
#pragma unroll
            for (int j = 0; j < 8; j++) {
                const int c = wn + j * 8;
                b[j][0] = Bs[c + gid][k8 + tig];
                b[j][1] = Bs[c + gid][k8 + tig + 4];
            }
#pragma unroll
            for (int i = 0; i < 2; i++)
#pragma unroll
                for (int j = 0; j < 8; j++)
                    mma_tf32(acc[i][j], a[i], b[j]);
        }
        __syncthreads();
    }

    // epilogue: scatter with fragment-friendly permutations
#pragma unroll
    for (int i = 0; i < 2; i++) {
        const int m0 = bm + wm + i * 16 + gid;
        const int s0 = m0 >> 2, b0 = m0 & 3;
        const int m1 = m0 + 8;
        const int s1 = m1 >> 2, b1 = m1 & 3;
#pragma unroll
        for (int j = 0; j < 8; j++) {
            const int c0 = bn + wn + j * 8 + tig * 2;
            const int h = c0 >> 5;
            const int d0 = c0 & 31, d1 = d0 + 1;
            const float bv0 = bias[c0], bv1 = bias[c0 + 1];
            const uint32_t r00 = f2tf(acc[i][j][0] + bv0), r01 = f2tf(acc[i][j][1] + bv1);
            const uint32_t r10 = f2tf(acc[i][j][2] + bv0), r11 = f2tf(acc[i][j][3] + bv1);
            if (wsel < 2) {
                const int dp0 = (d0 & ~7) | ((d0 & 3) << 1) | ((d0 >> 2) & 1);
                const int dp1 = (d1 & ~7) | ((d1 & 3) << 1) | ((d1 >> 2) & 1);
                uint32_t* p0 = reinterpret_cast<uint32_t*>(
                    &g_qkv[(((size_t)(proj * 4 + b0) * 8 + h) * 1024 + s0) * 32]);
                uint32_t* p1 = reinterpret_cast<uint32_t*>(
                    &g_qkv[(((size_t)(proj * 4 + b1) * 8 + h) * 1024 + s1) * 32]);
                p0[dp0] = r00; p0[dp1] = r01;
                p1[dp0] = r10; p1[dp1] = r11;
            } else {
                const int sp0 = (s0 & ~7) | ((s0 & 3) << 1) | ((s0 >> 2) & 1);
                const int sp1 = (s1 & ~7) | ((s1 & 3) << 1) | ((s1 >> 2) & 1);
                uint32_t* base0 = reinterpret_cast<uint32_t*>(
                    &g_qkv[(((size_t)(proj * 4 + b0) * 8 + h)) * (size_t)(32 * 1024)]);
                uint32_t* base1 = reinterpret_cast<uint32_t*>(
                    &g_qkv[(((size_t)(proj * 4 + b1) * 8 + h)) * (size_t)(32 * 1024)]);
                base0[(size_t)d0 * 1024 + sp0] = r00;
                base0[(size_t)d1 * 1024 + sp0] = r01;
                base1[(size_t)d0 * 1024 + sp1] = r10;
                base1[(size_t)d1 * 1024 + sp1] = r11;
            }
        }
    }
}

// ---------------------------------------------------------------------------
// Kernel 2 (FULLY FUSED, TWO-PHASE, self-contained softmax):
// Phase 1: sweep all k-tiles computing scores (tf32 mma, permuted layout) and
//          accumulate per-row exp2 sums in registers (mask applied); quad
//          shfl reduce -> each thread owns its 2 rows' sums per stream.
// Phase 2: sweep again: recompute scores, exp/normalize/blend, single prob
//          write (stcs), PV mma (probs are B-fragments; O^T = V^T * P^T).
// No sums kernel, no atomics, no g_sums. Same deterministic mma order in
// both phases -> sums exactly match phase-2 scores.
// ---------------------------------------------------------------------------
// smem layout (u32 indices):
#define KSOFF(st,buf)  (((st) * 2 + (buf)) * 1280)          // K tiles 2x2 x 32x40
#define VSOFF(st,buf)  (5120 + ((st) * 2 + (buf)) * 1280)   // V tiles 2x2 x 32x40
#define MSKOFF         10240                                // mask 1024 f32
#define FUSED_SMEM     (11264 * 4)                          // 45056 bytes

__global__ __launch_bounds__(256, 2) void attn_fused_kernel(
    float* __restrict__ dout, const unsigned char* __restrict__ mask,
    const float* __restrict__ alpha_p, const float* __restrict__ beta_p)
{
    extern __shared__ uint32_t sm[];
    float* msk = reinterpret_cast<float*>(sm + MSKOFF);
    const int bh = blockIdx.y;
    const int b = bh >> 3, h = bh & 7;
    const int bq = blockIdx.x * 128;

    const int tid = threadIdx.x;
    const int wid = tid >> 5;
    const int lane = tid & 31;
    const int gid = lane >> 2;
    const int tig = lane & 3;
    const int sr0 = tid >> 3;          // 0..31
    const int sc0 = (tid & 7) * 4;     // 0,4,..28
    const int r = wid * 16;            // warp q-row base (local)
    const int spr = (sr0 & ~7) | ((sr0 & 3) << 1) | ((sr0 >> 2) & 1);

    const float* Q1 = g_qkv + ((size_t)(0) * 32 + bh) * (SDIM * DDIM);
    const float* K1 = g_qkv + ((size_t)(1) * 32 + bh) * (SDIM * DDIM);
    const float* V1 = g_qkv + ((size_t)(2) * 32 + bh) * (SDIM * DDIM);  // [d][s']
    const float* Q2 = g_qkv + ((size_t)(3) * 32 + bh) * (SDIM * DDIM);
    const float* K2 = g_qkv + ((size_t)(4) * 32 + bh) * (SDIM * DDIM);
    const float* V2 = g_qkv + ((size_t)(5) * 32 + bh) * (SDIM * DDIM);  // [d][s']
    float* S1 = dout + OFF_SHARED + ((size_t)bh * SDIM + bq) * SDIM;
    float* S2 = S1 + BHSS;

    // mask multiplier table
    for (int i = tid; i < SDIM; i += 256)
        msk[i] = mask[(size_t)b * SDIM + i] ? 0.f : 1.f;

    // Q fragments: pre-rounded + d-permuted -> uint2 loads, no CVT
    uint32_t qf[2][4][4];
#pragma unroll
    for (int st = 0; st < 2; st++) {
        const uint32_t* Q = reinterpret_cast<const uint32_t*>(st ? Q2 : Q1);
#pragma unroll
        for (int ks = 0; ks < 4; ks++) {
            uint2 q0v = *reinterpret_cast<const uint2*>(&Q[(size_t)(bq + r + gid) * 32 + 8 * ks + 2 * tig]);
            uint2 q1v = *reinterpret_cast<const uint2*>(&Q[(size_t)(bq + r + gid + 8) * 32 + 8 * ks + 2 * tig]);
            qf[st][ks][0] = q0v.x; qf[st][ks][2] = q0v.y;
            qf[st][ks][1] = q1v.x; qf[st][ks][3] = q1v.y;
        }
    }

    // ======================= PHASE 1: exp-sum sweep =======================
    // stage K tile 0 (rows permuted) into buffer 0
    cpa16(sm + KSOFF(0, 0) + spr * 40 + sc0, K1 + (size_t)sr0 * 32 + sc0);
    cpa16(sm + KSOFF(1, 0) + spr * 40 + sc0, K2 + (size_t)sr0 * 32 + sc0);
    cpa_commit();
    cpa_wait0();
    __syncthreads();

    float s1lo = 0.f, s1hi = 0.f, s2lo = 0.f, s2hi = 0.f;

    for (int kt = 0; kt < 32; kt++) {
        const int cur = kt & 1;
        if (kt < 31) {
            const int k0 = (kt + 1) * 32;
            cpa16(sm + KSOFF(0, cur ^ 1) + spr * 40 + sc0, K1 + (size_t)(k0 + sr0) * 32 + sc0);
            cpa16(sm + KSOFF(1, cur ^ 1) + spr * 40 + sc0, K2 + (size_t)(k0 + sr0) * 32 + sc0);
            cpa_commit();
        }
        const uint32_t* KA = sm + KSOFF(0, cur);
        const uint32_t* KB = sm + KSOFF(1, cur);
#pragma unroll
        for (int j = 0; j < 4; j++) {
            float sA[4] = {}, sB[4] = {};
#pragma unroll
            for (int ks = 0; ks < 4; ks++) {
                uint32_t bf[2];
                uint2 kk = *reinterpret_cast<const uint2*>(&KA[(j * 8 + gid) * 40 + 8 * ks + 2 * tig]);
                bf[0] = kk.x; bf[1] = kk.y;
                mma_tf32(sA, qf[0][ks], bf);
                kk = *reinterpret_cast<const uint2*>(&KB[(j * 8 + gid) * 40 + 8 * ks + 2 * tig]);
                bf[0] = kk.x; bf[1] = kk.y;
                mma_tf32(sB, qf[1][ks], bf);
            }
            const int cb = kt * 32 + j * 8;
            const float m0 = msk[cb + tig], m1 = msk[cb + tig + 4];
            s1lo += m0 * exp2f(sA[0] * EXC) + m1 * exp2f(sA[1] * EXC);
            s1hi += m0 * exp2f(sA[2] * EXC) + m1 * exp2f(sA[3] * EXC);
            s2lo += m0 * exp2f(sB[0] * EXC) + m1 * exp2f(sB[1] * EXC);
            s2hi += m0 * exp2f(sB[2] * EXC) + m1 * exp2f(sB[3] * EXC);
        }
        if (kt < 31) cpa_wait0();
        __syncthreads();
    }

    // quad reduce (across tig) -> full row sums on every lane of the quad
#pragma unroll
    for (int o = 1; o <= 2; o <<= 1) {
        s1lo += __shfl_xor_sync(0xffffffffu, s1lo, o);
        s1hi += __shfl_xor_sync(0xffffffffu, s1hi, o);
        s2lo += __shfl_xor_sync(0xffffffffu, s2lo, o);
        s2hi += __shfl_xor_sync(0xffffffffu, s2hi, o);
    }

    // blend coefficients folded with inverse sums (per thread's 2 rows)
    const float a = *alpha_p, bt = *beta_p;
    const float i1lo = 1.f / s1lo, i1hi = 1.f / s1hi;
    const float i2lo = 1.f / s2lo, i2hi = 1.f / s2hi;
    const float c1lo = (1.f - a) * i1lo, c2lo = a * i2lo;
    const float c1hi = (1.f - a) * i1hi, c2hi = a * i2hi;
    const float d2lo = (1.f - bt) * i2lo, d1lo = bt * i1lo;
    const float d2hi = (1.f - bt) * i2hi, d1hi = bt * i1hi;

    // ======================= PHASE 2: probs + PV ==========================
    cpa16(sm + KSOFF(0, 0) + spr * 40 + sc0, K1 + (size_t)sr0 * 32 + sc0);
    cpa16(sm + KSOFF(1, 0) + spr * 40 + sc0, K2 + (size_t)sr0 * 32 + sc0);
    cpa16(sm + VSOFF(0, 0) + sr0 * 40 + sc0, V1 + (size_t)sr0 * 1024 + sc0);
    cpa16(sm + VSOFF(1, 0) + sr0 * 40 + sc0, V2 + (size_t)sr0 * 1024 + sc0);
    cpa_commit();
    cpa_wait0();
    __syncthreads();

    float oo[2][2][2][4] = {};   // [stream][d-tile][q-tile][frag]
    const int q0 = bq + r + gid;

    for (int kt = 0; kt < 32; kt++) {
        const int cur = kt & 1;

        if (kt < 31) {
            const int k0 = (kt + 1) * 32;
            cpa16(sm + KSOFF(0, cur ^ 1) + spr * 40 + sc0, K1 + (size_t)(k0 + sr0) * 32 + sc0);
            cpa16(sm + KSOFF(1, cur ^ 1) + spr * 40 + sc0, K2 + (size_t)(k0 + sr0) * 32 + sc0);
            cpa16(sm + VSOFF(0, cur ^ 1) + sr0 * 40 + sc0, V1 + (size_t)sr0 * 1024 + k0 + sc0);
            cpa16(sm + VSOFF(1, cur ^ 1) + sr0 * 40 + sc0, V2 + (size_t)sr0 * 1024 + k0 + sc0);
            cpa_commit();
        }

        const uint32_t* KA = sm + KSOFF(0, cur);
        const uint32_t* KB = sm + KSOFF(1, cur);
        const uint32_t* VA = sm + VSOFF(0, cur);
        const uint32_t* VB = sm + VSOFF(1, cur);

#pragma unroll
        for (int j = 0; j < 4; j++) {
            // scores: permuted layout -> thread holds keys {tig, tig+4}
            float sA[4] = {}, sB[4] = {};
#pragma unroll
            for (int ks = 0; ks < 4; ks++) {
                uint32_t bf[2];
                uint2 kk = *reinterpret_cast<const uint2*>(&KA[(j * 8 + gid) * 40 + 8 * ks + 2 * tig]);
                bf[0] = kk.x; bf[1] = kk.y;
                mma_tf32(sA, qf[0][ks], bf);
                kk = *reinterpret_cast<const uint2*>(&KB[(j * 8 + gid) * 40 + 8 * ks + 2 * tig]);
                bf[0] = kk.x; bf[1] = kk.y;
                mma_tf32(sB, qf[1][ks], bf);
            }
            const int cb = kt * 32 + j * 8;
            const float m0 = msk[cb + tig], m1 = msk[cb + tig + 4];
            const float e1x = m0 * exp2f(sA[0] * EXC), e1y = m1 * exp2f(sA[1] * EXC);
            const float e1z = m0 * exp2f(sA[2] * EXC), e1w = m1 * exp2f(sA[3] * EXC);
            const float e2x = m0 * exp2f(sB[0] * EXC), e2y = m1 * exp2f(sB[1] * EXC);
            const float e2z = m0 * exp2f(sB[2] * EXC), e2w = m1 * exp2f(sB[3] * EXC);
            const float p1x = c1lo * e1x + c2lo * e2x, p1y = c1lo * e1y + c2lo * e2y;
            const float p1z = c1hi * e1z + c2hi * e2z, p1w = c1hi * e1w + c2hi * e2w;
            const float p2x = d2lo * e2x + d1lo * e1x, p2y = d2lo * e2y + d1lo * e1y;
            const float p2z = d2hi * e2z + d1hi * e1z, p2w = d2hi * e2w + d1hi * e1w;

            // PV: probs ARE B-fragments (no shuffle). O^T = V^T * P^T.
            uint32_t bA0[2] = { f2tf(p1x), f2tf(p1y) };
            uint32_t bA1[2] = { f2tf(p1z), f2tf(p1w) };
            uint32_t bB0[2] = { f2tf(p2x), f2tf(p2y) };
            uint32_t bB1[2] = { f2tf(p2z), f2tf(p2w) };
#pragma unroll
            for (int i2 = 0; i2 < 2; i2++) {
                uint32_t av[4];
                uint2 v0 = *reinterpret_cast<const uint2*>(&VA[(16 * i2 + gid) * 40 + j * 8 + 2 * tig]);
                uint2 v1 = *reinterpret_cast<const uint2*>(&VA[(16 * i2 + gid + 8) * 40 + j * 8 + 2 * tig]);
                av[0] = v0.x; av[1] = v1.x; av[2] = v0.y; av[3] = v1.y;
                mma_tf32(oo[0][i2][0], av, bA0);
                mma_tf32(oo[0][i2][1], av, bA1);
                v0 = *reinterpret_cast<const uint2*>(&VB[(16 * i2 + gid) * 40 + j * 8 + 2 * tig]);
                v1 = *reinterpret_cast<const uint2*>(&VB[(16 * i2 + gid + 8) * 40 + j * 8 + 2 * tig]);
                av[0] = v0.x; av[1] = v1.x; av[2] = v0.y; av[3] = v1.y;
                mma_tf32(oo[1][i2][0], av, bB0);
                mma_tf32(oo[1][i2][1], av, bB1);
            }

            // coalesced prob stores via inverse shuffle (store path only)
            const int l0 = (lane & ~3) | ((2 * tig) & 3);
            const int l1 = (lane & ~3) | ((2 * tig + 1) & 3);
            const bool hiSel = tig >= 2;
            float2 sv;
            sv = unperm(p1x, p1y, l0, l1, hiSel);
            __stcs(reinterpret_cast<float2*>(S1 + (size_t)(r + gid) * SDIM + cb + 2 * tig), sv);
            sv = unperm(p1z, p1w, l0, l1, hiSel);
            __stcs(reinterpret_cast<float2*>(S1 + (size_t)(r + gid + 8) * SDIM + cb + 2 * tig), sv);
            sv = unperm(p2x, p2y, l0, l1, hiSel);
            __stcs(reinterpret_cast<float2*>(S2 + (size_t)(r + gid) * SDIM + cb + 2 * tig), sv);
            sv = unperm(p2z, p2w, l0, l1, hiSel);
            __stcs(reinterpret_cast<float2*>(S2 + (size_t)(r + gid + 8) * SDIM + cb + 2 * tig), sv);
        }

        if (kt < 31) cpa_wait0();
        __syncthreads();
    }

    // epilogue: O^T fragments -> g_ocat[q][h*32+d]
#pragma unroll
    for (int st2 = 0; st2 < 2; st2++)
#pragma unroll
        for (int i2 = 0; i2 < 2; i2++)
#pragma unroll
            for (int np = 0; np < 2; np++) {
                const int qg = bq + r + np * 8 + 2 * tig;
                const int dd = 16 * i2 + gid;
                float* base = &g_ocat[((size_t)(st2 * 4 + b) * SDIM + qg) * EDIM + h * 32];
                base[dd]            = oo[st2][i2][np][0];
                base[EDIM + dd]     = oo[st2][i2][np][1];
                base[dd + 8]        = oo[st2][i2][np][2];
                base[EDIM + dd + 8] = oo[st2][i2][np][3];
            }
}

// ---------------------------------------------------------------------------
// Kernel 3: batched output projection via tf32 mma. 64m x 128n tiles,
// grid (2, 64, 2) = 256 CTAs. 8 warps: 2 in m x 4 in n; warp tile 32m x 32n.
// ---------------------------------------------------------------------------
struct OutArgs {
    const float* w[2];
    const float* b[2];
};

__global__ __launch_bounds__(256) void outproj_tf32_kernel(OutArgs args, float* __restrict__ dout)
{
    __shared__ uint32_t As[64][36];
    __shared__ uint32_t Bs[128][36];
    const int st = blockIdx.z;
    const float* A = g_ocat + (size_t)st * (BDIM * SDIM * EDIM);
    const float* W = args.w[st];
    const float* bias = args.b[st];
    float* out = dout + (size_t)st * (SDIM * BDIM * EDIM);

    const int bm = blockIdx.y * 64;
    const int bn = blockIdx.x * 128;
    const int tid = threadIdx.x;
    const int wid = tid >> 5;
    const int lane = tid & 31;
    const int gid = lane >> 2;
    const int tig = lane & 3;
    const int wm = (wid & 1) * 32;      // 2 warps in m
    const int wn = (wid >> 1) * 32;     // 4 warps in n

    const int sr0 = tid >> 3;           // 0..31
    const int sc0 = (tid & 7) * 4;

    float4 pa[2], pb[4];
#pragma unroll
    for (int t = 0; t < 2; t++)
        pa[t] = *reinterpret_cast<const float4*>(A + (size_t)(bm + sr0 + t * 32) * 256 + sc0);
#pragma unroll
    for (int t = 0; t < 4; t++)
        pb[t] = *reinterpret_cast<const float4*>(W + (size_t)(bn + sr0 + t * 32) * 256 + sc0);

    float acc[2][4][4] = {};

    for (int kt = 0; kt < 8; kt++) {
#pragma unroll
        for (int t = 0; t < 2; t++) {
            const int r = sr0 + t * 32;
            As[r][sc0 + 0] = f2tf(pa[t].x); As[r][sc0 + 1] = f2tf(pa[t].y);
            As[r][sc0 + 2] = f2tf(pa[t].z); As[r][sc0 + 3] = f2tf(pa[t].w);
        }
#pragma unroll
        for (int t = 0; t < 4; t++) {
            const int r = sr0 + t * 32;
            Bs[r][sc0 + 0] = f2tf(pb[t].x); Bs[r][sc0 + 1] = f2tf(pb[t].y);
            Bs[r][sc0 + 2] = f2tf(pb[t].z); Bs[r][sc0 + 3] = f2tf(pb[t].w);
        }
        __syncthreads();

        if (kt < 7) {
            const int k0 = (kt + 1) * 32;
#pragma unroll
            for (int t = 0; t < 2; t++)
                pa[t] = *reinterpret_cast<const float4*>(A + (size_t)(bm + sr0 + t * 32) * 256 + k0 + sc0);
#pragma unroll
            for (int t = 0; t < 4; t++)
                pb[t] = *reinterpret_cast<const float4*>(W + (size_t)(bn + sr0 + t * 32) * 256 + k0 + sc0);
        }

#pragma unroll
        for (int kc = 0; kc < 4; kc++) {
            const int k8 = kc * 8;
            uint32_t a[2][4], b[4][2];
#pragma unroll
            for (int i = 0; i < 2; i++) {
                const int r = wm + i * 16;
                a[i][0] = As[r + gid][k8 + tig];
                a[i][1] = As[r + gid + 8][k8 + tig];
                a[i][2] = As[r + gid][k8 + tig + 4];
                a[i][3] = As[r + gid + 8][k8 + tig + 4];
            }
#pragma unroll
            for (int j = 0; j < 4; j++) {
                const int c = wn + j * 8;
                b[j][0] = Bs[c + gid][k8 + tig];
                b[j][1] = Bs[c + gid][k8 + tig + 4];
            }
#pragma unroll
            for (int i = 0; i < 2; i++)
#pragma unroll
                for (int j = 0; j < 4; j++)
                    mma_tf32(acc[i][j], a[i], b[j]);
        }
        __syncthreads();
    }

    // epilogue: rows m = b*1024 + s  ->  out[(s*4+b)*256 + n]
#pragma unroll
    for (int i = 0; i < 2; i++) {
        const int m0 = bm + wm + i * 16 + gid;
        const int b0 = m0 >> 10, s0 = m0 & 1023;
        const int m1 = m0 + 8;
        const int b1 = m1 >> 10, s1 = m1 & 1023;
#pragma unroll
        for (int j = 0; j < 4; j++) {
            const int c0 = bn + wn + j * 8 + tig * 2;
            const float bv0 = bias[c0], bv1 = bias[c0 + 1];
            *reinterpret_cast<float2*>(out + (size_t)(s0 * 4 + b0) * 256 + c0) =
                make_float2(acc[i][j][0] + bv0, acc[i][j][1] + bv1);
            *reinterpret_cast<float2*>(out + (size_t)(s1 * 4 + b1) * 256 + c0) =
                make_float2(acc[i][j][2] + bv0, acc[i][j][3] + bv1);
        }
    }
}

// ---------------------------------------------------------------------------
extern "C" void kernel_launch(void* const* d_in, const int* in_sizes, int n_in,
                              void* d_out, int out_size)
{
    const unsigned char* mask = (const unsigned char*)d_in[6];
    const float* alpha = (const float*)d_in[15];
    const float* beta  = (const float*)d_in[16];
    float* out = (float*)d_out;

    cudaFuncSetAttribute(attn_fused_kernel,
                         cudaFuncAttributeMaxDynamicSharedMemorySize, FUSED_SMEM);

    // 1) QKV projections (tf32 mma, pre-rounded fragment-friendly output)
    ProjArgs pa;
    for (int i = 0; i < 6; i++) pa.x[i] = (const float*)d_in[i];
    pa.w[0] = (const float*)d_in[7];  pa.b[0] = (const float*)d_in[8];
    pa.w[1] = (const float*)d_in[11]; pa.b[1] = (const float*)d_in[12];
    proj_tf32_kernel<<<dim3(2, 32, 6), 256>>>(pa);

    // 2) two-phase fused attention (self-contained softmax, no sums kernel)
    attn_fused_kernel<<<dim3(8, 32), 256, FUSED_SMEM>>>(out, mask, alpha, beta);

    // 3) output projections (tf32 mma, 256 CTAs)
    OutArgs oa;
    oa.w[0] = (const float*)d_in[9];  oa.b[0] = (const float*)d_in[10];
    oa.w[1] = (const float*)d_in[13]; oa.b[1] = (const float*)d_in[14];
    outproj_tf32_kernel<<<dim3(2, 64, 2), 256>>>(oa, out);
}